// round 6
// baseline (speedup 1.0000x reference)
#include <cuda_runtime.h>
#include <math.h>
#include <stdint.h>

// ---------------- problem constants (hardcoded) ----------------
constexpr int   Bb   = 4;
constexpr int   Ss   = 2048;
constexpr int   DIN  = 256;
constexpr int   Dd   = 512;
constexpr int   Hh   = 8;
constexpr int   DOUT = 128;
constexpr int   HD   = 64;       // Dd / Hh
constexpr int   BS   = Bb * Ss;  // 8192 rows
constexpr float SCALE = 0.125f;  // 1/sqrt(64)

// ---------------- scratch (static device memory; no allocs) ----------------
constexpr size_t NBD  = (size_t)BS * Dd;
constexpr size_t O_H   = 0;
constexpr size_t O_QL  = 1 * NBD;   // QL,KL,VL,QG,KG,VG consecutive
constexpr size_t O_KL  = 2 * NBD;
constexpr size_t O_VL  = 3 * NBD;
constexpr size_t O_QG  = 4 * NBD;
constexpr size_t O_KG  = 5 * NBD;
constexpr size_t O_VG  = 6 * NBD;
constexpr size_t O_AOL = 7 * NBD;
constexpr size_t O_AOG = 8 * NBD;
constexpr size_t O_LOC = 9 * NBD;   // LOC,GLO consecutive
constexpr size_t O_GLO = 10 * NBD;
constexpr size_t O_FUS = 11 * NBD;
constexpr size_t O_H1  = 12 * NBD;
constexpr size_t O_FFN = 13 * NBD;
constexpr size_t O_H3  = 14 * NBD;
constexpr size_t O_T1  = 15 * NBD;  // 2*NBD wide
constexpr size_t O_PP  = 17 * NBD;
constexpr size_t O_P   = 17 * NBD + (size_t)16 * Bb * Dd;
constexpr size_t SCRATCH_FLOATS = O_P + (size_t)Bb * Dd;

__device__ float g_scratch[SCRATCH_FLOATS];

// ---------------- helpers: tf32 convert + mma + ldmatrix ----------------
__device__ __forceinline__ float cvt_tf32(float x) {
    uint32_t u;
    asm("cvt.rna.tf32.f32 %0, %1;" : "=r"(u) : "f"(x));
    return __uint_as_float(u);
}

__device__ __forceinline__ void mma_tf32(float c[4], const uint32_t a[4],
                                         const uint32_t b[2]) {
    asm volatile(
        "mma.sync.aligned.m16n8k8.row.col.f32.tf32.tf32.f32 "
        "{%0,%1,%2,%3},{%4,%5,%6,%7},{%8,%9},{%0,%1,%2,%3};\n"
        : "+f"(c[0]), "+f"(c[1]), "+f"(c[2]), "+f"(c[3])
        : "r"(a[0]), "r"(a[1]), "r"(a[2]), "r"(a[3]), "r"(b[0]), "r"(b[1]));
}

__device__ __forceinline__ void ldsm_x4(uint32_t r[4], uint32_t saddr) {
    asm volatile("ldmatrix.sync.aligned.m8n8.x4.shared.b16 {%0,%1,%2,%3}, [%4];"
                 : "=r"(r[0]), "=r"(r[1]), "=r"(r[2]), "=r"(r[3]) : "r"(saddr));
}

__device__ __forceinline__ uint32_t smem_u32(const void* p) {
    uint32_t a;
    asm("{ .reg .u64 t; cvta.to.shared.u64 t, %1; cvt.u32.u64 %0, t; }"
        : "=r"(a) : "l"(p));
    return a;
}

// ---------------- TF32 tensor-core GEMM, 128x128 tile, fused epilogues -----
// MODE 0: +bias
// MODE 1: +bias + pos[(row%S)*N + col]
// MODE 2: relu(+bias)
// MODE 3: A=concat(A,A2) on K (split KA); g=tanh(relu(acc+bias)); C=g*p1+(1-g)*p2
// MODE 4: 6-slice QKV: isl=bx>>2; W = isl<3? W+isl*D*D : p1+(isl-3)*D*D;
//         bias = isl<3? bias+isl*D : A2+(isl-3)*D; C += isl*NBD
// MODE 5: 2-slice Wo:  isl=bx>>2; A = isl? A2:A; W = isl? p1:W;
//         bias = isl? p2:bias; C += isl*NBD
// A-fragments via ldmatrix from As[m][RSA] (m-major).
constexpr int RSA = 20;

template <int MODE>
__global__ void __launch_bounds__(256) gemm_tc_k(
    const float* __restrict__ A, const float* __restrict__ A2, int lda, int KA,
    const float* __restrict__ W, const float* __restrict__ bias,
    const float* __restrict__ p1, const float* __restrict__ p2,
    float* __restrict__ C, int M, int N, int K)
{
    __shared__ float As[2][128][RSA];   // [m][k], k-tile 16 + pad
    __shared__ float Bs[2][16][136];    // [k][n]

    const int t  = threadIdx.x;
    const int m0 = blockIdx.y * 128;

    // ---- slice / column-base resolution ----
    const float* Asel = A;
    const float* Wsel = W;
    const float* bsel = bias;
    float* Csel = C;
    int n0;
    if (MODE == 4 || MODE == 5) {
        const int isl = blockIdx.x >> 2;
        n0 = (blockIdx.x & 3) * 128;
        if (MODE == 4) {
            Wsel = (isl < 3) ? W + (size_t)isl * Dd * Dd
                             : p1 + (size_t)(isl - 3) * Dd * Dd;
            bsel = (isl < 3) ? bias + isl * Dd : A2 + (isl - 3) * Dd;
        } else {
            Asel = isl ? A2 : A;
            Wsel = isl ? p1 : W;
            bsel = isl ? p2 : bias;
        }
        Csel = C + (size_t)isl * NBD;
    } else {
        n0 = blockIdx.x * 128;
    }

    const int lane = t & 31, w = t >> 5;
    const int wm = w & 1, wn = w >> 1;
    const int gid = lane >> 2, tig = lane & 3;
    const int mw = wm * 64, nw = wn * 32;

    const int amr = t >> 1;          // A loader: m row 0..127
    const int akc = (t & 1) * 8;     // A loader: k col 0 or 8
    const int bkr = t >> 4;          // B loader: k row 0..15
    const int bnc = (t & 15) * 8;    // B loader: n col 0..120

    // ldmatrix lane geometry for A-frags
    const int lm_row = (lane & 7) + (lane & 8);     // 0..15
    const int lm_kc  = (lane >> 2) & 4;             // 0 or 4
    const uint32_t aAddr0 = smem_u32(&As[0][mw + lm_row][lm_kc]);
    const uint32_t aAddr1 = smem_u32(&As[1][mw + lm_row][lm_kc]);

    float acc[4][4][4] = {};
    float4 pa0, pa1, pb0, pb1;

    // ---- prefetch tile 0 ----
    {
        const float* Asrc = Asel;
        int kk0 = 0;
        if (MODE == 3 && 0 >= KA) { Asrc = A2; kk0 = -KA; }
        pa0 = *(const float4*)(Asrc + (size_t)(m0 + amr) * lda + kk0 + akc);
        pa1 = *(const float4*)(Asrc + (size_t)(m0 + amr) * lda + kk0 + akc + 4);
        pb0 = *(const float4*)(Wsel + (size_t)bkr * N + n0 + bnc);
        pb1 = *(const float4*)(Wsel + (size_t)bkr * N + n0 + bnc + 4);
    }
    {
        float4 a0, a1;
        a0.x = cvt_tf32(pa0.x); a0.y = cvt_tf32(pa0.y);
        a0.z = cvt_tf32(pa0.z); a0.w = cvt_tf32(pa0.w);
        a1.x = cvt_tf32(pa1.x); a1.y = cvt_tf32(pa1.y);
        a1.z = cvt_tf32(pa1.z); a1.w = cvt_tf32(pa1.w);
        *(float4*)&As[0][amr][akc]     = a0;
        *(float4*)&As[0][amr][akc + 4] = a1;
        float4 c0, c1;
        c0.x = cvt_tf32(pb0.x); c0.y = cvt_tf32(pb0.y);
        c0.z = cvt_tf32(pb0.z); c0.w = cvt_tf32(pb0.w);
        c1.x = cvt_tf32(pb1.x); c1.y = cvt_tf32(pb1.y);
        c1.z = cvt_tf32(pb1.z); c1.w = cvt_tf32(pb1.w);
        *(float4*)&Bs[0][bkr][bnc]     = c0;
        *(float4*)&Bs[0][bkr][bnc + 4] = c1;
    }
    __syncthreads();

    int buf = 0;
    for (int k0 = 0; k0 < K; k0 += 16) {
        const int kn = k0 + 16;
        const bool has_next = kn < K;
        if (has_next) {
            const float* Asrc = Asel;
            int kk0 = kn;
            if (MODE == 3 && kn >= KA) { Asrc = A2; kk0 = kn - KA; }
            pa0 = *(const float4*)(Asrc + (size_t)(m0 + amr) * lda + kk0 + akc);
            pa1 = *(const float4*)(Asrc + (size_t)(m0 + amr) * lda + kk0 + akc + 4);
            pb0 = *(const float4*)(Wsel + (size_t)(kn + bkr) * N + n0 + bnc);
            pb1 = *(const float4*)(Wsel + (size_t)(kn + bkr) * N + n0 + bnc + 4);
        }

        const uint32_t aAddr = buf ? aAddr1 : aAddr0;
#pragma unroll
        for (int kk = 0; kk < 16; kk += 8) {
            uint32_t af[4][4], bf[4][2];
#pragma unroll
            for (int mt = 0; mt < 4; mt++)
                ldsm_x4(af[mt], aAddr + (uint32_t)((mt * 16 * RSA + kk) * 4));
#pragma unroll
            for (int nt = 0; nt < 4; nt++) {
                const int n = nw + nt * 8 + gid;
                bf[nt][0] = __float_as_uint(Bs[buf][kk + tig][n]);
                bf[nt][1] = __float_as_uint(Bs[buf][kk + tig + 4][n]);
            }
#pragma unroll
            for (int mt = 0; mt < 4; mt++)
#pragma unroll
                for (int nt = 0; nt < 4; nt++)
                    mma_tf32(acc[mt][nt], af[mt], bf[nt]);
        }

        if (has_next) {
            const int nb = buf ^ 1;
            float4 a0, a1;
            a0.x = cvt_tf32(pa0.x); a0.y = cvt_tf32(pa0.y);
            a0.z = cvt_tf32(pa0.z); a0.w = cvt_tf32(pa0.w);
            a1.x = cvt_tf32(pa1.x); a1.y = cvt_tf32(pa1.y);
            a1.z = cvt_tf32(pa1.z); a1.w = cvt_tf32(pa1.w);
            *(float4*)&As[nb][amr][akc]     = a0;
            *(float4*)&As[nb][amr][akc + 4] = a1;
            float4 c0, c1;
            c0.x = cvt_tf32(pb0.x); c0.y = cvt_tf32(pb0.y);
            c0.z = cvt_tf32(pb0.z); c0.w = cvt_tf32(pb0.w);
            c1.x = cvt_tf32(pb1.x); c1.y = cvt_tf32(pb1.y);
            c1.z = cvt_tf32(pb1.z); c1.w = cvt_tf32(pb1.w);
            *(float4*)&Bs[nb][bkr][bnc]     = c0;
            *(float4*)&Bs[nb][bkr][bnc + 4] = c1;
        }
        __syncthreads();
        buf ^= 1;
    }

    // ---- epilogue ----
#pragma unroll
    for (int mt = 0; mt < 4; mt++) {
#pragma unroll
        for (int half = 0; half < 2; half++) {
            const int row = m0 + mw + mt * 16 + gid + half * 8;
#pragma unroll
            for (int nt = 0; nt < 4; nt++) {
                const int col = n0 + nw + nt * 8 + tig * 2;
                float v0 = acc[mt][nt][half * 2 + 0] + bsel[col];
                float v1 = acc[mt][nt][half * 2 + 1] + bsel[col + 1];
                if (MODE == 1) {
                    const size_t pr = (size_t)(row & (Ss - 1)) * N + col;
                    v0 += p1[pr]; v1 += p1[pr + 1];
                }
                if (MODE == 2) { v0 = fmaxf(v0, 0.f); v1 = fmaxf(v1, 0.f); }
                if (MODE == 3) {
                    const size_t pr = (size_t)row * N + col;
                    float g0 = tanhf(fmaxf(v0, 0.f));
                    float g1 = tanhf(fmaxf(v1, 0.f));
                    v0 = g0 * p1[pr] + (1.f - g0) * p2[pr];
                    v1 = g1 * p1[pr + 1] + (1.f - g1) * p2[pr + 1];
                }
                float2 o2; o2.x = v0; o2.y = v1;
                *(float2*)(Csel + (size_t)row * N + col) = o2;
            }
        }
    }
}

// ---------------- TF32 tensor-core flash attention ------------------------
// BANDED=0: full attention over S. BANDED=1: band |q-k|<=32 (4 k-tiles).
// Q-tile 128, K-tile 64, HD=64. 8 warps x 16 q-rows, mma m16n8k8.
constexpr int FQ_OFF = 0;
constexpr int FP_OFF = 128 * 68;
constexpr int FK_OFF = 2 * 128 * 68;
constexpr int FV_OFF = FK_OFF + 64 * 68;
constexpr int FL_SMEM_FLOATS = FV_OFF + 64 * 72;
constexpr int FL_SMEM_BYTES  = FL_SMEM_FLOATS * 4;   // 105,472 B

template <int BANDED>
__global__ void __launch_bounds__(256) flash_tc_k(
    const float* __restrict__ Q, const float* __restrict__ K,
    const float* __restrict__ V, float* __restrict__ O)
{
    extern __shared__ float sm[];
    float* Qs = sm + FQ_OFF;
    float* Ps = sm + FP_OFF;
    float* Ks = sm + FK_OFF;
    float* Vs = sm + FV_OFF;

    const int qt = blockIdx.x, h = blockIdx.y, b = blockIdx.z;
    const int t  = threadIdx.x;
    const int lane = t & 31, w = t >> 5;
    const int gid = lane >> 2, tig = lane & 3;
    const int q0 = w * 16;

    // ---- load Q tile (pre-scaled, tf32) ----
    {
        const int r  = t >> 1;
        const int c0 = (t & 1) * 32;
        const float* src = Q + ((size_t)(b * Ss + qt * 128 + r)) * Dd + h * HD + c0;
#pragma unroll
        for (int i = 0; i < 8; i++) {
            float4 v = *(const float4*)(src + i * 4);
            Qs[r * 68 + c0 + i * 4 + 0] = cvt_tf32(v.x * SCALE);
            Qs[r * 68 + c0 + i * 4 + 1] = cvt_tf32(v.y * SCALE);
            Qs[r * 68 + c0 + i * 4 + 2] = cvt_tf32(v.z * SCALE);
            Qs[r * 68 + c0 + i * 4 + 3] = cvt_tf32(v.w * SCALE);
        }
    }

    float o_acc[8][4] = {};
    float m0 = BANDED ? -1e30f : -INFINITY;
    float m1 = m0;
    float l0 = 0.f, l1 = 0.f;

    const int rowA0 = (q0 + gid) * 68;
    const int rowA1 = (q0 + gid + 8) * 68;
    const int qr0 = qt * 128 + q0 + gid;       // global q rows for masking
    const int qr1 = qr0 + 8;

    int k_begin = 0, k_end = Ss;
    if (BANDED) {
        k_begin = qt * 128 - 64; if (k_begin < 0) k_begin = 0;
        k_end   = qt * 128 + 192; if (k_end > Ss) k_end = Ss;
    }

    for (int k0 = k_begin; k0 < k_end; k0 += 64) {
        __syncthreads();

        // ---- load K/V tile (tf32) ----
        {
            const int r  = t >> 2;
            const int c0 = (t & 3) * 16;
            const float* ks = K + ((size_t)(b * Ss + k0 + r)) * Dd + h * HD + c0;
            const float* vs = V + ((size_t)(b * Ss + k0 + r)) * Dd + h * HD + c0;
#pragma unroll
            for (int i = 0; i < 4; i++) {
                float4 kv = *(const float4*)(ks + i * 4);
                Ks[r * 68 + c0 + i * 4 + 0] = cvt_tf32(kv.x);
                Ks[r * 68 + c0 + i * 4 + 1] = cvt_tf32(kv.y);
                Ks[r * 68 + c0 + i * 4 + 2] = cvt_tf32(kv.z);
                Ks[r * 68 + c0 + i * 4 + 3] = cvt_tf32(kv.w);
                float4 vv = *(const float4*)(vs + i * 4);
                Vs[r * 72 + c0 + i * 4 + 0] = cvt_tf32(vv.x);
                Vs[r * 72 + c0 + i * 4 + 1] = cvt_tf32(vv.y);
                Vs[r * 72 + c0 + i * 4 + 2] = cvt_tf32(vv.z);
                Vs[r * 72 + c0 + i * 4 + 3] = cvt_tf32(vv.w);
            }
        }
        __syncthreads();

        // ---- S = Q K^T ----
        float sreg[8][4] = {};
#pragma unroll
        for (int kk = 0; kk < 8; kk++) {
            uint32_t a[4];
            a[0] = __float_as_uint(Qs[rowA0 + kk * 8 + tig]);
            a[1] = __float_as_uint(Qs[rowA1 + kk * 8 + tig]);
            a[2] = __float_as_uint(Qs[rowA0 + kk * 8 + tig + 4]);
            a[3] = __float_as_uint(Qs[rowA1 + kk * 8 + tig + 4]);
#pragma unroll
            for (int nt = 0; nt < 8; nt++) {
                uint32_t bf[2];
                bf[0] = __float_as_uint(Ks[(nt * 8 + gid) * 68 + kk * 8 + tig]);
                bf[1] = __float_as_uint(Ks[(nt * 8 + gid) * 68 + kk * 8 + tig + 4]);
                mma_tf32(sreg[nt], a, bf);
            }
        }

        // ---- band mask ----
        if (BANDED) {
#pragma unroll
            for (int nt = 0; nt < 8; nt++) {
                const int kg = k0 + nt * 8 + 2 * tig;
                if (abs(qr0 - kg)       > 32) sreg[nt][0] = -1e30f;
                if (abs(qr0 - (kg + 1)) > 32) sreg[nt][1] = -1e30f;
                if (abs(qr1 - kg)       > 32) sreg[nt][2] = -1e30f;
                if (abs(qr1 - (kg + 1)) > 32) sreg[nt][3] = -1e30f;
            }
        }

        // ---- online softmax ----
        float mt0 = -1e30f, mt1 = -1e30f;
#pragma unroll
        for (int nt = 0; nt < 8; nt++) {
            mt0 = fmaxf(mt0, fmaxf(sreg[nt][0], sreg[nt][1]));
            mt1 = fmaxf(mt1, fmaxf(sreg[nt][2], sreg[nt][3]));
        }
        mt0 = fmaxf(mt0, __shfl_xor_sync(0xffffffffu, mt0, 1));
        mt0 = fmaxf(mt0, __shfl_xor_sync(0xffffffffu, mt0, 2));
        mt1 = fmaxf(mt1, __shfl_xor_sync(0xffffffffu, mt1, 1));
        mt1 = fmaxf(mt1, __shfl_xor_sync(0xffffffffu, mt1, 2));

        const float mn0 = fmaxf(m0, mt0), mn1 = fmaxf(m1, mt1);
        const float al0 = __expf(m0 - mn0), al1 = __expf(m1 - mn1);
        m0 = mn0; m1 = mn1;

        float ls0 = 0.f, ls1 = 0.f;
#pragma unroll
        for (int nt = 0; nt < 8; nt++) {
            float p00, p01, p10, p11;
            if (BANDED) {
                p00 = (sreg[nt][0] > -1e29f) ? __expf(sreg[nt][0] - mn0) : 0.f;
                p01 = (sreg[nt][1] > -1e29f) ? __expf(sreg[nt][1] - mn0) : 0.f;
                p10 = (sreg[nt][2] > -1e29f) ? __expf(sreg[nt][2] - mn1) : 0.f;
                p11 = (sreg[nt][3] > -1e29f) ? __expf(sreg[nt][3] - mn1) : 0.f;
            } else {
                p00 = __expf(sreg[nt][0] - mn0);
                p01 = __expf(sreg[nt][1] - mn0);
                p10 = __expf(sreg[nt][2] - mn1);
                p11 = __expf(sreg[nt][3] - mn1);
            }
            ls0 += p00 + p01;
            ls1 += p10 + p11;
            float2 w0; w0.x = cvt_tf32(p00); w0.y = cvt_tf32(p01);
            float2 w1; w1.x = cvt_tf32(p10); w1.y = cvt_tf32(p11);
            *(float2*)&Ps[rowA0 + nt * 8 + 2 * tig] = w0;
            *(float2*)&Ps[rowA1 + nt * 8 + 2 * tig] = w1;
        }
        ls0 += __shfl_xor_sync(0xffffffffu, ls0, 1);
        ls0 += __shfl_xor_sync(0xffffffffu, ls0, 2);
        ls1 += __shfl_xor_sync(0xffffffffu, ls1, 1);
        ls1 += __shfl_xor_sync(0xffffffffu, ls1, 2);
        l0 = l0 * al0 + ls0;
        l1 = l1 * al1 + ls1;
#pragma unroll
        for (int nt = 0; nt < 8; nt++) {
            o_acc[nt][0] *= al0; o_acc[nt][1] *= al0;
            o_acc[nt][2] *= al1; o_acc[nt][3] *= al1;
        }
        __syncwarp();

        // ---- O += P V ----
#pragma unroll
        for (int kk = 0; kk < 8; kk++) {
            uint32_t a[4];
            a[0] = __float_as_uint(Ps[rowA0 + kk * 8 + tig]);
            a[1] = __float_as_uint(Ps[rowA1 + kk * 8 + tig]);
            a[2] = __float_as_uint(Ps[rowA0 + kk * 8 + tig + 4]);
            a[3] = __float_as_uint(Ps[rowA1 + kk * 8 + tig + 4]);
#pragma unroll
            for (int nt = 0; nt < 8; nt++) {
                uint32_t bf[2];
                bf[0] = __float_as_uint(Vs[(kk * 8 + tig) * 72 + nt * 8 + gid]);
                bf[1] = __float_as_uint(Vs[(kk * 8 + tig + 4) * 72 + nt * 8 + gid]);
                mma_tf32(o_acc[nt], a, bf);
            }
        }
    }

    // ---- epilogue ----
    const float inv0 = 1.f / l0, inv1 = 1.f / l1;
    float* orow0 = O + ((size_t)(b * Ss + qt * 128 + q0 + gid)) * Dd + h * HD;
    float* orow1 = O + ((size_t)(b * Ss + qt * 128 + q0 + gid + 8)) * Dd + h * HD;
#pragma unroll
    for (int nt = 0; nt < 8; nt++) {
        float2 w0; w0.x = o_acc[nt][0] * inv0; w0.y = o_acc[nt][1] * inv0;
        float2 w1; w1.x = o_acc[nt][2] * inv1; w1.y = o_acc[nt][3] * inv1;
        *(float2*)(orow0 + nt * 8 + 2 * tig) = w0;
        *(float2*)(orow1 + nt * 8 + 2 * tig) = w1;
    }
}

// ---------------- LayerNorm kernels ----------------
__global__ void __launch_bounds__(128) ln_add_k(
    const float* __restrict__ A, const float* __restrict__ R,
    const float* __restrict__ g, const float* __restrict__ be,
    float* __restrict__ O)
{
    const int row = blockIdx.x, t = threadIdx.x;
    const size_t base = (size_t)row * Dd + t * 4;
    float4 a = *(const float4*)(A + base);
    float4 r = *(const float4*)(R + base);
    float x[4] = {a.x + r.x, a.y + r.y, a.z + r.z, a.w + r.w};

    float s = x[0] + x[1] + x[2] + x[3];
    float ss = x[0]*x[0] + x[1]*x[1] + x[2]*x[2] + x[3]*x[3];
    __shared__ float sh1[4], sh2[4];
#pragma unroll
    for (int o = 16; o; o >>= 1) {
        s  += __shfl_xor_sync(0xffffffffu, s, o);
        ss += __shfl_xor_sync(0xffffffffu, ss, o);
    }
    if (!(t & 31)) { sh1[t >> 5] = s; sh2[t >> 5] = ss; }
    __syncthreads();
    s  = sh1[0] + sh1[1] + sh1[2] + sh1[3];
    ss = sh2[0] + sh2[1] + sh2[2] + sh2[3];

    const float mean = s * (1.f / Dd);
    const float var = ss * (1.f / Dd) - mean * mean;
    const float rs = rsqrtf(var + 1e-5f);
    float4 gg = *(const float4*)(g + t * 4);
    float4 bb = *(const float4*)(be + t * 4);
    float4 o4;
    o4.x = (x[0] - mean) * rs * gg.x + bb.x;
    o4.y = (x[1] - mean) * rs * gg.y + bb.y;
    o4.z = (x[2] - mean) * rs * gg.z + bb.z;
    o4.w = (x[3] - mean) * rs * gg.w + bb.w;
    *(float4*)(O + base) = o4;
}

__global__ void __launch_bounds__(128) ln_add_ln_k(
    const float* __restrict__ A, const float* __restrict__ R,
    const float* __restrict__ g2, const float* __restrict__ b2,
    const float* __restrict__ g3, const float* __restrict__ b3,
    float* __restrict__ O)
{
    const int row = blockIdx.x, t = threadIdx.x;
    const size_t base = (size_t)row * Dd + t * 4;
    float4 a = *(const float4*)(A + base);
    float4 r = *(const float4*)(R + base);
    float x[4] = {a.x + r.x, a.y + r.y, a.z + r.z, a.w + r.w};

    __shared__ float sh1[4], sh2[4];
    float s = x[0] + x[1] + x[2] + x[3];
    float ss = x[0]*x[0] + x[1]*x[1] + x[2]*x[2] + x[3]*x[3];
#pragma unroll
    for (int o = 16; o; o >>= 1) {
        s  += __shfl_xor_sync(0xffffffffu, s, o);
        ss += __shfl_xor_sync(0xffffffffu, ss, o);
    }
    if (!(t & 31)) { sh1[t >> 5] = s; sh2[t >> 5] = ss; }
    __syncthreads();
    s  = sh1[0] + sh1[1] + sh1[2] + sh1[3];
    ss = sh2[0] + sh2[1] + sh2[2] + sh2[3];
    float mean = s * (1.f / Dd);
    float var = ss * (1.f / Dd) - mean * mean;
    float rs = rsqrtf(var + 1e-5f);

    float4 gg = *(const float4*)(g2 + t * 4);
    float4 bb = *(const float4*)(b2 + t * 4);
    float y[4];
    y[0] = (x[0] - mean) * rs * gg.x + bb.x;
    y[1] = (x[1] - mean) * rs * gg.y + bb.y;
    y[2] = (x[2] - mean) * rs * gg.z + bb.z;
    y[3] = (x[3] - mean) * rs * gg.w + bb.w;

    __syncthreads();
    s  = y[0] + y[1] + y[2] + y[3];
    ss = y[0]*y[0] + y[1]*y[1] + y[2]*y[2] + y[3]*y[3];
#pragma unroll
    for (int o = 16; o; o >>= 1) {
        s  += __shfl_xor_sync(0xffffffffu, s, o);
        ss += __shfl_xor_sync(0xffffffffu, ss, o);
    }
    if (!(t & 31)) { sh1[t >> 5] = s; sh2[t >> 5] = ss; }
    __syncthreads();
    s  = sh1[0] + sh1[1] + sh1[2] + sh1[3];
    ss = sh2[0] + sh2[1] + sh2[2] + sh2[3];
    mean = s * (1.f / Dd);
    var = ss * (1.f / Dd) - mean * mean;
    rs = rsqrtf(var + 1e-5f);

    float4 g3v = *(const float4*)(g3 + t * 4);
    float4 b3v = *(const float4*)(b3 + t * 4);
    float4 o4;
    o4.x = (y[0] - mean) * rs * g3v.x + b3v.x;
    o4.y = (y[1] - mean) * rs * g3v.y + b3v.y;
    o4.z = (y[2] - mean) * rs * g3v.z + b3v.z;
    o4.w = (y[3] - mean) * rs * g3v.w + b3v.w;
    *(float4*)(O + base) = o4;
}

// ---------------- mean pool over S (deterministic 2-stage) ----------------
__global__ void __launch_bounds__(128) colmean_part_k(const float* __restrict__ X,
                                                      float* __restrict__ PP)
{
    const int b = blockIdx.x >> 2;
    const int d = (blockIdx.x & 3) * 128 + threadIdx.x;
    const int sc = blockIdx.y;
    float s = 0.f;
    for (int j = sc * 128; j < sc * 128 + 128; j++)
        s += X[((size_t)(b * Ss + j)) * Dd + d];
    PP[((size_t)sc * Bb + b) * Dd + d] = s;
}

__global__ void __launch_bounds__(128) colmean_fin_k(const float* __restrict__ PP,
                                                     float* __restrict__ P)
{
    const int idx = blockIdx.x * 128 + threadIdx.x;
    const int b = idx / Dd, d = idx % Dd;
    float s = 0.f;
#pragma unroll
    for (int c = 0; c < 16; c++) s += PP[((size_t)c * Bb + b) * Dd + d];
    P[idx] = s * (1.f / Ss);
}

// ---------------- final tiny GEMM ----------------
__global__ void __launch_bounds__(128) final_k(const float* __restrict__ P,
                                               const float* __restrict__ Wt,
                                               const float* __restrict__ bias,
                                               float* __restrict__ out)
{
    const int b = blockIdx.x, o = threadIdx.x;
    float s = bias[o];
    for (int d = 0; d < Dd; d++) s += P[b * Dd + d] * Wt[d * DOUT + o];
    out[b * DOUT + o] = s;
}

// ---------------- launch ----------------
extern "C" void kernel_launch(void* const* d_in, const int* in_sizes, int n_in,
                              void* d_out, int out_size)
{
    const float* x      = (const float*)d_in[0];
    const float* pos    = (const float*)d_in[1];
    const float* win_w  = (const float*)d_in[2];
    const float* win_b  = (const float*)d_in[3];
    const float* l_wqkv = (const float*)d_in[4];
    const float* l_bqkv = (const float*)d_in[5];
    const float* l_wo   = (const float*)d_in[6];
    const float* l_bo   = (const float*)d_in[7];
    const float* g_wqkv = (const float*)d_in[8];
    const float* g_bqkv = (const float*)d_in[9];
    const float* g_wo   = (const float*)d_in[10];
    const float* g_bo   = (const float*)d_in[11];
    const float* gate_w = (const float*)d_in[12];
    const float* gate_b = (const float*)d_in[13];
    const float* ffn_w1 = (const float*)d_in[14];
    const float* ffn_b1 = (const float*)d_in[15];
    const float* ffn_w2 = (const float*)d_in[16];
    const float* ffn_b2 = (const float*)d_in[17];
    const float* n1_g   = (const float*)d_in[18];
    const float* n1_b   = (const float*)d_in[19];
    const float* n2_g   = (const float*)d_in[20];
    const float* n2_b   = (const float*)d_in[21];
    const float* n3_g   = (const float*)d_in[22];
    const float* n3_b   = (const float*)d_in[23];
    const float* out_w  = (const float*)d_in[24];
    const float* out_b  = (const float*)d_in[25];

    float* sp = nullptr;
    cudaGetSymbolAddress((void**)&sp, g_scratch);
    float* bH   = sp + O_H;
    float* bQL  = sp + O_QL;
    float* bKL  = sp + O_KL;
    float* bVL  = sp + O_VL;
    float* bQG  = sp + O_QG;
    float* bKG  = sp + O_KG;
    float* bVG  = sp + O_VG;
    float* bAOL = sp + O_AOL;
    float* bAOG = sp + O_AOG;
    float* bLOC = sp + O_LOC;
    float* bGLO = sp + O_GLO;
    float* bFUS = sp + O_FUS;
    float* bH1  = sp + O_H1;
    float* bFFN = sp + O_FFN;
    float* bH3  = sp + O_H3;
    float* bT1  = sp + O_T1;
    float* bPP  = sp + O_PP;
    float* bP   = sp + O_P;

    static bool attr_set = false;
    if (!attr_set) {
        cudaFuncSetAttribute(flash_tc_k<0>, cudaFuncAttributeMaxDynamicSharedMemorySize,
                             FL_SMEM_BYTES);
        cudaFuncSetAttribute(flash_tc_k<1>, cudaFuncAttributeMaxDynamicSharedMemorySize,
                             FL_SMEM_BYTES);
        attr_set = true;
    }

    const dim3 blk(256);

    // 1. h = x @ win_w + win_b + pos
    gemm_tc_k<1><<<dim3(4, 64), blk>>>(x, nullptr, DIN, 0, win_w, win_b, pos,
                                       nullptr, bH, BS, Dd, DIN);

    // 2. merged 6-slice QKV (local 0..2, global 3..5) -> bQL..bVG
    gemm_tc_k<4><<<dim3(24, 64), blk>>>(bH, g_bqkv, Dd, 0, l_wqkv, l_bqkv,
                                        g_wqkv, nullptr, bQL, BS, Dd, Dd);

    // 3. local banded flash attention
    flash_tc_k<1><<<dim3(Ss / 128, Hh, Bb), 256, FL_SMEM_BYTES>>>(bQL, bKL, bVL, bAOL);

    // 4. global flash attention
    flash_tc_k<0><<<dim3(Ss / 128, Hh, Bb), 256, FL_SMEM_BYTES>>>(bQG, bKG, bVG, bAOG);

    // 5. merged 2-slice output projections -> bLOC, bGLO
    gemm_tc_k<5><<<dim3(8, 64), blk>>>(bAOL, bAOG, Dd, 0, l_wo, l_bo,
                                       g_wo, g_bo, bLOC, BS, Dd, Dd);

    // 6. gate GEMM fused with blend
    gemm_tc_k<3><<<dim3(4, 64), blk>>>(bLOC, bGLO, Dd, Dd, gate_w, gate_b,
                                       bLOC, bGLO, bFUS, BS, Dd, 2 * Dd);

    // 7. h1 = LN(h + fused)
    ln_add_k<<<BS, 128>>>(bH, bFUS, n1_g, n1_b, bH1);

    // 8. FFN
    gemm_tc_k<2><<<dim3(8, 64), blk>>>(bH1, nullptr, Dd, 0, ffn_w1, ffn_b1,
                                       nullptr, nullptr, bT1, BS, 2 * Dd, Dd);
    gemm_tc_k<0><<<dim3(4, 64), blk>>>(bT1, nullptr, 2 * Dd, 0, ffn_w2, ffn_b2,
                                       nullptr, nullptr, bFFN, BS, Dd, 2 * Dd);

    // 9. h3 = LN(LN(h1 + ffn))
    ln_add_ln_k<<<BS, 128>>>(bH1, bFFN, n2_g, n2_b, n3_g, n3_b, bH3);

    // 10. mean-pool over S, then final projection
    colmean_part_k<<<dim3(Bb * 4, 16), 128>>>(bH3, bPP);
    colmean_fin_k<<<(Bb * Dd) / 128, 128>>>(bPP, bP);
    final_k<<<Bb, DOUT>>>(bP, out_w, out_b, (float*)d_out);

    (void)in_sizes; (void)n_in; (void)out_size;
}

// round 7
// speedup vs baseline: 1.0053x; 1.0053x over previous
#include <cuda_runtime.h>
#include <math.h>
#include <stdint.h>

// ---------------- problem constants (hardcoded) ----------------
constexpr int   Bb   = 4;
constexpr int   Ss   = 2048;
constexpr int   DIN  = 256;
constexpr int   Dd   = 512;
constexpr int   Hh   = 8;
constexpr int   DOUT = 128;
constexpr int   HD   = 64;       // Dd / Hh
constexpr int   BS   = Bb * Ss;  // 8192 rows
constexpr float SCALE = 0.125f;  // 1/sqrt(64)

// ---------------- scratch (static device memory; no allocs) ----------------
constexpr size_t NBD  = (size_t)BS * Dd;
constexpr size_t O_H   = 0;
constexpr size_t O_QL  = 1 * NBD;   // QL,KL,VL,QG,KG,VG consecutive
constexpr size_t O_KL  = 2 * NBD;
constexpr size_t O_VL  = 3 * NBD;
constexpr size_t O_QG  = 4 * NBD;
constexpr size_t O_KG  = 5 * NBD;
constexpr size_t O_VG  = 6 * NBD;
constexpr size_t O_AOL = 7 * NBD;
constexpr size_t O_AOG = 8 * NBD;
constexpr size_t O_LOC = 9 * NBD;   // LOC,GLO consecutive
constexpr size_t O_GLO = 10 * NBD;
constexpr size_t O_FUS = 11 * NBD;
constexpr size_t O_H1  = 12 * NBD;
constexpr size_t O_FFN = 13 * NBD;
constexpr size_t O_H3  = 14 * NBD;
constexpr size_t O_T1  = 15 * NBD;  // 2*NBD wide
constexpr size_t O_PP  = 17 * NBD;
constexpr size_t O_P   = 17 * NBD + (size_t)16 * Bb * Dd;
constexpr size_t SCRATCH_FLOATS = O_P + (size_t)Bb * Dd;

__device__ float g_scratch[SCRATCH_FLOATS];

// ---------------- helpers: tf32 convert + mma + ldmatrix ----------------
__device__ __forceinline__ float cvt_tf32(float x) {
    uint32_t u;
    asm("cvt.rna.tf32.f32 %0, %1;" : "=r"(u) : "f"(x));
    return __uint_as_float(u);
}

__device__ __forceinline__ void mma_tf32(float c[4], const uint32_t a[4],
                                         const uint32_t b[2]) {
    asm volatile(
        "mma.sync.aligned.m16n8k8.row.col.f32.tf32.tf32.f32 "
        "{%0,%1,%2,%3},{%4,%5,%6,%7},{%8,%9},{%0,%1,%2,%3};\n"
        : "+f"(c[0]), "+f"(c[1]), "+f"(c[2]), "+f"(c[3])
        : "r"(a[0]), "r"(a[1]), "r"(a[2]), "r"(a[3]), "r"(b[0]), "r"(b[1]));
}

__device__ __forceinline__ void ldsm_x4(uint32_t r[4], uint32_t saddr) {
    asm volatile("ldmatrix.sync.aligned.m8n8.x4.shared.b16 {%0,%1,%2,%3}, [%4];"
                 : "=r"(r[0]), "=r"(r[1]), "=r"(r[2]), "=r"(r[3]) : "r"(saddr));
}

__device__ __forceinline__ uint32_t smem_u32(const void* p) {
    uint32_t a;
    asm("{ .reg .u64 t; cvta.to.shared.u64 t, %1; cvt.u32.u64 %0, t; }"
        : "=r"(a) : "l"(p));
    return a;
}

// ---------------- TF32 tensor-core GEMM, 128x128 tile, fused epilogues -----
// MODE 0: +bias
// MODE 1: +bias + pos[(row%S)*N + col]
// MODE 2: relu(+bias)
// MODE 3: A=concat(A,A2) on K (split KA); g=tanh(relu(acc+bias)); C=g*p1+(1-g)*p2
// MODE 4: 6-slice QKV; MODE 5: 2-slice Wo (see launch)
constexpr int RSA = 20;

template <int MODE>
__global__ void __launch_bounds__(256) gemm_tc_k(
    const float* __restrict__ A, const float* __restrict__ A2, int lda, int KA,
    const float* __restrict__ W, const float* __restrict__ bias,
    const float* __restrict__ p1, const float* __restrict__ p2,
    float* __restrict__ C, int M, int N, int K)
{
    __shared__ float As[2][128][RSA];   // [m][k], k-tile 16 + pad
    __shared__ float Bs[2][16][136];    // [k][n]

    const int t  = threadIdx.x;
    const int m0 = blockIdx.y * 128;

    const float* Asel = A;
    const float* Wsel = W;
    const float* bsel = bias;
    float* Csel = C;
    int n0;
    if (MODE == 4 || MODE == 5) {
        const int isl = blockIdx.x >> 2;
        n0 = (blockIdx.x & 3) * 128;
        if (MODE == 4) {
            Wsel = (isl < 3) ? W + (size_t)isl * Dd * Dd
                             : p1 + (size_t)(isl - 3) * Dd * Dd;
            bsel = (isl < 3) ? bias + isl * Dd : A2 + (isl - 3) * Dd;
        } else {
            Asel = isl ? A2 : A;
            Wsel = isl ? p1 : W;
            bsel = isl ? p2 : bias;
        }
        Csel = C + (size_t)isl * NBD;
    } else {
        n0 = blockIdx.x * 128;
    }

    const int lane = t & 31, w = t >> 5;
    const int wm = w & 1, wn = w >> 1;
    const int gid = lane >> 2, tig = lane & 3;
    const int mw = wm * 64, nw = wn * 32;

    const int amr = t >> 1;
    const int akc = (t & 1) * 8;
    const int bkr = t >> 4;
    const int bnc = (t & 15) * 8;

    const int lm_row = (lane & 7) + (lane & 8);
    const int lm_kc  = (lane >> 2) & 4;
    const uint32_t aAddr0 = smem_u32(&As[0][mw + lm_row][lm_kc]);
    const uint32_t aAddr1 = smem_u32(&As[1][mw + lm_row][lm_kc]);

    float acc[4][4][4] = {};
    float4 pa0, pa1, pb0, pb1;

    {
        const float* Asrc = Asel;
        int kk0 = 0;
        if (MODE == 3 && 0 >= KA) { Asrc = A2; kk0 = -KA; }
        pa0 = *(const float4*)(Asrc + (size_t)(m0 + amr) * lda + kk0 + akc);
        pa1 = *(const float4*)(Asrc + (size_t)(m0 + amr) * lda + kk0 + akc + 4);
        pb0 = *(const float4*)(Wsel + (size_t)bkr * N + n0 + bnc);
        pb1 = *(const float4*)(Wsel + (size_t)bkr * N + n0 + bnc + 4);
    }
    {
        float4 a0, a1;
        a0.x = cvt_tf32(pa0.x); a0.y = cvt_tf32(pa0.y);
        a0.z = cvt_tf32(pa0.z); a0.w = cvt_tf32(pa0.w);
        a1.x = cvt_tf32(pa1.x); a1.y = cvt_tf32(pa1.y);
        a1.z = cvt_tf32(pa1.z); a1.w = cvt_tf32(pa1.w);
        *(float4*)&As[0][amr][akc]     = a0;
        *(float4*)&As[0][amr][akc + 4] = a1;
        float4 c0, c1;
        c0.x = cvt_tf32(pb0.x); c0.y = cvt_tf32(pb0.y);
        c0.z = cvt_tf32(pb0.z); c0.w = cvt_tf32(pb0.w);
        c1.x = cvt_tf32(pb1.x); c1.y = cvt_tf32(pb1.y);
        c1.z = cvt_tf32(pb1.z); c1.w = cvt_tf32(pb1.w);
        *(float4*)&Bs[0][bkr][bnc]     = c0;
        *(float4*)&Bs[0][bkr][bnc + 4] = c1;
    }
    __syncthreads();

    int buf = 0;
    for (int k0 = 0; k0 < K; k0 += 16) {
        const int kn = k0 + 16;
        const bool has_next = kn < K;
        if (has_next) {
            const float* Asrc = Asel;
            int kk0 = kn;
            if (MODE == 3 && kn >= KA) { Asrc = A2; kk0 = kn - KA; }
            pa0 = *(const float4*)(Asrc + (size_t)(m0 + amr) * lda + kk0 + akc);
            pa1 = *(const float4*)(Asrc + (size_t)(m0 + amr) * lda + kk0 + akc + 4);
            pb0 = *(const float4*)(Wsel + (size_t)(kn + bkr) * N + n0 + bnc);
            pb1 = *(const float4*)(Wsel + (size_t)(kn + bkr) * N + n0 + bnc + 4);
        }

        const uint32_t aAddr = buf ? aAddr1 : aAddr0;
#pragma unroll
        for (int kk = 0; kk < 16; kk += 8) {
            uint32_t af[4][4], bf[4][2];
#pragma unroll
            for (int mt = 0; mt < 4; mt++)
                ldsm_x4(af[mt], aAddr + (uint32_t)((mt * 16 * RSA + kk) * 4));
#pragma unroll
            for (int nt = 0; nt < 4; nt++) {
                const int n = nw + nt * 8 + gid;
                bf[nt][0] = __float_as_uint(Bs[buf][kk + tig][n]);
                bf[nt][1] = __float_as_uint(Bs[buf][kk + tig + 4][n]);
            }
#pragma unroll
            for (int mt = 0; mt < 4; mt++)
#pragma unroll
                for (int nt = 0; nt < 4; nt++)
                    mma_tf32(acc[mt][nt], af[mt], bf[nt]);
        }

        if (has_next) {
            const int nb = buf ^ 1;
            float4 a0, a1;
            a0.x = cvt_tf32(pa0.x); a0.y = cvt_tf32(pa0.y);
            a0.z = cvt_tf32(pa0.z); a0.w = cvt_tf32(pa0.w);
            a1.x = cvt_tf32(pa1.x); a1.y = cvt_tf32(pa1.y);
            a1.z = cvt_tf32(pa1.z); a1.w = cvt_tf32(pa1.w);
            *(float4*)&As[nb][amr][akc]     = a0;
            *(float4*)&As[nb][amr][akc + 4] = a1;
            float4 c0, c1;
            c0.x = cvt_tf32(pb0.x); c0.y = cvt_tf32(pb0.y);
            c0.z = cvt_tf32(pb0.z); c0.w = cvt_tf32(pb0.w);
            c1.x = cvt_tf32(pb1.x); c1.y = cvt_tf32(pb1.y);
            c1.z = cvt_tf32(pb1.z); c1.w = cvt_tf32(pb1.w);
            *(float4*)&Bs[nb][bkr][bnc]     = c0;
            *(float4*)&Bs[nb][bkr][bnc + 4] = c1;
        }
        __syncthreads();
        buf ^= 1;
    }

#pragma unroll
    for (int mt = 0; mt < 4; mt++) {
#pragma unroll
        for (int half = 0; half < 2; half++) {
            const int row = m0 + mw + mt * 16 + gid + half * 8;
#pragma unroll
            for (int nt = 0; nt < 4; nt++) {
                const int col = n0 + nw + nt * 8 + tig * 2;
                float v0 = acc[mt][nt][half * 2 + 0] + bsel[col];
                float v1 = acc[mt][nt][half * 2 + 1] + bsel[col + 1];
                if (MODE == 1) {
                    const size_t pr = (size_t)(row & (Ss - 1)) * N + col;
                    v0 += p1[pr]; v1 += p1[pr + 1];
                }
                if (MODE == 2) { v0 = fmaxf(v0, 0.f); v1 = fmaxf(v1, 0.f); }
                if (MODE == 3) {
                    const size_t pr = (size_t)row * N + col;
                    float g0 = tanhf(fmaxf(v0, 0.f));
                    float g1 = tanhf(fmaxf(v1, 0.f));
                    v0 = g0 * p1[pr] + (1.f - g0) * p2[pr];
                    v1 = g1 * p1[pr + 1] + (1.f - g1) * p2[pr + 1];
                }
                float2 o2; o2.x = v0; o2.y = v1;
                *(float2*)(Csel + (size_t)row * N + col) = o2;
            }
        }
    }
}

// ---------------- TF32 tensor-core flash attention (full ldmatrix) ---------
// BANDED=0: full attention. BANDED=1: band |q-k|<=32.
// Q-tile 128, K-tile 64, HD=64. 8 warps x 16 q-rows, mma m16n8k8.
// smem: Qs[128][68] (q-major), Ps[128][68] (q-major), Ks[64][68] (key-major),
//       Vst[64][68] (d-major = V transposed). All frags via ldmatrix.x4.
constexpr int FQ_OFF = 0;
constexpr int FP_OFF = 128 * 68;
constexpr int FK_OFF = 2 * 128 * 68;
constexpr int FV_OFF = FK_OFF + 64 * 68;
constexpr int FL_SMEM_FLOATS = FV_OFF + 64 * 68;
constexpr int FL_SMEM_BYTES  = FL_SMEM_FLOATS * 4;   // 104,448 B

template <int BANDED>
__global__ void __launch_bounds__(256) flash_tc_k(
    const float* __restrict__ Q, const float* __restrict__ K,
    const float* __restrict__ V, float* __restrict__ O)
{
    extern __shared__ float sm[];
    float* Qs  = sm + FQ_OFF;
    float* Ps  = sm + FP_OFF;
    float* Ks  = sm + FK_OFF;
    float* Vst = sm + FV_OFF;

    const int qt = blockIdx.x, h = blockIdx.y, b = blockIdx.z;
    const int t  = threadIdx.x;
    const int lane = t & 31, w = t >> 5;
    const int gid = lane >> 2, tig = lane & 3;
    const int q0 = w * 16;

    // ldmatrix lane geometry
    const int lm_row = (lane & 7) + (lane & 8);
    const int lm_kc  = (lane >> 2) & 4;
    const uint32_t qA = smem_u32(&Qs[(q0 + lm_row) * 68 + lm_kc]);
    const uint32_t pA = smem_u32(&Ps[(q0 + lm_row) * 68 + lm_kc]);
    const uint32_t kB = smem_u32(&Ks[lm_row * 68 + lm_kc]);
    const uint32_t vB = smem_u32(&Vst[lm_row * 68 + lm_kc]);

    // ---- load Q tile (pre-scaled, tf32) ----
    {
        const int r  = t >> 1;
        const int c0 = (t & 1) * 32;
        const float* src = Q + ((size_t)(b * Ss + qt * 128 + r)) * Dd + h * HD + c0;
#pragma unroll
        for (int i = 0; i < 8; i++) {
            float4 v = *(const float4*)(src + i * 4);
            float4 c;
            c.x = cvt_tf32(v.x * SCALE); c.y = cvt_tf32(v.y * SCALE);
            c.z = cvt_tf32(v.z * SCALE); c.w = cvt_tf32(v.w * SCALE);
            *(float4*)&Qs[r * 68 + c0 + i * 4] = c;
        }
    }

    float o_acc[8][4] = {};
    float m0 = -1e30f, m1 = -1e30f, l0 = 0.f, l1 = 0.f;

    const int rowA0 = (q0 + gid) * 68;
    const int rowA1 = (q0 + gid + 8) * 68;
    const int qr0 = qt * 128 + q0 + gid;
    const int qr1 = qr0 + 8;

    int k_begin = 0, k_end = Ss;
    if (BANDED) {
        k_begin = qt * 128 - 64; if (k_begin < 0) k_begin = 0;
        k_end   = qt * 128 + 192; if (k_end > Ss) k_end = Ss;
    }

    for (int k0 = k_begin; k0 < k_end; k0 += 64) {
        __syncthreads();

        // ---- load K (row-major) + V (transposed) tiles, tf32 ----
        {
            const int r  = t >> 2;            // key 0..63
            const int c0 = (t & 3) * 16;      // dim base
            const float* ks = K + ((size_t)(b * Ss + k0 + r)) * Dd + h * HD + c0;
            const float* vs = V + ((size_t)(b * Ss + k0 + r)) * Dd + h * HD + c0;
#pragma unroll
            for (int i = 0; i < 4; i++) {
                float4 kv = *(const float4*)(ks + i * 4);
                float4 c;
                c.x = cvt_tf32(kv.x); c.y = cvt_tf32(kv.y);
                c.z = cvt_tf32(kv.z); c.w = cvt_tf32(kv.w);
                *(float4*)&Ks[r * 68 + c0 + i * 4] = c;
                float4 vv = *(const float4*)(vs + i * 4);
                const int d0 = c0 + i * 4;
                Vst[(d0 + 0) * 68 + r] = cvt_tf32(vv.x);
                Vst[(d0 + 1) * 68 + r] = cvt_tf32(vv.y);
                Vst[(d0 + 2) * 68 + r] = cvt_tf32(vv.z);
                Vst[(d0 + 3) * 68 + r] = cvt_tf32(vv.w);
            }
        }
        __syncthreads();

        // ---- S = Q K^T (all frags via ldmatrix) ----
        float sreg[8][4] = {};
#pragma unroll
        for (int kk = 0; kk < 8; kk++) {
            uint32_t a[4];
            ldsm_x4(a, qA + (uint32_t)(kk * 32));
#pragma unroll
            for (int nt2 = 0; nt2 < 4; nt2++) {
                uint32_t kb[4];
                ldsm_x4(kb, kB + (uint32_t)((nt2 * 16 * 68 + kk * 8) * 4));
                uint32_t b0[2] = {kb[0], kb[2]};
                uint32_t b1[2] = {kb[1], kb[3]};
                mma_tf32(sreg[2 * nt2],     a, b0);
                mma_tf32(sreg[2 * nt2 + 1], a, b1);
            }
        }

        // ---- band mask ----
        if (BANDED) {
#pragma unroll
            for (int nt = 0; nt < 8; nt++) {
                const int kg = k0 + nt * 8 + 2 * tig;
                if (abs(qr0 - kg)       > 32) sreg[nt][0] = -1e30f;
                if (abs(qr0 - (kg + 1)) > 32) sreg[nt][1] = -1e30f;
                if (abs(qr1 - kg)       > 32) sreg[nt][2] = -1e30f;
                if (abs(qr1 - (kg + 1)) > 32) sreg[nt][3] = -1e30f;
            }
        }

        // ---- online softmax ----
        float mt0 = -1e30f, mt1 = -1e30f;
#pragma unroll
        for (int nt = 0; nt < 8; nt++) {
            mt0 = fmaxf(mt0, fmaxf(sreg[nt][0], sreg[nt][1]));
            mt1 = fmaxf(mt1, fmaxf(sreg[nt][2], sreg[nt][3]));
        }
        mt0 = fmaxf(mt0, __shfl_xor_sync(0xffffffffu, mt0, 1));
        mt0 = fmaxf(mt0, __shfl_xor_sync(0xffffffffu, mt0, 2));
        mt1 = fmaxf(mt1, __shfl_xor_sync(0xffffffffu, mt1, 1));
        mt1 = fmaxf(mt1, __shfl_xor_sync(0xffffffffu, mt1, 2));

        const float mn0 = fmaxf(m0, mt0), mn1 = fmaxf(m1, mt1);
        const float al0 = __expf(m0 - mn0), al1 = __expf(m1 - mn1);
        m0 = mn0; m1 = mn1;

        float ls0 = 0.f, ls1 = 0.f;
#pragma unroll
        for (int nt = 0; nt < 8; nt++) {
            float p00, p01, p10, p11;
            if (BANDED) {
                p00 = (sreg[nt][0] > -1e29f) ? __expf(sreg[nt][0] - mn0) : 0.f;
                p01 = (sreg[nt][1] > -1e29f) ? __expf(sreg[nt][1] - mn0) : 0.f;
                p10 = (sreg[nt][2] > -1e29f) ? __expf(sreg[nt][2] - mn1) : 0.f;
                p11 = (sreg[nt][3] > -1e29f) ? __expf(sreg[nt][3] - mn1) : 0.f;
            } else {
                p00 = __expf(sreg[nt][0] - mn0);
                p01 = __expf(sreg[nt][1] - mn0);
                p10 = __expf(sreg[nt][2] - mn1);
                p11 = __expf(sreg[nt][3] - mn1);
            }
            ls0 += p00 + p01;
            ls1 += p10 + p11;
            float2 w0; w0.x = cvt_tf32(p00); w0.y = cvt_tf32(p01);
            float2 w1; w1.x = cvt_tf32(p10); w1.y = cvt_tf32(p11);
            *(float2*)&Ps[rowA0 + nt * 8 + 2 * tig] = w0;
            *(float2*)&Ps[rowA1 + nt * 8 + 2 * tig] = w1;
        }
        ls0 += __shfl_xor_sync(0xffffffffu, ls0, 1);
        ls0 += __shfl_xor_sync(0xffffffffu, ls0, 2);
        ls1 += __shfl_xor_sync(0xffffffffu, ls1, 1);
        ls1 += __shfl_xor_sync(0xffffffffu, ls1, 2);
        l0 = l0 * al0 + ls0;
        l1 = l1 * al1 + ls1;
#pragma unroll
        for (int nt = 0; nt < 8; nt++) {
            o_acc[nt][0] *= al0; o_acc[nt][1] *= al0;
            o_acc[nt][2] *= al1; o_acc[nt][3] *= al1;
        }
        __syncwarp();   // Ps rows q0..q0+15 are warp-local

        // ---- O += P V (all frags via ldmatrix) ----
#pragma unroll
        for (int kk = 0; kk < 8; kk++) {
            uint32_t a[4];
            ldsm_x4(a, pA + (uint32_t)(kk * 32));
#pragma unroll
            for (int nt2 = 0; nt2 < 4; nt2++) {
                uint32_t vb[4];
                ldsm_x4(vb, vB + (uint32_t)((nt2 * 16 * 68 + kk * 8) * 4));
                uint32_t b0[2] = {vb[0], vb[2]};
                uint32_t b1[2] = {vb[1], vb[3]};
                mma_tf32(o_acc[2 * nt2],     a, b0);
                mma_tf32(o_acc[2 * nt2 + 1], a, b1);
            }
        }
    }

    // ---- epilogue ----
    const float inv0 = 1.f / l0, inv1 = 1.f / l1;
    float* orow0 = O + ((size_t)(b * Ss + qt * 128 + q0 + gid)) * Dd + h * HD;
    float* orow1 = O + ((size_t)(b * Ss + qt * 128 + q0 + gid + 8)) * Dd + h * HD;
#pragma unroll
    for (int nt = 0; nt < 8; nt++) {
        float2 w0; w0.x = o_acc[nt][0] * inv0; w0.y = o_acc[nt][1] * inv0;
        float2 w1; w1.x = o_acc[nt][2] * inv1; w1.y = o_acc[nt][3] * inv1;
        *(float2*)(orow0 + nt * 8 + 2 * tig) = w0;
        *(float2*)(orow1 + nt * 8 + 2 * tig) = w1;
    }
}

// ---------------- LayerNorm kernels ----------------
__global__ void __launch_bounds__(128) ln_add_k(
    const float* __restrict__ A, const float* __restrict__ R,
    const float* __restrict__ g, const float* __restrict__ be,
    float* __restrict__ O)
{
    const int row = blockIdx.x, t = threadIdx.x;
    const size_t base = (size_t)row * Dd + t * 4;
    float4 a = *(const float4*)(A + base);
    float4 r = *(const float4*)(R + base);
    float x[4] = {a.x + r.x, a.y + r.y, a.z + r.z, a.w + r.w};

    float s = x[0] + x[1] + x[2] + x[3];
    float ss = x[0]*x[0] + x[1]*x[1] + x[2]*x[2] + x[3]*x[3];
    __shared__ float sh1[4], sh2[4];
#pragma unroll
    for (int o = 16; o; o >>= 1) {
        s  += __shfl_xor_sync(0xffffffffu, s, o);
        ss += __shfl_xor_sync(0xffffffffu, ss, o);
    }
    if (!(t & 31)) { sh1[t >> 5] = s; sh2[t >> 5] = ss; }
    __syncthreads();
    s  = sh1[0] + sh1[1] + sh1[2] + sh1[3];
    ss = sh2[0] + sh2[1] + sh2[2] + sh2[3];

    const float mean = s * (1.f / Dd);
    const float var = ss * (1.f / Dd) - mean * mean;
    const float rs = rsqrtf(var + 1e-5f);
    float4 gg = *(const float4*)(g + t * 4);
    float4 bb = *(const float4*)(be + t * 4);
    float4 o4;
    o4.x = (x[0] - mean) * rs * gg.x + bb.x;
    o4.y = (x[1] - mean) * rs * gg.y + bb.y;
    o4.z = (x[2] - mean) * rs * gg.z + bb.z;
    o4.w = (x[3] - mean) * rs * gg.w + bb.w;
    *(float4*)(O + base) = o4;
}

__global__ void __launch_bounds__(128) ln_add_ln_k(
    const float* __restrict__ A, const float* __restrict__ R,
    const float* __restrict__ g2, const float* __restrict__ b2,
    const float* __restrict__ g3, const float* __restrict__ b3,
    float* __restrict__ O)
{
    const int row = blockIdx.x, t = threadIdx.x;
    const size_t base = (size_t)row * Dd + t * 4;
    float4 a = *(const float4*)(A + base);
    float4 r = *(const float4*)(R + base);
    float x[4] = {a.x + r.x, a.y + r.y, a.z + r.z, a.w + r.w};

    __shared__ float sh1[4], sh2[4];
    float s = x[0] + x[1] + x[2] + x[3];
    float ss = x[0]*x[0] + x[1]*x[1] + x[2]*x[2] + x[3]*x[3];
#pragma unroll
    for (int o = 16; o; o >>= 1) {
        s  += __shfl_xor_sync(0xffffffffu, s, o);
        ss += __shfl_xor_sync(0xffffffffu, ss, o);
    }
    if (!(t & 31)) { sh1[t >> 5] = s; sh2[t >> 5] = ss; }
    __syncthreads();
    s  = sh1[0] + sh1[1] + sh1[2] + sh1[3];
    ss = sh2[0] + sh2[1] + sh2[2] + sh2[3];
    float mean = s * (1.f / Dd);
    float var = ss * (1.f / Dd) - mean * mean;
    float rs = rsqrtf(var + 1e-5f);

    float4 gg = *(const float4*)(g2 + t * 4);
    float4 bb = *(const float4*)(b2 + t * 4);
    float y[4];
    y[0] = (x[0] - mean) * rs * gg.x + bb.x;
    y[1] = (x[1] - mean) * rs * gg.y + bb.y;
    y[2] = (x[2] - mean) * rs * gg.z + bb.z;
    y[3] = (x[3] - mean) * rs * gg.w + bb.w;

    __syncthreads();
    s  = y[0] + y[1] + y[2] + y[3];
    ss = y[0]*y[0] + y[1]*y[1] + y[2]*y[2] + y[3]*y[3];
#pragma unroll
    for (int o = 16; o; o >>= 1) {
        s  += __shfl_xor_sync(0xffffffffu, s, o);
        ss += __shfl_xor_sync(0xffffffffu, ss, o);
    }
    if (!(t & 31)) { sh1[t >> 5] = s; sh2[t >> 5] = ss; }
    __syncthreads();
    s  = sh1[0] + sh1[1] + sh1[2] + sh1[3];
    ss = sh2[0] + sh2[1] + sh2[2] + sh2[3];
    mean = s * (1.f / Dd);
    var = ss * (1.f / Dd) - mean * mean;
    rs = rsqrtf(var + 1e-5f);

    float4 g3v = *(const float4*)(g3 + t * 4);
    float4 b3v = *(const float4*)(b3 + t * 4);
    float4 o4;
    o4.x = (y[0] - mean) * rs * g3v.x + b3v.x;
    o4.y = (y[1] - mean) * rs * g3v.y + b3v.y;
    o4.z = (y[2] - mean) * rs * g3v.z + b3v.z;
    o4.w = (y[3] - mean) * rs * g3v.w + b3v.w;
    *(float4*)(O + base) = o4;
}

// ---------------- mean pool over S (deterministic 2-stage) ----------------
__global__ void __launch_bounds__(128) colmean_part_k(const float* __restrict__ X,
                                                      float* __restrict__ PP)
{
    const int b = blockIdx.x >> 2;
    const int d = (blockIdx.x & 3) * 128 + threadIdx.x;
    const int sc = blockIdx.y;
    float s = 0.f;
    for (int j = sc * 128; j < sc * 128 + 128; j++)
        s += X[((size_t)(b * Ss + j)) * Dd + d];
    PP[((size_t)sc * Bb + b) * Dd + d] = s;
}

__global__ void __launch_bounds__(128) colmean_fin_k(const float* __restrict__ PP,
                                                     float* __restrict__ P)
{
    const int idx = blockIdx.x * 128 + threadIdx.x;
    const int b = idx / Dd, d = idx % Dd;
    float s = 0.f;
#pragma unroll
    for (int c = 0; c < 16; c++) s += PP[((size_t)c * Bb + b) * Dd + d];
    P[idx] = s * (1.f / Ss);
}

// ---------------- final tiny GEMM ----------------
__global__ void __launch_bounds__(128) final_k(const float* __restrict__ P,
                                               const float* __restrict__ Wt,
                                               const float* __restrict__ bias,
                                               float* __restrict__ out)
{
    const int b = blockIdx.x, o = threadIdx.x;
    float s = bias[o];
    for (int d = 0; d < Dd; d++) s += P[b * Dd + d] * Wt[d * DOUT + o];
    out[b * DOUT + o] = s;
}

// ---------------- launch ----------------
extern "C" void kernel_launch(void* const* d_in, const int* in_sizes, int n_in,
                              void* d_out, int out_size)
{
    const float* x      = (const float*)d_in[0];
    const float* pos    = (const float*)d_in[1];
    const float* win_w  = (const float*)d_in[2];
    const float* win_b  = (const float*)d_in[3];
    const float* l_wqkv = (const float*)d_in[4];
    const float* l_bqkv = (const float*)d_in[5];
    const float* l_wo   = (const float*)d_in[6];
    const float* l_bo   = (const float*)d_in[7];
    const float* g_wqkv = (const float*)d_in[8];
    const float* g_bqkv = (const float*)d_in[9];
    const float* g_wo   = (const float*)d_in[10];
    const float* g_bo   = (const float*)d_in[11];
    const float* gate_w = (const float*)d_in[12];
    const float* gate_b = (const float*)d_in[13];
    const float* ffn_w1 = (const float*)d_in[14];
    const float* ffn_b1 = (const float*)d_in[15];
    const float* ffn_w2 = (const float*)d_in[16];
    const float* ffn_b2 = (const float*)d_in[17];
    const float* n1_g   = (const float*)d_in[18];
    const float* n1_b   = (const float*)d_in[19];
    const float* n2_g   = (const float*)d_in[20];
    const float* n2_b   = (const float*)d_in[21];
    const float* n3_g   = (const float*)d_in[22];
    const float* n3_b   = (const float*)d_in[23];
    const float* out_w  = (const float*)d_in[24];
    const float* out_b  = (const float*)d_in[25];

    float* sp = nullptr;
    cudaGetSymbolAddress((void**)&sp, g_scratch);
    float* bH   = sp + O_H;
    float* bQL  = sp + O_QL;
    float* bKL  = sp + O_KL;
    float* bVL  = sp + O_VL;
    float* bQG  = sp + O_QG;
    float* bKG  = sp + O_KG;
    float* bVG  = sp + O_VG;
    float* bAOL = sp + O_AOL;
    float* bAOG = sp + O_AOG;
    float* bLOC = sp + O_LOC;
    float* bGLO = sp + O_GLO;
    float* bFUS = sp + O_FUS;
    float* bH1  = sp + O_H1;
    float* bFFN = sp + O_FFN;
    float* bH3  = sp + O_H3;
    float* bT1  = sp + O_T1;
    float* bPP  = sp + O_PP;
    float* bP   = sp + O_P;

    static bool attr_set = false;
    if (!attr_set) {
        cudaFuncSetAttribute(flash_tc_k<0>, cudaFuncAttributeMaxDynamicSharedMemorySize,
                             FL_SMEM_BYTES);
        cudaFuncSetAttribute(flash_tc_k<1>, cudaFuncAttributeMaxDynamicSharedMemorySize,
                             FL_SMEM_BYTES);
        attr_set = true;
    }

    const dim3 blk(256);

    // 1. h = x @ win_w + win_b + pos
    gemm_tc_k<1><<<dim3(4, 64), blk>>>(x, nullptr, DIN, 0, win_w, win_b, pos,
                                       nullptr, bH, BS, Dd, DIN);

    // 2. merged 6-slice QKV (local 0..2, global 3..5) -> bQL..bVG
    gemm_tc_k<4><<<dim3(24, 64), blk>>>(bH, g_bqkv, Dd, 0, l_wqkv, l_bqkv,
                                        g_wqkv, nullptr, bQL, BS, Dd, Dd);

    // 3. local banded flash attention
    flash_tc_k<1><<<dim3(Ss / 128, Hh, Bb), 256, FL_SMEM_BYTES>>>(bQL, bKL, bVL, bAOL);

    // 4. global flash attention
    flash_tc_k<0><<<dim3(Ss / 128, Hh, Bb), 256, FL_SMEM_BYTES>>>(bQG, bKG, bVG, bAOG);

    // 5. merged 2-slice output projections -> bLOC, bGLO
    gemm_tc_k<5><<<dim3(8, 64), blk>>>(bAOL, bAOG, Dd, 0, l_wo, l_bo,
                                       g_wo, g_bo, bLOC, BS, Dd, Dd);

    // 6. gate GEMM fused with blend
    gemm_tc_k<3><<<dim3(4, 64), blk>>>(bLOC, bGLO, Dd, Dd, gate_w, gate_b,
                                       bLOC, bGLO, bFUS, BS, Dd, 2 * Dd);

    // 7. h1 = LN(h + fused)
    ln_add_k<<<BS, 128>>>(bH, bFUS, n1_g, n1_b, bH1);

    // 8. FFN
    gemm_tc_k<2><<<dim3(8, 64), blk>>>(bH1, nullptr, Dd, 0, ffn_w1, ffn_b1,
                                       nullptr, nullptr, bT1, BS, 2 * Dd, Dd);
    gemm_tc_k<0><<<dim3(4, 64), blk>>>(bT1, nullptr, 2 * Dd, 0, ffn_w2, ffn_b2,
                                       nullptr, nullptr, bFFN, BS, Dd, 2 * Dd);

    // 9. h3 = LN(LN(h1 + ffn))
    ln_add_ln_k<<<BS, 128>>>(bH1, bFFN, n2_g, n2_b, n3_g, n3_b, bH3);

    // 10. mean-pool over S, then final projection
    colmean_part_k<<<dim3(Bb * 4, 16), 128>>>(bH3, bPP);
    colmean_fin_k<<<(Bb * Dd) / 128, 128>>>(bPP, bP);
    final_k<<<Bb, DOUT>>>(bP, out_w, out_b, (float*)d_out);

    (void)in_sizes; (void)n_in; (void)out_size;
}

// round 8
// speedup vs baseline: 1.5918x; 1.5834x over previous
#include <cuda_runtime.h>
#include <cuda_fp16.h>
#include <math.h>
#include <stdint.h>

// ---------------- problem constants (hardcoded) ----------------
constexpr int   Bb   = 4;
constexpr int   Ss   = 2048;
constexpr int   DIN  = 256;
constexpr int   Dd   = 512;
constexpr int   Hh   = 8;
constexpr int   DOUT = 128;
constexpr int   HD   = 64;       // Dd / Hh
constexpr int   BS   = Bb * Ss;  // 8192 rows
constexpr float SCALE = 0.125f;  // 1/sqrt(64)

// ---------------- scratch (static device memory; no allocs) ----------------
constexpr size_t NBD  = (size_t)BS * Dd;
constexpr size_t O_H   = 0;
constexpr size_t O_QL  = 1 * NBD;
constexpr size_t O_KL  = 2 * NBD;
constexpr size_t O_VL  = 3 * NBD;
constexpr size_t O_QG  = 4 * NBD;
constexpr size_t O_KG  = 5 * NBD;
constexpr size_t O_VG  = 6 * NBD;
constexpr size_t O_AOL = 7 * NBD;
constexpr size_t O_AOG = 8 * NBD;
constexpr size_t O_LOC = 9 * NBD;
constexpr size_t O_GLO = 10 * NBD;
constexpr size_t O_FUS = 11 * NBD;
constexpr size_t O_H1  = 12 * NBD;
constexpr size_t O_FFN = 13 * NBD;
constexpr size_t O_H3  = 14 * NBD;
constexpr size_t O_T1  = 15 * NBD;  // 2*NBD wide
constexpr size_t O_PP  = 17 * NBD;
constexpr size_t O_P   = 17 * NBD + (size_t)16 * Bb * Dd;
constexpr size_t SCRATCH_FLOATS = O_P + (size_t)Bb * Dd;

__device__ float g_scratch[SCRATCH_FLOATS];

// ---------------- helpers: fp16 pack + mma + ldmatrix ----------------
__device__ __forceinline__ uint32_t pack_h2(float x, float y) {
    __half2 h = __floats2half2_rn(x, y);
    return *(uint32_t*)&h;
}

__device__ __forceinline__ void mma_f16(float c[4], const uint32_t a[4],
                                        uint32_t b0, uint32_t b1) {
    asm volatile(
        "mma.sync.aligned.m16n8k16.row.col.f32.f16.f16.f32 "
        "{%0,%1,%2,%3},{%4,%5,%6,%7},{%8,%9},{%0,%1,%2,%3};\n"
        : "+f"(c[0]), "+f"(c[1]), "+f"(c[2]), "+f"(c[3])
        : "r"(a[0]), "r"(a[1]), "r"(a[2]), "r"(a[3]), "r"(b0), "r"(b1));
}

__device__ __forceinline__ void ldsm_x4(uint32_t r[4], uint32_t saddr) {
    asm volatile("ldmatrix.sync.aligned.m8n8.x4.shared.b16 {%0,%1,%2,%3}, [%4];"
                 : "=r"(r[0]), "=r"(r[1]), "=r"(r[2]), "=r"(r[3]) : "r"(saddr));
}

__device__ __forceinline__ void ldsm_x4_t(uint32_t r[4], uint32_t saddr) {
    asm volatile("ldmatrix.sync.aligned.m8n8.x4.trans.shared.b16 {%0,%1,%2,%3}, [%4];"
                 : "=r"(r[0]), "=r"(r[1]), "=r"(r[2]), "=r"(r[3]) : "r"(saddr));
}

__device__ __forceinline__ uint32_t smem_u32(const void* p) {
    uint32_t a;
    asm("{ .reg .u64 t; cvta.to.shared.u64 t, %1; cvt.u32.u64 %0, t; }"
        : "=r"(a) : "l"(p));
    return a;
}

// ---------------- FP16 tensor-core GEMM, 128x128 tile, fused epilogues -----
// MODE 0: +bias ; 1: +bias+pos ; 2: relu(+bias)
// MODE 3: A=concat(A,A2) on K (split KA); g=tanh(relu(acc+bias)); C=g*p1+(1-g)*p2
// MODE 4: 6-slice QKV ; MODE 5: 2-slice Wo
// As [m][k] stride 24 halfs (ldsm, 3r%8 conflict-free)
// Bs [k][n] stride 136 halfs (ldsm.trans, 17r%8 conflict-free)
constexpr int SRA = 24;
constexpr int SRB = 136;

template <int MODE>
__global__ void __launch_bounds__(256) gemm_tc_k(
    const float* __restrict__ A, const float* __restrict__ A2, int lda, int KA,
    const float* __restrict__ W, const float* __restrict__ bias,
    const float* __restrict__ p1, const float* __restrict__ p2,
    float* __restrict__ C, int M, int N, int K)
{
    __shared__ __half As[2][128][SRA];
    __shared__ __half Bs[2][16][SRB];

    const int t  = threadIdx.x;
    const int m0 = blockIdx.y * 128;

    const float* Asel = A;
    const float* Wsel = W;
    const float* bsel = bias;
    float* Csel = C;
    int n0;
    if (MODE == 4 || MODE == 5) {
        const int isl = blockIdx.x >> 2;
        n0 = (blockIdx.x & 3) * 128;
        if (MODE == 4) {
            Wsel = (isl < 3) ? W + (size_t)isl * Dd * Dd
                             : p1 + (size_t)(isl - 3) * Dd * Dd;
            bsel = (isl < 3) ? bias + isl * Dd : A2 + (isl - 3) * Dd;
        } else {
            Asel = isl ? A2 : A;
            Wsel = isl ? p1 : W;
            bsel = isl ? p2 : bias;
        }
        Csel = C + (size_t)isl * NBD;
    } else {
        n0 = blockIdx.x * 128;
    }

    const int lane = t & 31, w = t >> 5;
    const int wm = w & 1, wn = w >> 1;
    const int gid = lane >> 2, tig = lane & 3;
    const int mw = wm * 64, nw = wn * 32;

    const int amr = t >> 1;          // A loader: m row
    const int akc = (t & 1) * 8;     // A loader: k col 0/8
    const int bkr = t >> 4;          // B loader: k row
    const int bnc = (t & 15) * 8;    // B loader: n col

    // ldmatrix addresses
    const uint32_t aAddr0 = smem_u32(&As[0][mw + (lane & 15)][(lane >> 4) * 8]);
    const uint32_t aAddr1 = smem_u32(&As[1][mw + (lane & 15)][(lane >> 4) * 8]);
    const uint32_t bAddr0 = smem_u32(&Bs[0][(lane & 7) + 8 * ((lane >> 3) & 1)]
                                        [nw + 8 * (lane >> 4)]);
    const uint32_t bAddr1 = smem_u32(&Bs[1][(lane & 7) + 8 * ((lane >> 3) & 1)]
                                        [nw + 8 * (lane >> 4)]);

    float acc[4][4][4] = {};
    float4 pa0, pa1, pb0, pb1;

    {
        const float* Asrc = Asel;
        int kk0 = 0;
        if (MODE == 3 && 0 >= KA) { Asrc = A2; kk0 = -KA; }
        pa0 = *(const float4*)(Asrc + (size_t)(m0 + amr) * lda + kk0 + akc);
        pa1 = *(const float4*)(Asrc + (size_t)(m0 + amr) * lda + kk0 + akc + 4);
        pb0 = *(const float4*)(Wsel + (size_t)bkr * N + n0 + bnc);
        pb1 = *(const float4*)(Wsel + (size_t)bkr * N + n0 + bnc + 4);
    }
    {
        uint4 aw;
        aw.x = pack_h2(pa0.x, pa0.y); aw.y = pack_h2(pa0.z, pa0.w);
        aw.z = pack_h2(pa1.x, pa1.y); aw.w = pack_h2(pa1.z, pa1.w);
        *(uint4*)&As[0][amr][akc] = aw;
        uint4 bw;
        bw.x = pack_h2(pb0.x, pb0.y); bw.y = pack_h2(pb0.z, pb0.w);
        bw.z = pack_h2(pb1.x, pb1.y); bw.w = pack_h2(pb1.z, pb1.w);
        *(uint4*)&Bs[0][bkr][bnc] = bw;
    }
    __syncthreads();

    int buf = 0;
    for (int k0 = 0; k0 < K; k0 += 16) {
        const int kn = k0 + 16;
        const bool has_next = kn < K;
        if (has_next) {
            const float* Asrc = Asel;
            int kk0 = kn;
            if (MODE == 3 && kn >= KA) { Asrc = A2; kk0 = kn - KA; }
            pa0 = *(const float4*)(Asrc + (size_t)(m0 + amr) * lda + kk0 + akc);
            pa1 = *(const float4*)(Asrc + (size_t)(m0 + amr) * lda + kk0 + akc + 4);
            pb0 = *(const float4*)(Wsel + (size_t)(kn + bkr) * N + n0 + bnc);
            pb1 = *(const float4*)(Wsel + (size_t)(kn + bkr) * N + n0 + bnc + 4);
        }

        const uint32_t aA = buf ? aAddr1 : aAddr0;
        const uint32_t bA = buf ? bAddr1 : bAddr0;
        uint32_t af[4][4], bb[2][4];
#pragma unroll
        for (int mt = 0; mt < 4; mt++)
            ldsm_x4(af[mt], aA + (uint32_t)(mt * 16 * SRA * 2));
#pragma unroll
        for (int nb2 = 0; nb2 < 2; nb2++)
            ldsm_x4_t(bb[nb2], bA + (uint32_t)(nb2 * 32));
#pragma unroll
        for (int mt = 0; mt < 4; mt++) {
            mma_f16(acc[mt][0], af[mt], bb[0][0], bb[0][1]);
            mma_f16(acc[mt][1], af[mt], bb[0][2], bb[0][3]);
            mma_f16(acc[mt][2], af[mt], bb[1][0], bb[1][1]);
            mma_f16(acc[mt][3], af[mt], bb[1][2], bb[1][3]);
        }

        if (has_next) {
            const int nb = buf ^ 1;
            uint4 aw;
            aw.x = pack_h2(pa0.x, pa0.y); aw.y = pack_h2(pa0.z, pa0.w);
            aw.z = pack_h2(pa1.x, pa1.y); aw.w = pack_h2(pa1.z, pa1.w);
            *(uint4*)&As[nb][amr][akc] = aw;
            uint4 bw;
            bw.x = pack_h2(pb0.x, pb0.y); bw.y = pack_h2(pb0.z, pb0.w);
            bw.z = pack_h2(pb1.x, pb1.y); bw.w = pack_h2(pb1.z, pb1.w);
            *(uint4*)&Bs[nb][bkr][bnc] = bw;
        }
        __syncthreads();
        buf ^= 1;
    }

#pragma unroll
    for (int mt = 0; mt < 4; mt++) {
#pragma unroll
        for (int half = 0; half < 2; half++) {
            const int row = m0 + mw + mt * 16 + gid + half * 8;
#pragma unroll
            for (int nt = 0; nt < 4; nt++) {
                const int col = n0 + nw + nt * 8 + tig * 2;
                float v0 = acc[mt][nt][half * 2 + 0] + bsel[col];
                float v1 = acc[mt][nt][half * 2 + 1] + bsel[col + 1];
                if (MODE == 1) {
                    const size_t pr = (size_t)(row & (Ss - 1)) * N + col;
                    v0 += p1[pr]; v1 += p1[pr + 1];
                }
                if (MODE == 2) { v0 = fmaxf(v0, 0.f); v1 = fmaxf(v1, 0.f); }
                if (MODE == 3) {
                    const size_t pr = (size_t)row * N + col;
                    float g0 = tanhf(fmaxf(v0, 0.f));
                    float g1 = tanhf(fmaxf(v1, 0.f));
                    v0 = g0 * p1[pr] + (1.f - g0) * p2[pr];
                    v1 = g1 * p1[pr + 1] + (1.f - g1) * p2[pr + 1];
                }
                float2 o2; o2.x = v0; o2.y = v1;
                *(float2*)(Csel + (size_t)row * N + col) = o2;
            }
        }
    }
}

// ---------------- FP16 tensor-core flash attention ------------------------
// BANDED=0: full. BANDED=1: band |q-k|<=32.
// Q-tile 128, K-tile 64, HD=64. 8 warps x 16 q-rows, mma m16n8k16.
// smem halfs: Qs[128][72], Ps[128][72], Ks[64][72], Vs[64][72]  (9r%8 ✓)
constexpr int SRF = 72;
constexpr int FQ_OFF = 0;
constexpr int FP_OFF = 128 * SRF;
constexpr int FK_OFF = 2 * 128 * SRF;
constexpr int FV_OFF = FK_OFF + 64 * SRF;
constexpr int FL_SMEM_HALFS = FV_OFF + 64 * SRF;
constexpr int FL_SMEM_BYTES = FL_SMEM_HALFS * 2;   // 55,296 B

template <int BANDED>
__global__ void __launch_bounds__(256) flash_tc_k(
    const float* __restrict__ Q, const float* __restrict__ K,
    const float* __restrict__ V, float* __restrict__ O)
{
    extern __shared__ __half smh[];
    __half* Qs = smh + FQ_OFF;
    __half* Ps = smh + FP_OFF;
    __half* Ks = smh + FK_OFF;
    __half* Vs = smh + FV_OFF;

    const int qt = blockIdx.x, h = blockIdx.y, b = blockIdx.z;
    const int t  = threadIdx.x;
    const int lane = t & 31, w = t >> 5;
    const int gid = lane >> 2, tig = lane & 3;
    const int q0 = w * 16;

    // ldmatrix lane addresses
    const uint32_t qA = smem_u32(&Qs[(q0 + (lane & 15)) * SRF + (lane >> 4) * 8]);
    const uint32_t pA = smem_u32(&Ps[(q0 + (lane & 15)) * SRF + (lane >> 4) * 8]);
    const uint32_t kA = smem_u32(&Ks[((lane & 7) + 8 * ((lane >> 3) & 1)) * SRF
                                     + (lane >> 4) * 8]);
    const uint32_t vA = smem_u32(&Vs[((lane & 7) + 8 * ((lane >> 3) & 1)) * SRF
                                     + (lane >> 4) * 8]);
    constexpr uint32_t ROW16 = 16 * SRF * 2;   // 16-row byte stride

    // ---- load Q tile (pre-scaled, fp16) ----
    {
        const int r  = t >> 1;
        const int c0 = (t & 1) * 32;
        const float* src = Q + ((size_t)(b * Ss + qt * 128 + r)) * Dd + h * HD + c0;
#pragma unroll
        for (int i = 0; i < 8; i++) {
            float4 v = *(const float4*)(src + i * 4);
            uint2 pk;
            pk.x = pack_h2(v.x * SCALE, v.y * SCALE);
            pk.y = pack_h2(v.z * SCALE, v.w * SCALE);
            *(uint2*)&Qs[r * SRF + c0 + i * 4] = pk;
        }
    }

    float o_acc[8][4] = {};
    float m0 = -1e30f, m1 = -1e30f, l0 = 0.f, l1 = 0.f;

    const int rowA0 = (q0 + gid) * SRF;
    const int rowA1 = (q0 + gid + 8) * SRF;
    const int qr0 = qt * 128 + q0 + gid;
    const int qr1 = qr0 + 8;

    int k_begin = 0, k_end = Ss;
    if (BANDED) {
        k_begin = qt * 128 - 64; if (k_begin < 0) k_begin = 0;
        k_end   = qt * 128 + 192; if (k_end > Ss) k_end = Ss;
    }

    for (int k0 = k_begin; k0 < k_end; k0 += 64) {
        __syncthreads();

        // ---- load K/V tiles (fp16, both row-major [key][d]) ----
        {
            const int r  = t >> 2;
            const int c0 = (t & 3) * 16;
            const float* ks = K + ((size_t)(b * Ss + k0 + r)) * Dd + h * HD + c0;
            const float* vs = V + ((size_t)(b * Ss + k0 + r)) * Dd + h * HD + c0;
#pragma unroll
            for (int i = 0; i < 4; i++) {
                float4 kv = *(const float4*)(ks + i * 4);
                uint2 pk;
                pk.x = pack_h2(kv.x, kv.y); pk.y = pack_h2(kv.z, kv.w);
                *(uint2*)&Ks[r * SRF + c0 + i * 4] = pk;
                float4 vv = *(const float4*)(vs + i * 4);
                uint2 pv;
                pv.x = pack_h2(vv.x, vv.y); pv.y = pack_h2(vv.z, vv.w);
                *(uint2*)&Vs[r * SRF + c0 + i * 4] = pv;
            }
        }
        __syncthreads();

        // ---- S = Q K^T : 4 k16-steps over d ----
        float sreg[8][4] = {};
#pragma unroll
        for (int kk = 0; kk < 4; kk++) {
            uint32_t a[4];
            ldsm_x4(a, qA + (uint32_t)(kk * 32));
#pragma unroll
            for (int nt2 = 0; nt2 < 4; nt2++) {
                uint32_t kb[4];
                ldsm_x4(kb, kA + (uint32_t)(nt2 * ROW16 + kk * 32));
                mma_f16(sreg[2 * nt2],     a, kb[0], kb[2]);
                mma_f16(sreg[2 * nt2 + 1], a, kb[1], kb[3]);
            }
        }

        // ---- band mask ----
        if (BANDED) {
#pragma unroll
            for (int nt = 0; nt < 8; nt++) {
                const int kg = k0 + nt * 8 + 2 * tig;
                if (abs(qr0 - kg)       > 32) sreg[nt][0] = -1e30f;
                if (abs(qr0 - (kg + 1)) > 32) sreg[nt][1] = -1e30f;
                if (abs(qr1 - kg)       > 32) sreg[nt][2] = -1e30f;
                if (abs(qr1 - (kg + 1)) > 32) sreg[nt][3] = -1e30f;
            }
        }

        // ---- online softmax ----
        float mt0 = -1e30f, mt1 = -1e30f;
#pragma unroll
        for (int nt = 0; nt < 8; nt++) {
            mt0 = fmaxf(mt0, fmaxf(sreg[nt][0], sreg[nt][1]));
            mt1 = fmaxf(mt1, fmaxf(sreg[nt][2], sreg[nt][3]));
        }
        mt0 = fmaxf(mt0, __shfl_xor_sync(0xffffffffu, mt0, 1));
        mt0 = fmaxf(mt0, __shfl_xor_sync(0xffffffffu, mt0, 2));
        mt1 = fmaxf(mt1, __shfl_xor_sync(0xffffffffu, mt1, 1));
        mt1 = fmaxf(mt1, __shfl_xor_sync(0xffffffffu, mt1, 2));

        const float mn0 = fmaxf(m0, mt0), mn1 = fmaxf(m1, mt1);
        const float al0 = __expf(m0 - mn0), al1 = __expf(m1 - mn1);
        m0 = mn0; m1 = mn1;

        float ls0 = 0.f, ls1 = 0.f;
#pragma unroll
        for (int nt = 0; nt < 8; nt++) {
            float p00, p01, p10, p11;
            if (BANDED) {
                p00 = (sreg[nt][0] > -1e29f) ? __expf(sreg[nt][0] - mn0) : 0.f;
                p01 = (sreg[nt][1] > -1e29f) ? __expf(sreg[nt][1] - mn0) : 0.f;
                p10 = (sreg[nt][2] > -1e29f) ? __expf(sreg[nt][2] - mn1) : 0.f;
                p11 = (sreg[nt][3] > -1e29f) ? __expf(sreg[nt][3] - mn1) : 0.f;
            } else {
                p00 = __expf(sreg[nt][0] - mn0);
                p01 = __expf(sreg[nt][1] - mn0);
                p10 = __expf(sreg[nt][2] - mn1);
                p11 = __expf(sreg[nt][3] - mn1);
            }
            ls0 += p00 + p01;
            ls1 += p10 + p11;
            *(uint32_t*)&Ps[rowA0 + nt * 8 + 2 * tig] = pack_h2(p00, p01);
            *(uint32_t*)&Ps[rowA1 + nt * 8 + 2 * tig] = pack_h2(p10, p11);
        }
        ls0 += __shfl_xor_sync(0xffffffffu, ls0, 1);
        ls0 += __shfl_xor_sync(0xffffffffu, ls0, 2);
        ls1 += __shfl_xor_sync(0xffffffffu, ls1, 1);
        ls1 += __shfl_xor_sync(0xffffffffu, ls1, 2);
        l0 = l0 * al0 + ls0;
        l1 = l1 * al1 + ls1;
#pragma unroll
        for (int nt = 0; nt < 8; nt++) {
            o_acc[nt][0] *= al0; o_acc[nt][1] *= al0;
            o_acc[nt][2] *= al1; o_acc[nt][3] *= al1;
        }
        __syncwarp();   // Ps rows q0..q0+15 are warp-local

        // ---- O += P V : 4 k16-steps over keys ----
#pragma unroll
        for (int kk = 0; kk < 4; kk++) {
            uint32_t a[4];
            ldsm_x4(a, pA + (uint32_t)(kk * 32));
#pragma unroll
            for (int nt2 = 0; nt2 < 4; nt2++) {
                uint32_t vb[4];
                ldsm_x4_t(vb, vA + (uint32_t)(kk * ROW16 + nt2 * 32));
                mma_f16(o_acc[2 * nt2],     a, vb[0], vb[1]);
                mma_f16(o_acc[2 * nt2 + 1], a, vb[2], vb[3]);
            }
        }
    }

    // ---- epilogue ----
    const float inv0 = 1.f / l0, inv1 = 1.f / l1;
    float* orow0 = O + ((size_t)(b * Ss + qt * 128 + q0 + gid)) * Dd + h * HD;
    float* orow1 = O + ((size_t)(b * Ss + qt * 128 + q0 + gid + 8)) * Dd + h * HD;
#pragma unroll
    for (int nt = 0; nt < 8; nt++) {
        float2 w0; w0.x = o_acc[nt][0] * inv0; w0.y = o_acc[nt][1] * inv0;
        float2 w1; w1.x = o_acc[nt][2] * inv1; w1.y = o_acc[nt][3] * inv1;
        *(float2*)(orow0 + nt * 8 + 2 * tig) = w0;
        *(float2*)(orow1 + nt * 8 + 2 * tig) = w1;
    }
}

// ---------------- LayerNorm kernels ----------------
__global__ void __launch_bounds__(128) ln_add_k(
    const float* __restrict__ A, const float* __restrict__ R,
    const float* __restrict__ g, const float* __restrict__ be,
    float* __restrict__ O)
{
    const int row = blockIdx.x, t = threadIdx.x;
    const size_t base = (size_t)row * Dd + t * 4;
    float4 a = *(const float4*)(A + base);
    float4 r = *(const float4*)(R + base);
    float x[4] = {a.x + r.x, a.y + r.y, a.z + r.z, a.w + r.w};

    float s = x[0] + x[1] + x[2] + x[3];
    float ss = x[0]*x[0] + x[1]*x[1] + x[2]*x[2] + x[3]*x[3];
    __shared__ float sh1[4], sh2[4];
#pragma unroll
    for (int o = 16; o; o >>= 1) {
        s  += __shfl_xor_sync(0xffffffffu, s, o);
        ss += __shfl_xor_sync(0xffffffffu, ss, o);
    }
    if (!(t & 31)) { sh1[t >> 5] = s; sh2[t >> 5] = ss; }
    __syncthreads();
    s  = sh1[0] + sh1[1] + sh1[2] + sh1[3];
    ss = sh2[0] + sh2[1] + sh2[2] + sh2[3];

    const float mean = s * (1.f / Dd);
    const float var = ss * (1.f / Dd) - mean * mean;
    const float rs = rsqrtf(var + 1e-5f);
    float4 gg = *(const float4*)(g + t * 4);
    float4 bb = *(const float4*)(be + t * 4);
    float4 o4;
    o4.x = (x[0] - mean) * rs * gg.x + bb.x;
    o4.y = (x[1] - mean) * rs * gg.y + bb.y;
    o4.z = (x[2] - mean) * rs * gg.z + bb.z;
    o4.w = (x[3] - mean) * rs * gg.w + bb.w;
    *(float4*)(O + base) = o4;
}

__global__ void __launch_bounds__(128) ln_add_ln_k(
    const float* __restrict__ A, const float* __restrict__ R,
    const float* __restrict__ g2, const float* __restrict__ b2,
    const float* __restrict__ g3, const float* __restrict__ b3,
    float* __restrict__ O)
{
    const int row = blockIdx.x, t = threadIdx.x;
    const size_t base = (size_t)row * Dd + t * 4;
    float4 a = *(const float4*)(A + base);
    float4 r = *(const float4*)(R + base);
    float x[4] = {a.x + r.x, a.y + r.y, a.z + r.z, a.w + r.w};

    __shared__ float sh1[4], sh2[4];
    float s = x[0] + x[1] + x[2] + x[3];
    float ss = x[0]*x[0] + x[1]*x[1] + x[2]*x[2] + x[3]*x[3];
#pragma unroll
    for (int o = 16; o; o >>= 1) {
        s  += __shfl_xor_sync(0xffffffffu, s, o);
        ss += __shfl_xor_sync(0xffffffffu, ss, o);
    }
    if (!(t & 31)) { sh1[t >> 5] = s; sh2[t >> 5] = ss; }
    __syncthreads();
    s  = sh1[0] + sh1[1] + sh1[2] + sh1[3];
    ss = sh2[0] + sh2[1] + sh2[2] + sh2[3];
    float mean = s * (1.f / Dd);
    float var = ss * (1.f / Dd) - mean * mean;
    float rs = rsqrtf(var + 1e-5f);

    float4 gg = *(const float4*)(g2 + t * 4);
    float4 bb = *(const float4*)(b2 + t * 4);
    float y[4];
    y[0] = (x[0] - mean) * rs * gg.x + bb.x;
    y[1] = (x[1] - mean) * rs * gg.y + bb.y;
    y[2] = (x[2] - mean) * rs * gg.z + bb.z;
    y[3] = (x[3] - mean) * rs * gg.w + bb.w;

    __syncthreads();
    s  = y[0] + y[1] + y[2] + y[3];
    ss = y[0]*y[0] + y[1]*y[1] + y[2]*y[2] + y[3]*y[3];
#pragma unroll
    for (int o = 16; o; o >>= 1) {
        s  += __shfl_xor_sync(0xffffffffu, s, o);
        ss += __shfl_xor_sync(0xffffffffu, ss, o);
    }
    if (!(t & 31)) { sh1[t >> 5] = s; sh2[t >> 5] = ss; }
    __syncthreads();
    s  = sh1[0] + sh1[1] + sh1[2] + sh1[3];
    ss = sh2[0] + sh2[1] + sh2[2] + sh2[3];
    mean = s * (1.f / Dd);
    var = ss * (1.f / Dd) - mean * mean;
    rs = rsqrtf(var + 1e-5f);

    float4 g3v = *(const float4*)(g3 + t * 4);
    float4 b3v = *(const float4*)(b3 + t * 4);
    float4 o4;
    o4.x = (y[0] - mean) * rs * g3v.x + b3v.x;
    o4.y = (y[1] - mean) * rs * g3v.y + b3v.y;
    o4.z = (y[2] - mean) * rs * g3v.z + b3v.z;
    o4.w = (y[3] - mean) * rs * g3v.w + b3v.w;
    *(float4*)(O + base) = o4;
}

// ---------------- mean pool over S (deterministic 2-stage) ----------------
__global__ void __launch_bounds__(128) colmean_part_k(const float* __restrict__ X,
                                                      float* __restrict__ PP)
{
    const int b = blockIdx.x >> 2;
    const int d = (blockIdx.x & 3) * 128 + threadIdx.x;
    const int sc = blockIdx.y;
    float s = 0.f;
    for (int j = sc * 128; j < sc * 128 + 128; j++)
        s += X[((size_t)(b * Ss + j)) * Dd + d];
    PP[((size_t)sc * Bb + b) * Dd + d] = s;
}

__global__ void __launch_bounds__(128) colmean_fin_k(const float* __restrict__ PP,
                                                     float* __restrict__ P)
{
    const int idx = blockIdx.x * 128 + threadIdx.x;
    const int b = idx / Dd, d = idx % Dd;
    float s = 0.f;
#pragma unroll
    for (int c = 0; c < 16; c++) s += PP[((size_t)c * Bb + b) * Dd + d];
    P[idx] = s * (1.f / Ss);
}

// ---------------- final tiny GEMM ----------------
__global__ void __launch_bounds__(128) final_k(const float* __restrict__ P,
                                               const float* __restrict__ Wt,
                                               const float* __restrict__ bias,
                                               float* __restrict__ out)
{
    const int b = blockIdx.x, o = threadIdx.x;
    float s = bias[o];
    for (int d = 0; d < Dd; d++) s += P[b * Dd + d] * Wt[d * DOUT + o];
    out[b * DOUT + o] = s;
}

// ---------------- launch ----------------
extern "C" void kernel_launch(void* const* d_in, const int* in_sizes, int n_in,
                              void* d_out, int out_size)
{
    const float* x      = (const float*)d_in[0];
    const float* pos    = (const float*)d_in[1];
    const float* win_w  = (const float*)d_in[2];
    const float* win_b  = (const float*)d_in[3];
    const float* l_wqkv = (const float*)d_in[4];
    const float* l_bqkv = (const float*)d_in[5];
    const float* l_wo   = (const float*)d_in[6];
    const float* l_bo   = (const float*)d_in[7];
    const float* g_wqkv = (const float*)d_in[8];
    const float* g_bqkv = (const float*)d_in[9];
    const float* g_wo   = (const float*)d_in[10];
    const float* g_bo   = (const float*)d_in[11];
    const float* gate_w = (const float*)d_in[12];
    const float* gate_b = (const float*)d_in[13];
    const float* ffn_w1 = (const float*)d_in[14];
    const float* ffn_b1 = (const float*)d_in[15];
    const float* ffn_w2 = (const float*)d_in[16];
    const float* ffn_b2 = (const float*)d_in[17];
    const float* n1_g   = (const float*)d_in[18];
    const float* n1_b   = (const float*)d_in[19];
    const float* n2_g   = (const float*)d_in[20];
    const float* n2_b   = (const float*)d_in[21];
    const float* n3_g   = (const float*)d_in[22];
    const float* n3_b   = (const float*)d_in[23];
    const float* out_w  = (const float*)d_in[24];
    const float* out_b  = (const float*)d_in[25];

    float* sp = nullptr;
    cudaGetSymbolAddress((void**)&sp, g_scratch);
    float* bH   = sp + O_H;
    float* bQL  = sp + O_QL;
    float* bKL  = sp + O_KL;
    float* bVL  = sp + O_VL;
    float* bQG  = sp + O_QG;
    float* bKG  = sp + O_KG;
    float* bVG  = sp + O_VG;
    float* bAOL = sp + O_AOL;
    float* bAOG = sp + O_AOG;
    float* bLOC = sp + O_LOC;
    float* bGLO = sp + O_GLO;
    float* bFUS = sp + O_FUS;
    float* bH1  = sp + O_H1;
    float* bFFN = sp + O_FFN;
    float* bH3  = sp + O_H3;
    float* bT1  = sp + O_T1;
    float* bPP  = sp + O_PP;
    float* bP   = sp + O_P;

    static bool attr_set = false;
    if (!attr_set) {
        cudaFuncSetAttribute(flash_tc_k<0>, cudaFuncAttributeMaxDynamicSharedMemorySize,
                             FL_SMEM_BYTES);
        cudaFuncSetAttribute(flash_tc_k<1>, cudaFuncAttributeMaxDynamicSharedMemorySize,
                             FL_SMEM_BYTES);
        attr_set = true;
    }

    const dim3 blk(256);

    // 1. h = x @ win_w + win_b + pos
    gemm_tc_k<1><<<dim3(4, 64), blk>>>(x, nullptr, DIN, 0, win_w, win_b, pos,
                                       nullptr, bH, BS, Dd, DIN);

    // 2. merged 6-slice QKV (local 0..2, global 3..5) -> bQL..bVG
    gemm_tc_k<4><<<dim3(24, 64), blk>>>(bH, g_bqkv, Dd, 0, l_wqkv, l_bqkv,
                                        g_wqkv, nullptr, bQL, BS, Dd, Dd);

    // 3. local banded flash attention
    flash_tc_k<1><<<dim3(Ss / 128, Hh, Bb), 256, FL_SMEM_BYTES>>>(bQL, bKL, bVL, bAOL);

    // 4. global flash attention
    flash_tc_k<0><<<dim3(Ss / 128, Hh, Bb), 256, FL_SMEM_BYTES>>>(bQG, bKG, bVG, bAOG);

    // 5. merged 2-slice output projections -> bLOC, bGLO
    gemm_tc_k<5><<<dim3(8, 64), blk>>>(bAOL, bAOG, Dd, 0, l_wo, l_bo,
                                       g_wo, g_bo, bLOC, BS, Dd, Dd);

    // 6. gate GEMM fused with blend
    gemm_tc_k<3><<<dim3(4, 64), blk>>>(bLOC, bGLO, Dd, Dd, gate_w, gate_b,
                                       bLOC, bGLO, bFUS, BS, Dd, 2 * Dd);

    // 7. h1 = LN(h + fused)
    ln_add_k<<<BS, 128>>>(bH, bFUS, n1_g, n1_b, bH1);

    // 8. FFN
    gemm_tc_k<2><<<dim3(8, 64), blk>>>(bH1, nullptr, Dd, 0, ffn_w1, ffn_b1,
                                       nullptr, nullptr, bT1, BS, 2 * Dd, Dd);
    gemm_tc_k<0><<<dim3(4, 64), blk>>>(bT1, nullptr, 2 * Dd, 0, ffn_w2, ffn_b2,
                                       nullptr, nullptr, bFFN, BS, Dd, 2 * Dd);

    // 9. h3 = LN(LN(h1 + ffn))
    ln_add_ln_k<<<BS, 128>>>(bH1, bFFN, n2_g, n2_b, n3_g, n3_b, bH3);

    // 10. mean-pool over S, then final projection
    colmean_part_k<<<dim3(Bb * 4, 16), 128>>>(bH3, bPP);
    colmean_fin_k<<<(Bb * Dd) / 128, 128>>>(bPP, bP);
    final_k<<<Bb, DOUT>>>(bP, out_w, out_b, (float*)d_out);

    (void)in_sizes; (void)n_in; (void)out_size;
}

// round 9
// speedup vs baseline: 1.7207x; 1.0810x over previous
#include <cuda_runtime.h>
#include <cuda_fp16.h>
#include <math.h>
#include <stdint.h>

// ---------------- problem constants (hardcoded) ----------------
constexpr int   Bb   = 4;
constexpr int   Ss   = 2048;
constexpr int   DIN  = 256;
constexpr int   Dd   = 512;
constexpr int   Hh   = 8;
constexpr int   DOUT = 128;
constexpr int   HD   = 64;       // Dd / Hh
constexpr int   BS   = Bb * Ss;  // 8192 rows
constexpr float SCALE = 0.125f;  // 1/sqrt(64)

// ---------------- scratch (static device memory; no allocs) ----------------
constexpr size_t NBD  = (size_t)BS * Dd;
constexpr size_t O_H   = 0;
constexpr size_t O_QL  = 1 * NBD;   // QKV buffers hold fp16 (half of each slot)
constexpr size_t O_KL  = 2 * NBD;
constexpr size_t O_VL  = 3 * NBD;
constexpr size_t O_QG  = 4 * NBD;
constexpr size_t O_KG  = 5 * NBD;
constexpr size_t O_VG  = 6 * NBD;
constexpr size_t O_AOL = 7 * NBD;
constexpr size_t O_AOG = 8 * NBD;
constexpr size_t O_LOC = 9 * NBD;
constexpr size_t O_GLO = 10 * NBD;
constexpr size_t O_FUS = 11 * NBD;
constexpr size_t O_H1  = 12 * NBD;
constexpr size_t O_FFN = 13 * NBD;
constexpr size_t O_H3  = 14 * NBD;
constexpr size_t O_T1  = 15 * NBD;  // 2*NBD wide
constexpr size_t O_PP  = 17 * NBD;
constexpr size_t O_P   = 17 * NBD + (size_t)16 * Bb * Dd;
constexpr size_t SCRATCH_FLOATS = O_P + (size_t)Bb * Dd;

__device__ float g_scratch[SCRATCH_FLOATS];

// ---------------- helpers ----------------
__device__ __forceinline__ uint32_t pack_h2(float x, float y) {
    __half2 h = __floats2half2_rn(x, y);
    return *(uint32_t*)&h;
}

__device__ __forceinline__ void mma_f16(float c[4], const uint32_t a[4],
                                        uint32_t b0, uint32_t b1) {
    asm volatile(
        "mma.sync.aligned.m16n8k16.row.col.f32.f16.f16.f32 "
        "{%0,%1,%2,%3},{%4,%5,%6,%7},{%8,%9},{%0,%1,%2,%3};\n"
        : "+f"(c[0]), "+f"(c[1]), "+f"(c[2]), "+f"(c[3])
        : "r"(a[0]), "r"(a[1]), "r"(a[2]), "r"(a[3]), "r"(b0), "r"(b1));
}

__device__ __forceinline__ void ldsm_x4(uint32_t r[4], uint32_t saddr) {
    asm volatile("ldmatrix.sync.aligned.m8n8.x4.shared.b16 {%0,%1,%2,%3}, [%4];"
                 : "=r"(r[0]), "=r"(r[1]), "=r"(r[2]), "=r"(r[3]) : "r"(saddr));
}

__device__ __forceinline__ void ldsm_x4_t(uint32_t r[4], uint32_t saddr) {
    asm volatile("ldmatrix.sync.aligned.m8n8.x4.trans.shared.b16 {%0,%1,%2,%3}, [%4];"
                 : "=r"(r[0]), "=r"(r[1]), "=r"(r[2]), "=r"(r[3]) : "r"(saddr));
}

__device__ __forceinline__ uint32_t smem_u32(const void* p) {
    uint32_t a;
    asm("{ .reg .u64 t; cvta.to.shared.u64 t, %1; cvt.u32.u64 %0, t; }"
        : "=r"(a) : "l"(p));
    return a;
}

__device__ __forceinline__ void cp_async16(uint32_t dst, const void* src) {
    asm volatile("cp.async.cg.shared.global [%0], [%1], 16;"
                 :: "r"(dst), "l"(src));
}
__device__ __forceinline__ void cp_async_commit() {
    asm volatile("cp.async.commit_group;");
}
template <int N>
__device__ __forceinline__ void cp_async_wait() {
    asm volatile("cp.async.wait_group %0;" :: "n"(N));
}

// ---------------- FP16 tensor-core GEMM, 128x128 tile, fused epilogues -----
// MODE 0: +bias ; 1: +bias+pos ; 2: relu(+bias)
// MODE 3: A=concat(A,A2) on K; g=tanh(relu(acc+bias)); C=g*p1+(1-g)*p2
// MODE 4: 6-slice QKV, OUTPUT IS FP16 (half2), Q slices (isl 0,3) pre-scaled
// MODE 5: 2-slice Wo
constexpr int SRA = 24;
constexpr int SRB = 136;

template <int MODE>
__global__ void __launch_bounds__(256) gemm_tc_k(
    const float* __restrict__ A, const float* __restrict__ A2, int lda, int KA,
    const float* __restrict__ W, const float* __restrict__ bias,
    const float* __restrict__ p1, const float* __restrict__ p2,
    float* __restrict__ C, int M, int N, int K)
{
    __shared__ __half As[2][128][SRA];
    __shared__ __half Bs[2][16][SRB];

    const int t  = threadIdx.x;
    const int m0 = blockIdx.y * 128;

    const float* Asel = A;
    const float* Wsel = W;
    const float* bsel = bias;
    float* Csel = C;
    float oscale = 1.f;
    int n0;
    if (MODE == 4 || MODE == 5) {
        const int isl = blockIdx.x >> 2;
        n0 = (blockIdx.x & 3) * 128;
        if (MODE == 4) {
            Wsel = (isl < 3) ? W + (size_t)isl * Dd * Dd
                             : p1 + (size_t)(isl - 3) * Dd * Dd;
            bsel = (isl < 3) ? bias + isl * Dd : A2 + (isl - 3) * Dd;
            if (isl == 0 || isl == 3) oscale = SCALE;   // Q slices
        } else {
            Asel = isl ? A2 : A;
            Wsel = isl ? p1 : W;
            bsel = isl ? p2 : bias;
        }
        Csel = C + (size_t)isl * NBD;
    } else {
        n0 = blockIdx.x * 128;
    }

    const int lane = t & 31, w = t >> 5;
    const int wm = w & 1, wn = w >> 1;
    const int gid = lane >> 2, tig = lane & 3;
    const int mw = wm * 64, nw = wn * 32;

    const int amr = t >> 1;
    const int akc = (t & 1) * 8;
    const int bkr = t >> 4;
    const int bnc = (t & 15) * 8;

    const uint32_t aAddr0 = smem_u32(&As[0][mw + (lane & 15)][(lane >> 4) * 8]);
    const uint32_t aAddr1 = smem_u32(&As[1][mw + (lane & 15)][(lane >> 4) * 8]);
    const uint32_t bAddr0 = smem_u32(&Bs[0][(lane & 7) + 8 * ((lane >> 3) & 1)]
                                        [nw + 8 * (lane >> 4)]);
    const uint32_t bAddr1 = smem_u32(&Bs[1][(lane & 7) + 8 * ((lane >> 3) & 1)]
                                        [nw + 8 * (lane >> 4)]);

    float acc[4][4][4] = {};
    float4 pa0, pa1, pb0, pb1;

    {
        const float* Asrc = Asel;
        int kk0 = 0;
        if (MODE == 3 && 0 >= KA) { Asrc = A2; kk0 = -KA; }
        pa0 = *(const float4*)(Asrc + (size_t)(m0 + amr) * lda + kk0 + akc);
        pa1 = *(const float4*)(Asrc + (size_t)(m0 + amr) * lda + kk0 + akc + 4);
        pb0 = *(const float4*)(Wsel + (size_t)bkr * N + n0 + bnc);
        pb1 = *(const float4*)(Wsel + (size_t)bkr * N + n0 + bnc + 4);
    }
    {
        uint4 aw;
        aw.x = pack_h2(pa0.x, pa0.y); aw.y = pack_h2(pa0.z, pa0.w);
        aw.z = pack_h2(pa1.x, pa1.y); aw.w = pack_h2(pa1.z, pa1.w);
        *(uint4*)&As[0][amr][akc] = aw;
        uint4 bw;
        bw.x = pack_h2(pb0.x, pb0.y); bw.y = pack_h2(pb0.z, pb0.w);
        bw.z = pack_h2(pb1.x, pb1.y); bw.w = pack_h2(pb1.z, pb1.w);
        *(uint4*)&Bs[0][bkr][bnc] = bw;
    }
    __syncthreads();

    int buf = 0;
    for (int k0 = 0; k0 < K; k0 += 16) {
        const int kn = k0 + 16;
        const bool has_next = kn < K;
        if (has_next) {
            const float* Asrc = Asel;
            int kk0 = kn;
            if (MODE == 3 && kn >= KA) { Asrc = A2; kk0 = kn - KA; }
            pa0 = *(const float4*)(Asrc + (size_t)(m0 + amr) * lda + kk0 + akc);
            pa1 = *(const float4*)(Asrc + (size_t)(m0 + amr) * lda + kk0 + akc + 4);
            pb0 = *(const float4*)(Wsel + (size_t)(kn + bkr) * N + n0 + bnc);
            pb1 = *(const float4*)(Wsel + (size_t)(kn + bkr) * N + n0 + bnc + 4);
        }

        const uint32_t aA = buf ? aAddr1 : aAddr0;
        const uint32_t bA = buf ? bAddr1 : bAddr0;
        uint32_t af[4][4], bb[2][4];
#pragma unroll
        for (int mt = 0; mt < 4; mt++)
            ldsm_x4(af[mt], aA + (uint32_t)(mt * 16 * SRA * 2));
#pragma unroll
        for (int nb2 = 0; nb2 < 2; nb2++)
            ldsm_x4_t(bb[nb2], bA + (uint32_t)(nb2 * 32));
#pragma unroll
        for (int mt = 0; mt < 4; mt++) {
            mma_f16(acc[mt][0], af[mt], bb[0][0], bb[0][1]);
            mma_f16(acc[mt][1], af[mt], bb[0][2], bb[0][3]);
            mma_f16(acc[mt][2], af[mt], bb[1][0], bb[1][1]);
            mma_f16(acc[mt][3], af[mt], bb[1][2], bb[1][3]);
        }

        if (has_next) {
            const int nb = buf ^ 1;
            uint4 aw;
            aw.x = pack_h2(pa0.x, pa0.y); aw.y = pack_h2(pa0.z, pa0.w);
            aw.z = pack_h2(pa1.x, pa1.y); aw.w = pack_h2(pa1.z, pa1.w);
            *(uint4*)&As[nb][amr][akc] = aw;
            uint4 bw;
            bw.x = pack_h2(pb0.x, pb0.y); bw.y = pack_h2(pb0.z, pb0.w);
            bw.z = pack_h2(pb1.x, pb1.y); bw.w = pack_h2(pb1.z, pb1.w);
            *(uint4*)&Bs[nb][bkr][bnc] = bw;
        }
        __syncthreads();
        buf ^= 1;
    }

#pragma unroll
    for (int mt = 0; mt < 4; mt++) {
#pragma unroll
        for (int half = 0; half < 2; half++) {
            const int row = m0 + mw + mt * 16 + gid + half * 8;
#pragma unroll
            for (int nt = 0; nt < 4; nt++) {
                const int col = n0 + nw + nt * 8 + tig * 2;
                float v0 = acc[mt][nt][half * 2 + 0] + bsel[col];
                float v1 = acc[mt][nt][half * 2 + 1] + bsel[col + 1];
                if (MODE == 1) {
                    const size_t pr = (size_t)(row & (Ss - 1)) * N + col;
                    v0 += p1[pr]; v1 += p1[pr + 1];
                }
                if (MODE == 2) { v0 = fmaxf(v0, 0.f); v1 = fmaxf(v1, 0.f); }
                if (MODE == 3) {
                    const size_t pr = (size_t)row * N + col;
                    float g0 = tanhf(fmaxf(v0, 0.f));
                    float g1 = tanhf(fmaxf(v1, 0.f));
                    v0 = g0 * p1[pr] + (1.f - g0) * p2[pr];
                    v1 = g1 * p1[pr + 1] + (1.f - g1) * p2[pr + 1];
                }
                if (MODE == 4) {
                    *(uint32_t*)((__half*)Csel + (size_t)row * N + col) =
                        pack_h2(v0 * oscale, v1 * oscale);
                } else {
                    float2 o2; o2.x = v0; o2.y = v1;
                    *(float2*)(Csel + (size_t)row * N + col) = o2;
                }
            }
        }
    }
}

// ---------------- FP16 flash attention, cp.async double-buffered K/V -------
// BANDED=0: full. BANDED=1: band |q-k|<=32.
// Q-tile 128, K-tile 64, HD=64. 8 warps x 16 q-rows, mma m16n8k16.
// smem halfs: Qs[128][72], Ps[128][72], Ks[2][64][72], Vs[2][64][72]
constexpr int SRF = 72;
constexpr int FQ_OFF = 0;
constexpr int FP_OFF = 128 * SRF;
constexpr int FK_OFF = 2 * 128 * SRF;
constexpr int FV_OFF = FK_OFF + 2 * 64 * SRF;
constexpr int FL_SMEM_HALFS = FV_OFF + 2 * 64 * SRF;
constexpr int FL_SMEM_BYTES = FL_SMEM_HALFS * 2;   // 73,728 B

template <int BANDED>
__global__ void __launch_bounds__(256) flash_tc_k(
    const __half* __restrict__ Q, const __half* __restrict__ K,
    const __half* __restrict__ V, float* __restrict__ O)
{
    extern __shared__ __half smh[];
    __half* Qs = smh + FQ_OFF;
    __half* Ps = smh + FP_OFF;
    __half* Ks = smh + FK_OFF;
    __half* Vs = smh + FV_OFF;

    const int qt = blockIdx.x, h = blockIdx.y, b = blockIdx.z;
    const int t  = threadIdx.x;
    const int lane = t & 31, w = t >> 5;
    const int gid = lane >> 2, tig = lane & 3;
    const int q0 = w * 16;

    // ldmatrix lane addresses (buf 0; buf 1 = +BUFO bytes)
    constexpr uint32_t BUFO  = 64 * SRF * 2;
    constexpr uint32_t ROW16 = 16 * SRF * 2;
    const uint32_t qA  = smem_u32(&Qs[(q0 + (lane & 15)) * SRF + (lane >> 4) * 8]);
    const uint32_t pA  = smem_u32(&Ps[(q0 + (lane & 15)) * SRF + (lane >> 4) * 8]);
    const uint32_t kA0 = smem_u32(&Ks[((lane & 7) + 8 * ((lane >> 3) & 1)) * SRF
                                      + (lane >> 4) * 8]);
    const uint32_t vA0 = smem_u32(&Vs[((lane & 7) + 8 * ((lane >> 3) & 1)) * SRF
                                      + (lane >> 4) * 8]);

    // cp.async loader geometry: row lr, 32 halfs starting at lc
    const int lr = t >> 2;
    const int lc = (t & 3) * 16;
    const uint32_t kDst0 = smem_u32(&Ks[lr * SRF + lc]);
    const uint32_t vDst0 = smem_u32(&Vs[lr * SRF + lc]);
    const size_t g_row_base = ((size_t)(b * Ss + lr)) * Dd + h * HD + lc;

    // ---- load Q tile (already fp16 + pre-scaled) ----
    {
        const int r  = t >> 1;
        const int c0 = (t & 1) * 32;
        const __half* src = Q + ((size_t)(b * Ss + qt * 128 + r)) * Dd + h * HD + c0;
#pragma unroll
        for (int i = 0; i < 4; i++)
            *(uint4*)&Qs[r * SRF + c0 + i * 8] = *(const uint4*)(src + i * 8);
    }

    float o_acc[8][4] = {};
    float m0 = -1e30f, m1 = -1e30f, l0 = 0.f, l1 = 0.f;

    const int rowA0 = (q0 + gid) * SRF;
    const int rowA1 = (q0 + gid + 8) * SRF;
    const int qr0 = qt * 128 + q0 + gid;
    const int qr1 = qr0 + 8;

    int k_begin = 0, k_end = Ss;
    if (BANDED) {
        k_begin = qt * 128 - 64; if (k_begin < 0) k_begin = 0;
        k_end   = qt * 128 + 192; if (k_end > Ss) k_end = Ss;
    }

    // ---- preload tile k_begin into buf 0 ----
    {
        const __half* ks = K + g_row_base + (size_t)k_begin * Dd;
        const __half* vs = V + g_row_base + (size_t)k_begin * Dd;
        cp_async16(kDst0,      ks);
        cp_async16(kDst0 + 16, ks + 8);
        cp_async16(vDst0,      vs);
        cp_async16(vDst0 + 16, vs + 8);
        cp_async_commit();
    }

    int buf = 0;
    for (int k0 = k_begin; k0 < k_end; k0 += 64) {
        __syncthreads();   // prior tile's reads of buf^1 are complete

        const bool has_next = (k0 + 64) < k_end;
        if (has_next) {
            const uint32_t off = (buf ^ 1) ? BUFO : 0u;
            const __half* ks = K + g_row_base + (size_t)(k0 + 64) * Dd;
            const __half* vs = V + g_row_base + (size_t)(k0 + 64) * Dd;
            cp_async16(kDst0 + off,      ks);
            cp_async16(kDst0 + off + 16, ks + 8);
            cp_async16(vDst0 + off,      vs);
            cp_async16(vDst0 + off + 16, vs + 8);
            cp_async_commit();
            cp_async_wait<1>();
        } else {
            cp_async_wait<0>();
        }
        __syncthreads();   // tile k0 data visible to all

        const uint32_t kA = kA0 + (buf ? BUFO : 0u);
        const uint32_t vA = vA0 + (buf ? BUFO : 0u);

        // ---- S = Q K^T ----
        float sreg[8][4] = {};
#pragma unroll
        for (int kk = 0; kk < 4; kk++) {
            uint32_t a[4];
            ldsm_x4(a, qA + (uint32_t)(kk * 32));
#pragma unroll
            for (int nt2 = 0; nt2 < 4; nt2++) {
                uint32_t kb[4];
                ldsm_x4(kb, kA + (uint32_t)(nt2 * ROW16 + kk * 32));
                mma_f16(sreg[2 * nt2],     a, kb[0], kb[2]);
                mma_f16(sreg[2 * nt2 + 1], a, kb[1], kb[3]);
            }
        }

        // ---- band mask ----
        if (BANDED) {
#pragma unroll
            for (int nt = 0; nt < 8; nt++) {
                const int kg = k0 + nt * 8 + 2 * tig;
                if (abs(qr0 - kg)       > 32) sreg[nt][0] = -1e30f;
                if (abs(qr0 - (kg + 1)) > 32) sreg[nt][1] = -1e30f;
                if (abs(qr1 - kg)       > 32) sreg[nt][2] = -1e30f;
                if (abs(qr1 - (kg + 1)) > 32) sreg[nt][3] = -1e30f;
            }
        }

        // ---- online softmax ----
        float mt0 = -1e30f, mt1 = -1e30f;
#pragma unroll
        for (int nt = 0; nt < 8; nt++) {
            mt0 = fmaxf(mt0, fmaxf(sreg[nt][0], sreg[nt][1]));
            mt1 = fmaxf(mt1, fmaxf(sreg[nt][2], sreg[nt][3]));
        }
        mt0 = fmaxf(mt0, __shfl_xor_sync(0xffffffffu, mt0, 1));
        mt0 = fmaxf(mt0, __shfl_xor_sync(0xffffffffu, mt0, 2));
        mt1 = fmaxf(mt1, __shfl_xor_sync(0xffffffffu, mt1, 1));
        mt1 = fmaxf(mt1, __shfl_xor_sync(0xffffffffu, mt1, 2));

        const float mn0 = fmaxf(m0, mt0), mn1 = fmaxf(m1, mt1);
        const float al0 = __expf(m0 - mn0), al1 = __expf(m1 - mn1);
        m0 = mn0; m1 = mn1;

        float ls0 = 0.f, ls1 = 0.f;
#pragma unroll
        for (int nt = 0; nt < 8; nt++) {
            float p00, p01, p10, p11;
            if (BANDED) {
                p00 = (sreg[nt][0] > -1e29f) ? __expf(sreg[nt][0] - mn0) : 0.f;
                p01 = (sreg[nt][1] > -1e29f) ? __expf(sreg[nt][1] - mn0) : 0.f;
                p10 = (sreg[nt][2] > -1e29f) ? __expf(sreg[nt][2] - mn1) : 0.f;
                p11 = (sreg[nt][3] > -1e29f) ? __expf(sreg[nt][3] - mn1) : 0.f;
            } else {
                p00 = __expf(sreg[nt][0] - mn0);
                p01 = __expf(sreg[nt][1] - mn0);
                p10 = __expf(sreg[nt][2] - mn1);
                p11 = __expf(sreg[nt][3] - mn1);
            }
            ls0 += p00 + p01;
            ls1 += p10 + p11;
            *(uint32_t*)&Ps[rowA0 + nt * 8 + 2 * tig] = pack_h2(p00, p01);
            *(uint32_t*)&Ps[rowA1 + nt * 8 + 2 * tig] = pack_h2(p10, p11);
        }
        ls0 += __shfl_xor_sync(0xffffffffu, ls0, 1);
        ls0 += __shfl_xor_sync(0xffffffffu, ls0, 2);
        ls1 += __shfl_xor_sync(0xffffffffu, ls1, 1);
        ls1 += __shfl_xor_sync(0xffffffffu, ls1, 2);
        l0 = l0 * al0 + ls0;
        l1 = l1 * al1 + ls1;
#pragma unroll
        for (int nt = 0; nt < 8; nt++) {
            o_acc[nt][0] *= al0; o_acc[nt][1] *= al0;
            o_acc[nt][2] *= al1; o_acc[nt][3] *= al1;
        }
        __syncwarp();   // Ps rows q0..q0+15 are warp-local

        // ---- O += P V ----
#pragma unroll
        for (int kk = 0; kk < 4; kk++) {
            uint32_t a[4];
            ldsm_x4(a, pA + (uint32_t)(kk * 32));
#pragma unroll
            for (int nt2 = 0; nt2 < 4; nt2++) {
                uint32_t vb[4];
                ldsm_x4_t(vb, vA + (uint32_t)(kk * ROW16 + nt2 * 32));
                mma_f16(o_acc[2 * nt2],     a, vb[0], vb[1]);
                mma_f16(o_acc[2 * nt2 + 1], a, vb[2], vb[3]);
            }
        }
        buf ^= 1;
    }

    // ---- epilogue ----
    const float inv0 = 1.f / l0, inv1 = 1.f / l1;
    float* orow0 = O + ((size_t)(b * Ss + qt * 128 + q0 + gid)) * Dd + h * HD;
    float* orow1 = O + ((size_t)(b * Ss + qt * 128 + q0 + gid + 8)) * Dd + h * HD;
#pragma unroll
    for (int nt = 0; nt < 8; nt++) {
        float2 w0; w0.x = o_acc[nt][0] * inv0; w0.y = o_acc[nt][1] * inv0;
        float2 w1; w1.x = o_acc[nt][2] * inv1; w1.y = o_acc[nt][3] * inv1;
        *(float2*)(orow0 + nt * 8 + 2 * tig) = w0;
        *(float2*)(orow1 + nt * 8 + 2 * tig) = w1;
    }
}

// ---------------- LayerNorm kernels ----------------
__global__ void __launch_bounds__(128) ln_add_k(
    const float* __restrict__ A, const float* __restrict__ R,
    const float* __restrict__ g, const float* __restrict__ be,
    float* __restrict__ O)
{
    const int row = blockIdx.x, t = threadIdx.x;
    const size_t base = (size_t)row * Dd + t * 4;
    float4 a = *(const float4*)(A + base);
    float4 r = *(const float4*)(R + base);
    float x[4] = {a.x + r.x, a.y + r.y, a.z + r.z, a.w + r.w};

    float s = x[0] + x[1] + x[2] + x[3];
    float ss = x[0]*x[0] + x[1]*x[1] + x[2]*x[2] + x[3]*x[3];
    __shared__ float sh1[4], sh2[4];
#pragma unroll
    for (int o = 16; o; o >>= 1) {
        s  += __shfl_xor_sync(0xffffffffu, s, o);
        ss += __shfl_xor_sync(0xffffffffu, ss, o);
    }
    if (!(t & 31)) { sh1[t >> 5] = s; sh2[t >> 5] = ss; }
    __syncthreads();
    s  = sh1[0] + sh1[1] + sh1[2] + sh1[3];
    ss = sh2[0] + sh2[1] + sh2[2] + sh2[3];

    const float mean = s * (1.f / Dd);
    const float var = ss * (1.f / Dd) - mean * mean;
    const float rs = rsqrtf(var + 1e-5f);
    float4 gg = *(const float4*)(g + t * 4);
    float4 bb = *(const float4*)(be + t * 4);
    float4 o4;
    o4.x = (x[0] - mean) * rs * gg.x + bb.x;
    o4.y = (x[1] - mean) * rs * gg.y + bb.y;
    o4.z = (x[2] - mean) * rs * gg.z + bb.z;
    o4.w = (x[3] - mean) * rs * gg.w + bb.w;
    *(float4*)(O + base) = o4;
}

__global__ void __launch_bounds__(128) ln_add_ln_k(
    const float* __restrict__ A, const float* __restrict__ R,
    const float* __restrict__ g2, const float* __restrict__ b2,
    const float* __restrict__ g3, const float* __restrict__ b3,
    float* __restrict__ O)
{
    const int row = blockIdx.x, t = threadIdx.x;
    const size_t base = (size_t)row * Dd + t * 4;
    float4 a = *(const float4*)(A + base);
    float4 r = *(const float4*)(R + base);
    float x[4] = {a.x + r.x, a.y + r.y, a.z + r.z, a.w + r.w};

    __shared__ float sh1[4], sh2[4];
    float s = x[0] + x[1] + x[2] + x[3];
    float ss = x[0]*x[0] + x[1]*x[1] + x[2]*x[2] + x[3]*x[3];
#pragma unroll
    for (int o = 16; o; o >>= 1) {
        s  += __shfl_xor_sync(0xffffffffu, s, o);
        ss += __shfl_xor_sync(0xffffffffu, ss, o);
    }
    if (!(t & 31)) { sh1[t >> 5] = s; sh2[t >> 5] = ss; }
    __syncthreads();
    s  = sh1[0] + sh1[1] + sh1[2] + sh1[3];
    ss = sh2[0] + sh2[1] + sh2[2] + sh2[3];
    float mean = s * (1.f / Dd);
    float var = ss * (1.f / Dd) - mean * mean;
    float rs = rsqrtf(var + 1e-5f);

    float4 gg = *(const float4*)(g2 + t * 4);
    float4 bb = *(const float4*)(b2 + t * 4);
    float y[4];
    y[0] = (x[0] - mean) * rs * gg.x + bb.x;
    y[1] = (x[1] - mean) * rs * gg.y + bb.y;
    y[2] = (x[2] - mean) * rs * gg.z + bb.z;
    y[3] = (x[3] - mean) * rs * gg.w + bb.w;

    __syncthreads();
    s  = y[0] + y[1] + y[2] + y[3];
    ss = y[0]*y[0] + y[1]*y[1] + y[2]*y[2] + y[3]*y[3];
#pragma unroll
    for (int o = 16; o; o >>= 1) {
        s  += __shfl_xor_sync(0xffffffffu, s, o);
        ss += __shfl_xor_sync(0xffffffffu, ss, o);
    }
    if (!(t & 31)) { sh1[t >> 5] = s; sh2[t >> 5] = ss; }
    __syncthreads();
    s  = sh1[0] + sh1[1] + sh1[2] + sh1[3];
    ss = sh2[0] + sh2[1] + sh2[2] + sh2[3];
    mean = s * (1.f / Dd);
    var = ss * (1.f / Dd) - mean * mean;
    rs = rsqrtf(var + 1e-5f);

    float4 g3v = *(const float4*)(g3 + t * 4);
    float4 b3v = *(const float4*)(b3 + t * 4);
    float4 o4;
    o4.x = (y[0] - mean) * rs * g3v.x + b3v.x;
    o4.y = (y[1] - mean) * rs * g3v.y + b3v.y;
    o4.z = (y[2] - mean) * rs * g3v.z + b3v.z;
    o4.w = (y[3] - mean) * rs * g3v.w + b3v.w;
    *(float4*)(O + base) = o4;
}

// ---------------- mean pool over S (deterministic 2-stage) ----------------
__global__ void __launch_bounds__(128) colmean_part_k(const float* __restrict__ X,
                                                      float* __restrict__ PP)
{
    const int b = blockIdx.x >> 2;
    const int d = (blockIdx.x & 3) * 128 + threadIdx.x;
    const int sc = blockIdx.y;
    float s = 0.f;
    for (int j = sc * 128; j < sc * 128 + 128; j++)
        s += X[((size_t)(b * Ss + j)) * Dd + d];
    PP[((size_t)sc * Bb + b) * Dd + d] = s;
}

__global__ void __launch_bounds__(128) colmean_fin_k(const float* __restrict__ PP,
                                                     float* __restrict__ P)
{
    const int idx = blockIdx.x * 128 + threadIdx.x;
    const int b = idx / Dd, d = idx % Dd;
    float s = 0.f;
#pragma unroll
    for (int c = 0; c < 16; c++) s += PP[((size_t)c * Bb + b) * Dd + d];
    P[idx] = s * (1.f / Ss);
}

// ---------------- final tiny GEMM ----------------
__global__ void __launch_bounds__(128) final_k(const float* __restrict__ P,
                                               const float* __restrict__ Wt,
                                               const float* __restrict__ bias,
                                               float* __restrict__ out)
{
    const int b = blockIdx.x, o = threadIdx.x;
    float s = bias[o];
    for (int d = 0; d < Dd; d++) s += P[b * Dd + d] * Wt[d * DOUT + o];
    out[b * DOUT + o] = s;
}

// ---------------- launch ----------------
extern "C" void kernel_launch(void* const* d_in, const int* in_sizes, int n_in,
                              void* d_out, int out_size)
{
    const float* x      = (const float*)d_in[0];
    const float* pos    = (const float*)d_in[1];
    const float* win_w  = (const float*)d_in[2];
    const float* win_b  = (const float*)d_in[3];
    const float* l_wqkv = (const float*)d_in[4];
    const float* l_bqkv = (const float*)d_in[5];
    const float* l_wo   = (const float*)d_in[6];
    const float* l_bo   = (const float*)d_in[7];
    const float* g_wqkv = (const float*)d_in[8];
    const float* g_bqkv = (const float*)d_in[9];
    const float* g_wo   = (const float*)d_in[10];
    const float* g_bo   = (const float*)d_in[11];
    const float* gate_w = (const float*)d_in[12];
    const float* gate_b = (const float*)d_in[13];
    const float* ffn_w1 = (const float*)d_in[14];
    const float* ffn_b1 = (const float*)d_in[15];
    const float* ffn_w2 = (const float*)d_in[16];
    const float* ffn_b2 = (const float*)d_in[17];
    const float* n1_g   = (const float*)d_in[18];
    const float* n1_b   = (const float*)d_in[19];
    const float* n2_g   = (const float*)d_in[20];
    const float* n2_b   = (const float*)d_in[21];
    const float* n3_g   = (const float*)d_in[22];
    const float* n3_b   = (const float*)d_in[23];
    const float* out_w  = (const float*)d_in[24];
    const float* out_b  = (const float*)d_in[25];

    float* sp = nullptr;
    cudaGetSymbolAddress((void**)&sp, g_scratch);
    float* bH   = sp + O_H;
    float* bQKV = sp + O_QL;    // 6 fp16 slices, each NBD-float slot
    float* bAOL = sp + O_AOL;
    float* bAOG = sp + O_AOG;
    float* bLOC = sp + O_LOC;
    float* bGLO = sp + O_GLO;
    float* bFUS = sp + O_FUS;
    float* bH1  = sp + O_H1;
    float* bFFN = sp + O_FFN;
    float* bH3  = sp + O_H3;
    float* bT1  = sp + O_T1;
    float* bPP  = sp + O_PP;
    float* bP   = sp + O_P;

    const __half* hQL = (const __half*)(sp + O_QL);
    const __half* hKL = (const __half*)(sp + O_KL);
    const __half* hVL = (const __half*)(sp + O_VL);
    const __half* hQG = (const __half*)(sp + O_QG);
    const __half* hKG = (const __half*)(sp + O_KG);
    const __half* hVG = (const __half*)(sp + O_VG);

    static bool attr_set = false;
    if (!attr_set) {
        cudaFuncSetAttribute(flash_tc_k<0>, cudaFuncAttributeMaxDynamicSharedMemorySize,
                             FL_SMEM_BYTES);
        cudaFuncSetAttribute(flash_tc_k<1>, cudaFuncAttributeMaxDynamicSharedMemorySize,
                             FL_SMEM_BYTES);
        attr_set = true;
    }

    const dim3 blk(256);

    // 1. h = x @ win_w + win_b + pos
    gemm_tc_k<1><<<dim3(4, 64), blk>>>(x, nullptr, DIN, 0, win_w, win_b, pos,
                                       nullptr, bH, BS, Dd, DIN);

    // 2. merged 6-slice QKV -> fp16 buffers (Q slices pre-scaled)
    gemm_tc_k<4><<<dim3(24, 64), blk>>>(bH, g_bqkv, Dd, 0, l_wqkv, l_bqkv,
                                        g_wqkv, nullptr, bQKV, BS, Dd, Dd);

    // 3. local banded flash attention
    flash_tc_k<1><<<dim3(Ss / 128, Hh, Bb), 256, FL_SMEM_BYTES>>>(hQL, hKL, hVL, bAOL);

    // 4. global flash attention
    flash_tc_k<0><<<dim3(Ss / 128, Hh, Bb), 256, FL_SMEM_BYTES>>>(hQG, hKG, hVG, bAOG);

    // 5. merged 2-slice output projections -> bLOC, bGLO
    gemm_tc_k<5><<<dim3(8, 64), blk>>>(bAOL, bAOG, Dd, 0, l_wo, l_bo,
                                       g_wo, g_bo, bLOC, BS, Dd, Dd);

    // 6. gate GEMM fused with blend
    gemm_tc_k<3><<<dim3(4, 64), blk>>>(bLOC, bGLO, Dd, Dd, gate_w, gate_b,
                                       bLOC, bGLO, bFUS, BS, Dd, 2 * Dd);

    // 7. h1 = LN(h + fused)
    ln_add_k<<<BS, 128>>>(bH, bFUS, n1_g, n1_b, bH1);

    // 8. FFN
    gemm_tc_k<2><<<dim3(8, 64), blk>>>(bH1, nullptr, Dd, 0, ffn_w1, ffn_b1,
                                       nullptr, nullptr, bT1, BS, 2 * Dd, Dd);
    gemm_tc_k<0><<<dim3(4, 64), blk>>>(bT1, nullptr, 2 * Dd, 0, ffn_w2, ffn_b2,
                                       nullptr, nullptr, bFFN, BS, Dd, 2 * Dd);

    // 9. h3 = LN(LN(h1 + ffn))
    ln_add_ln_k<<<BS, 128>>>(bH1, bFFN, n2_g, n2_b, n3_g, n3_b, bH3);

    // 10. mean-pool over S, then final projection
    colmean_part_k<<<dim3(Bb * 4, 16), 128>>>(bH3, bPP);
    colmean_fin_k<<<(Bb * Dd) / 128, 128>>>(bPP, bP);
    final_k<<<Bb, DOUT>>>(bP, out_w, out_b, (float*)d_out);

    (void)in_sizes; (void)n_in; (void)out_size;
}

// round 10
// speedup vs baseline: 1.8805x; 1.0929x over previous
#include <cuda_runtime.h>
#include <cuda_fp16.h>
#include <math.h>
#include <stdint.h>

// ---------------- problem constants (hardcoded) ----------------
constexpr int   Bb   = 4;
constexpr int   Ss   = 2048;
constexpr int   DIN  = 256;
constexpr int   Dd   = 512;
constexpr int   Hh   = 8;
constexpr int   DOUT = 128;
constexpr int   HD   = 64;       // Dd / Hh
constexpr int   BS   = Bb * Ss;  // 8192 rows
constexpr float SCALE = 0.125f;  // 1/sqrt(64)

// ---------------- scratch (static device memory; no allocs) ----------------
constexpr size_t NBD  = (size_t)BS * Dd;
constexpr size_t O_H   = 0;          // fp32
constexpr size_t O_QL  = 1 * NBD;    // fp16 QKV slices (slot stride NBD floats)
constexpr size_t O_KL  = 2 * NBD;
constexpr size_t O_VL  = 3 * NBD;
constexpr size_t O_QG  = 4 * NBD;
constexpr size_t O_KG  = 5 * NBD;
constexpr size_t O_VG  = 6 * NBD;
constexpr size_t O_AOL = 7 * NBD;    // fp16
constexpr size_t O_AOG = 8 * NBD;    // fp16
constexpr size_t O_LOC = 9 * NBD;    // fp32
constexpr size_t O_GLO = 10 * NBD;   // fp32
constexpr size_t O_FUS = 11 * NBD;   // fp32
constexpr size_t O_H1  = 12 * NBD;   // fp32
constexpr size_t O_FFN = 13 * NBD;   // fp32
constexpr size_t O_H3  = 14 * NBD;   // fp32
constexpr size_t O_T1H = 15 * NBD;   // fp16, 2*NBD halfs
constexpr size_t O_HH  = 16 * NBD;   // bHh (NBD/2 fl) + bH1h (NBD/2 fl)
constexpr size_t O_LGH = 17 * NBD;   // LOCh (NBD/2 fl) + GLOh (NBD/2 fl)
constexpr size_t O_WH  = 18 * NBD;   // fp16 weights + x pool (<1 NBD)
constexpr size_t O_PP  = 19 * NBD;
constexpr size_t O_P   = 19 * NBD + (size_t)16 * Bb * Dd;
constexpr size_t SCRATCH_FLOATS = O_P + (size_t)Bb * Dd;

__device__ float g_scratch[SCRATCH_FLOATS];

// ---------------- helpers ----------------
__device__ __forceinline__ uint32_t pack_h2(float x, float y) {
    __half2 h = __floats2half2_rn(x, y);
    return *(uint32_t*)&h;
}

__device__ __forceinline__ void mma_f16(float c[4], const uint32_t a[4],
                                        uint32_t b0, uint32_t b1) {
    asm volatile(
        "mma.sync.aligned.m16n8k16.row.col.f32.f16.f16.f32 "
        "{%0,%1,%2,%3},{%4,%5,%6,%7},{%8,%9},{%0,%1,%2,%3};\n"
        : "+f"(c[0]), "+f"(c[1]), "+f"(c[2]), "+f"(c[3])
        : "r"(a[0]), "r"(a[1]), "r"(a[2]), "r"(a[3]), "r"(b0), "r"(b1));
}

__device__ __forceinline__ void ldsm_x4(uint32_t r[4], uint32_t saddr) {
    asm volatile("ldmatrix.sync.aligned.m8n8.x4.shared.b16 {%0,%1,%2,%3}, [%4];"
                 : "=r"(r[0]), "=r"(r[1]), "=r"(r[2]), "=r"(r[3]) : "r"(saddr));
}

__device__ __forceinline__ void ldsm_x4_t(uint32_t r[4], uint32_t saddr) {
    asm volatile("ldmatrix.sync.aligned.m8n8.x4.trans.shared.b16 {%0,%1,%2,%3}, [%4];"
                 : "=r"(r[0]), "=r"(r[1]), "=r"(r[2]), "=r"(r[3]) : "r"(saddr));
}

__device__ __forceinline__ uint32_t smem_u32(const void* p) {
    uint32_t a;
    asm("{ .reg .u64 t; cvta.to.shared.u64 t, %1; cvt.u32.u64 %0, t; }"
        : "=r"(a) : "l"(p));
    return a;
}

__device__ __forceinline__ void cp_async16(uint32_t dst, const void* src) {
    asm volatile("cp.async.cg.shared.global [%0], [%1], 16;"
                 :: "r"(dst), "l"(src));
}
__device__ __forceinline__ void cp_async_commit() {
    asm volatile("cp.async.commit_group;");
}
template <int N>
__device__ __forceinline__ void cp_async_wait() {
    asm volatile("cp.async.wait_group %0;" :: "n"(N));
}

// ---------------- fp32 -> fp16 convert ----------------
__global__ void __launch_bounds__(256) f2h_k(const float* __restrict__ s,
                                             __half* __restrict__ d, int n)
{
    const int i = (blockIdx.x * 256 + threadIdx.x) * 8;
    if (i >= n) return;
    float4 a = *(const float4*)(s + i);
    float4 b = *(const float4*)(s + i + 4);
    uint4 o;
    o.x = pack_h2(a.x, a.y); o.y = pack_h2(a.z, a.w);
    o.z = pack_h2(b.x, b.y); o.w = pack_h2(b.z, b.w);
    *(uint4*)(d + i) = o;
}

// ---------------- FP16 GEMM, cp.async pipelined, fused epilogues -----------
// MODE 0: C=fp32 +bias
// MODE 1: C=fp32 +bias+pos(p1); Ch=fp16 copy
// MODE 2: Ch=fp16 relu(+bias)
// MODE 3: A=concat(A,A2) on K; g=tanh(relu(acc+bias)); C=g*p1+(1-g)*p2 fp32
// MODE 4: 6-slice QKV -> Ch fp16 (Q slices x SCALE), slice stride chStride
// MODE 5: 2-slice Wo -> C fp32 (+isl*NBD) and Ch fp16 (+isl*chStride)
constexpr int SRA = 24;
constexpr int SRB = 136;

template <int MODE>
__global__ void __launch_bounds__(256) gemm_tc_k(
    const __half* __restrict__ A, const __half* __restrict__ A2, int lda, int KA,
    const __half* __restrict__ W, const __half* __restrict__ W2,
    const float* __restrict__ bias, const float* __restrict__ bias2,
    const float* __restrict__ p1, const float* __restrict__ p2,
    float* __restrict__ C, __half* __restrict__ Ch, long chStride,
    int N, int K)
{
    __shared__ __half As[2][128][SRA];
    __shared__ __half Bs[2][16][SRB];

    const int t  = threadIdx.x;
    const int m0 = blockIdx.y * 128;

    const __half* Asel = A;
    const __half* Wsel = W;
    const float* bsel = bias;
    float* Csel = C;
    __half* Chsel = Ch;
    float oscale = 1.f;
    int n0;
    if (MODE == 4 || MODE == 5) {
        const int isl = blockIdx.x >> 2;
        n0 = (blockIdx.x & 3) * 128;
        if (MODE == 4) {
            Wsel = (isl < 3) ? W + (size_t)isl * Dd * Dd
                             : W2 + (size_t)(isl - 3) * Dd * Dd;
            bsel = (isl < 3) ? bias + isl * Dd : bias2 + (isl - 3) * Dd;
            if (isl == 0 || isl == 3) oscale = SCALE;
        } else {
            Asel = isl ? A2 : A;
            Wsel = isl ? W2 : W;
            bsel = isl ? bias2 : bias;
            Csel = C + (size_t)isl * NBD;
        }
        Chsel = Ch + (size_t)isl * chStride;
    } else {
        n0 = blockIdx.x * 128;
    }

    const int lane = t & 31, w = t >> 5;
    const int wm = w & 1, wn = w >> 1;
    const int gid = lane >> 2, tig = lane & 3;
    const int mw = wm * 64, nw = wn * 32;

    const int amr = t >> 1;          // A loader: m row
    const int akc = (t & 1) * 8;     // A loader: k col 0/8
    const int bkr = t >> 4;          // B loader: k row
    const int bnc = (t & 15) * 8;    // B loader: n col

    constexpr uint32_t ABUF = 128 * SRA * 2;
    constexpr uint32_t BBUF = 16 * SRB * 2;
    const uint32_t aDst = smem_u32(&As[0][amr][akc]);
    const uint32_t bDst = smem_u32(&Bs[0][bkr][bnc]);

    const uint32_t aAddr0 = smem_u32(&As[0][mw + (lane & 15)][(lane >> 4) * 8]);
    const uint32_t bAddr0 = smem_u32(&Bs[0][(lane & 7) + 8 * ((lane >> 3) & 1)]
                                        [nw + 8 * (lane >> 4)]);

    float acc[4][4][4] = {};

    // ---- preload tile 0 into buf 0 ----
    {
        const __half* Asrc = Asel;
        int kk0 = 0;
        if (MODE == 3 && 0 >= KA) { Asrc = A2; kk0 = -KA; }
        cp_async16(aDst, Asrc + (size_t)(m0 + amr) * lda + kk0 + akc);
        cp_async16(bDst, Wsel + (size_t)bkr * N + n0 + bnc);
        cp_async_commit();
    }

    int buf = 0;
    for (int k0 = 0; k0 < K; k0 += 16) {
        __syncthreads();   // prior compute done reading write-target buffer
        const int kn = k0 + 16;
        const bool has_next = kn < K;
        if (has_next) {
            const uint32_t boff = (buf ^ 1) ? 1u : 0u;
            const __half* Asrc = Asel;
            int kk0 = kn;
            if (MODE == 3 && kn >= KA) { Asrc = A2; kk0 = kn - KA; }
            cp_async16(aDst + boff * ABUF,
                       Asrc + (size_t)(m0 + amr) * lda + kk0 + akc);
            cp_async16(bDst + boff * BBUF,
                       Wsel + (size_t)(kn + bkr) * N + n0 + bnc);
            cp_async_commit();
            cp_async_wait<1>();
        } else {
            cp_async_wait<0>();
        }
        __syncthreads();   // tile k0 visible

        const uint32_t aA = aAddr0 + (buf ? ABUF : 0u);
        const uint32_t bA = bAddr0 + (buf ? BBUF : 0u);
        uint32_t af[4][4], bb[2][4];
#pragma unroll
        for (int mt = 0; mt < 4; mt++)
            ldsm_x4(af[mt], aA + (uint32_t)(mt * 16 * SRA * 2));
#pragma unroll
        for (int nb2 = 0; nb2 < 2; nb2++)
            ldsm_x4_t(bb[nb2], bA + (uint32_t)(nb2 * 32));
#pragma unroll
        for (int mt = 0; mt < 4; mt++) {
            mma_f16(acc[mt][0], af[mt], bb[0][0], bb[0][1]);
            mma_f16(acc[mt][1], af[mt], bb[0][2], bb[0][3]);
            mma_f16(acc[mt][2], af[mt], bb[1][0], bb[1][1]);
            mma_f16(acc[mt][3], af[mt], bb[1][2], bb[1][3]);
        }
        buf ^= 1;
    }

    // ---- epilogue ----
#pragma unroll
    for (int mt = 0; mt < 4; mt++) {
#pragma unroll
        for (int hf = 0; hf < 2; hf++) {
            const int row = m0 + mw + mt * 16 + gid + hf * 8;
#pragma unroll
            for (int nt = 0; nt < 4; nt++) {
                const int col = n0 + nw + nt * 8 + tig * 2;
                float v0 = acc[mt][nt][hf * 2 + 0] + bsel[col];
                float v1 = acc[mt][nt][hf * 2 + 1] + bsel[col + 1];
                if (MODE == 1) {
                    const size_t pr = (size_t)(row & (Ss - 1)) * N + col;
                    v0 += p1[pr]; v1 += p1[pr + 1];
                }
                if (MODE == 2) { v0 = fmaxf(v0, 0.f); v1 = fmaxf(v1, 0.f); }
                if (MODE == 3) {
                    const size_t pr = (size_t)row * N + col;
                    float g0 = tanhf(fmaxf(v0, 0.f));
                    float g1 = tanhf(fmaxf(v1, 0.f));
                    v0 = g0 * p1[pr] + (1.f - g0) * p2[pr];
                    v1 = g1 * p1[pr + 1] + (1.f - g1) * p2[pr + 1];
                }
                if (MODE == 0 || MODE == 1 || MODE == 3 || MODE == 5) {
                    float2 o2; o2.x = v0; o2.y = v1;
                    *(float2*)(Csel + (size_t)row * N + col) = o2;
                }
                if (MODE == 1 || MODE == 2 || MODE == 4 || MODE == 5) {
                    *(uint32_t*)(Chsel + (size_t)row * N + col) =
                        pack_h2(v0 * oscale, v1 * oscale);
                }
            }
        }
    }
}

// ---------------- FP16 flash attention, cp.async K/V, fp16 output ----------
constexpr int SRF = 72;
constexpr int FQ_OFF = 0;
constexpr int FP_OFF = 128 * SRF;
constexpr int FK_OFF = 2 * 128 * SRF;
constexpr int FV_OFF = FK_OFF + 2 * 64 * SRF;
constexpr int FL_SMEM_HALFS = FV_OFF + 2 * 64 * SRF;
constexpr int FL_SMEM_BYTES = FL_SMEM_HALFS * 2;   // 73,728 B

template <int BANDED>
__global__ void __launch_bounds__(256) flash_tc_k(
    const __half* __restrict__ Q, const __half* __restrict__ K,
    const __half* __restrict__ V, __half* __restrict__ O)
{
    extern __shared__ __half smh[];
    __half* Qs = smh + FQ_OFF;
    __half* Ps = smh + FP_OFF;
    __half* Ks = smh + FK_OFF;
    __half* Vs = smh + FV_OFF;

    const int qt = blockIdx.x, h = blockIdx.y, b = blockIdx.z;
    const int t  = threadIdx.x;
    const int lane = t & 31, w = t >> 5;
    const int gid = lane >> 2, tig = lane & 3;
    const int q0 = w * 16;

    constexpr uint32_t BUFO  = 64 * SRF * 2;
    constexpr uint32_t ROW16 = 16 * SRF * 2;
    const uint32_t qA  = smem_u32(&Qs[(q0 + (lane & 15)) * SRF + (lane >> 4) * 8]);
    const uint32_t pA  = smem_u32(&Ps[(q0 + (lane & 15)) * SRF + (lane >> 4) * 8]);
    const uint32_t kA0 = smem_u32(&Ks[((lane & 7) + 8 * ((lane >> 3) & 1)) * SRF
                                      + (lane >> 4) * 8]);
    const uint32_t vA0 = smem_u32(&Vs[((lane & 7) + 8 * ((lane >> 3) & 1)) * SRF
                                      + (lane >> 4) * 8]);

    const int lr = t >> 2;
    const int lc = (t & 3) * 16;
    const uint32_t kDst0 = smem_u32(&Ks[lr * SRF + lc]);
    const uint32_t vDst0 = smem_u32(&Vs[lr * SRF + lc]);
    const size_t g_row_base = ((size_t)(b * Ss + lr)) * Dd + h * HD + lc;

    // ---- load Q tile (fp16, pre-scaled) ----
    {
        const int r  = t >> 1;
        const int c0 = (t & 1) * 32;
        const __half* src = Q + ((size_t)(b * Ss + qt * 128 + r)) * Dd + h * HD + c0;
#pragma unroll
        for (int i = 0; i < 4; i++)
            *(uint4*)&Qs[r * SRF + c0 + i * 8] = *(const uint4*)(src + i * 8);
    }

    float o_acc[8][4] = {};
    float m0 = -1e30f, m1 = -1e30f, l0 = 0.f, l1 = 0.f;

    const int rowA0 = (q0 + gid) * SRF;
    const int rowA1 = (q0 + gid + 8) * SRF;
    const int qr0 = qt * 128 + q0 + gid;
    const int qr1 = qr0 + 8;

    int k_begin = 0, k_end = Ss;
    if (BANDED) {
        k_begin = qt * 128 - 64; if (k_begin < 0) k_begin = 0;
        k_end   = qt * 128 + 192; if (k_end > Ss) k_end = Ss;
    }

    {
        const __half* ks = K + g_row_base + (size_t)k_begin * Dd;
        const __half* vs = V + g_row_base + (size_t)k_begin * Dd;
        cp_async16(kDst0,      ks);
        cp_async16(kDst0 + 16, ks + 8);
        cp_async16(vDst0,      vs);
        cp_async16(vDst0 + 16, vs + 8);
        cp_async_commit();
    }

    int buf = 0;
    for (int k0 = k_begin; k0 < k_end; k0 += 64) {
        __syncthreads();

        const bool has_next = (k0 + 64) < k_end;
        if (has_next) {
            const uint32_t off = (buf ^ 1) ? BUFO : 0u;
            const __half* ks = K + g_row_base + (size_t)(k0 + 64) * Dd;
            const __half* vs = V + g_row_base + (size_t)(k0 + 64) * Dd;
            cp_async16(kDst0 + off,      ks);
            cp_async16(kDst0 + off + 16, ks + 8);
            cp_async16(vDst0 + off,      vs);
            cp_async16(vDst0 + off + 16, vs + 8);
            cp_async_commit();
            cp_async_wait<1>();
        } else {
            cp_async_wait<0>();
        }
        __syncthreads();

        const uint32_t kA = kA0 + (buf ? BUFO : 0u);
        const uint32_t vA = vA0 + (buf ? BUFO : 0u);

        // ---- S = Q K^T ----
        float sreg[8][4] = {};
#pragma unroll
        for (int kk = 0; kk < 4; kk++) {
            uint32_t a[4];
            ldsm_x4(a, qA + (uint32_t)(kk * 32));
#pragma unroll
            for (int nt2 = 0; nt2 < 4; nt2++) {
                uint32_t kb[4];
                ldsm_x4(kb, kA + (uint32_t)(nt2 * ROW16 + kk * 32));
                mma_f16(sreg[2 * nt2],     a, kb[0], kb[2]);
                mma_f16(sreg[2 * nt2 + 1], a, kb[1], kb[3]);
            }
        }

        if (BANDED) {
#pragma unroll
            for (int nt = 0; nt < 8; nt++) {
                const int kg = k0 + nt * 8 + 2 * tig;
                if (abs(qr0 - kg)       > 32) sreg[nt][0] = -1e30f;
                if (abs(qr0 - (kg + 1)) > 32) sreg[nt][1] = -1e30f;
                if (abs(qr1 - kg)       > 32) sreg[nt][2] = -1e30f;
                if (abs(qr1 - (kg + 1)) > 32) sreg[nt][3] = -1e30f;
            }
        }

        // ---- online softmax ----
        float mt0 = -1e30f, mt1 = -1e30f;
#pragma unroll
        for (int nt = 0; nt < 8; nt++) {
            mt0 = fmaxf(mt0, fmaxf(sreg[nt][0], sreg[nt][1]));
            mt1 = fmaxf(mt1, fmaxf(sreg[nt][2], sreg[nt][3]));
        }
        mt0 = fmaxf(mt0, __shfl_xor_sync(0xffffffffu, mt0, 1));
        mt0 = fmaxf(mt0, __shfl_xor_sync(0xffffffffu, mt0, 2));
        mt1 = fmaxf(mt1, __shfl_xor_sync(0xffffffffu, mt1, 1));
        mt1 = fmaxf(mt1, __shfl_xor_sync(0xffffffffu, mt1, 2));

        const float mn0 = fmaxf(m0, mt0), mn1 = fmaxf(m1, mt1);
        const float al0 = __expf(m0 - mn0), al1 = __expf(m1 - mn1);
        m0 = mn0; m1 = mn1;

        float ls0 = 0.f, ls1 = 0.f;
#pragma unroll
        for (int nt = 0; nt < 8; nt++) {
            float p00, p01, p10, p11;
            if (BANDED) {
                p00 = (sreg[nt][0] > -1e29f) ? __expf(sreg[nt][0] - mn0) : 0.f;
                p01 = (sreg[nt][1] > -1e29f) ? __expf(sreg[nt][1] - mn0) : 0.f;
                p10 = (sreg[nt][2] > -1e29f) ? __expf(sreg[nt][2] - mn1) : 0.f;
                p11 = (sreg[nt][3] > -1e29f) ? __expf(sreg[nt][3] - mn1) : 0.f;
            } else {
                p00 = __expf(sreg[nt][0] - mn0);
                p01 = __expf(sreg[nt][1] - mn0);
                p10 = __expf(sreg[nt][2] - mn1);
                p11 = __expf(sreg[nt][3] - mn1);
            }
            ls0 += p00 + p01;
            ls1 += p10 + p11;
            *(uint32_t*)&Ps[rowA0 + nt * 8 + 2 * tig] = pack_h2(p00, p01);
            *(uint32_t*)&Ps[rowA1 + nt * 8 + 2 * tig] = pack_h2(p10, p11);
        }
        ls0 += __shfl_xor_sync(0xffffffffu, ls0, 1);
        ls0 += __shfl_xor_sync(0xffffffffu, ls0, 2);
        ls1 += __shfl_xor_sync(0xffffffffu, ls1, 1);
        ls1 += __shfl_xor_sync(0xffffffffu, ls1, 2);
        l0 = l0 * al0 + ls0;
        l1 = l1 * al1 + ls1;
#pragma unroll
        for (int nt = 0; nt < 8; nt++) {
            o_acc[nt][0] *= al0; o_acc[nt][1] *= al0;
            o_acc[nt][2] *= al1; o_acc[nt][3] *= al1;
        }
        __syncwarp();

        // ---- O += P V ----
#pragma unroll
        for (int kk = 0; kk < 4; kk++) {
            uint32_t a[4];
            ldsm_x4(a, pA + (uint32_t)(kk * 32));
#pragma unroll
            for (int nt2 = 0; nt2 < 4; nt2++) {
                uint32_t vb[4];
                ldsm_x4_t(vb, vA + (uint32_t)(kk * ROW16 + nt2 * 32));
                mma_f16(o_acc[2 * nt2],     a, vb[0], vb[1]);
                mma_f16(o_acc[2 * nt2 + 1], a, vb[2], vb[3]);
            }
        }
        buf ^= 1;
    }

    // ---- epilogue: fp16 output ----
    const float inv0 = 1.f / l0, inv1 = 1.f / l1;
    __half* orow0 = O + ((size_t)(b * Ss + qt * 128 + q0 + gid)) * Dd + h * HD;
    __half* orow1 = O + ((size_t)(b * Ss + qt * 128 + q0 + gid + 8)) * Dd + h * HD;
#pragma unroll
    for (int nt = 0; nt < 8; nt++) {
        *(uint32_t*)(orow0 + nt * 8 + 2 * tig) =
            pack_h2(o_acc[nt][0] * inv0, o_acc[nt][1] * inv0);
        *(uint32_t*)(orow1 + nt * 8 + 2 * tig) =
            pack_h2(o_acc[nt][2] * inv1, o_acc[nt][3] * inv1);
    }
}

// ---------------- LayerNorm kernels ----------------
__global__ void __launch_bounds__(128) ln_add_k(
    const float* __restrict__ A, const float* __restrict__ R,
    const float* __restrict__ g, const float* __restrict__ be,
    float* __restrict__ O, __half* __restrict__ Oh)
{
    const int row = blockIdx.x, t = threadIdx.x;
    const size_t base = (size_t)row * Dd + t * 4;
    float4 a = *(const float4*)(A + base);
    float4 r = *(const float4*)(R + base);
    float x[4] = {a.x + r.x, a.y + r.y, a.z + r.z, a.w + r.w};

    float s = x[0] + x[1] + x[2] + x[3];
    float ss = x[0]*x[0] + x[1]*x[1] + x[2]*x[2] + x[3]*x[3];
    __shared__ float sh1[4], sh2[4];
#pragma unroll
    for (int o = 16; o; o >>= 1) {
        s  += __shfl_xor_sync(0xffffffffu, s, o);
        ss += __shfl_xor_sync(0xffffffffu, ss, o);
    }
    if (!(t & 31)) { sh1[t >> 5] = s; sh2[t >> 5] = ss; }
    __syncthreads();
    s  = sh1[0] + sh1[1] + sh1[2] + sh1[3];
    ss = sh2[0] + sh2[1] + sh2[2] + sh2[3];

    const float mean = s * (1.f / Dd);
    const float var = ss * (1.f / Dd) - mean * mean;
    const float rs = rsqrtf(var + 1e-5f);
    float4 gg = *(const float4*)(g + t * 4);
    float4 bb = *(const float4*)(be + t * 4);
    float4 o4;
    o4.x = (x[0] - mean) * rs * gg.x + bb.x;
    o4.y = (x[1] - mean) * rs * gg.y + bb.y;
    o4.z = (x[2] - mean) * rs * gg.z + bb.z;
    o4.w = (x[3] - mean) * rs * gg.w + bb.w;
    *(float4*)(O + base) = o4;
    uint2 hv;
    hv.x = pack_h2(o4.x, o4.y);
    hv.y = pack_h2(o4.z, o4.w);
    *(uint2*)(Oh + base) = hv;
}

__global__ void __launch_bounds__(128) ln_add_ln_k(
    const float* __restrict__ A, const float* __restrict__ R,
    const float* __restrict__ g2, const float* __restrict__ b2,
    const float* __restrict__ g3, const float* __restrict__ b3,
    float* __restrict__ O)
{
    const int row = blockIdx.x, t = threadIdx.x;
    const size_t base = (size_t)row * Dd + t * 4;
    float4 a = *(const float4*)(A + base);
    float4 r = *(const float4*)(R + base);
    float x[4] = {a.x + r.x, a.y + r.y, a.z + r.z, a.w + r.w};

    __shared__ float sh1[4], sh2[4];
    float s = x[0] + x[1] + x[2] + x[3];
    float ss = x[0]*x[0] + x[1]*x[1] + x[2]*x[2] + x[3]*x[3];
#pragma unroll
    for (int o = 16; o; o >>= 1) {
        s  += __shfl_xor_sync(0xffffffffu, s, o);
        ss += __shfl_xor_sync(0xffffffffu, ss, o);
    }
    if (!(t & 31)) { sh1[t >> 5] = s; sh2[t >> 5] = ss; }
    __syncthreads();
    s  = sh1[0] + sh1[1] + sh1[2] + sh1[3];
    ss = sh2[0] + sh2[1] + sh2[2] + sh2[3];
    float mean = s * (1.f / Dd);
    float var = ss * (1.f / Dd) - mean * mean;
    float rs = rsqrtf(var + 1e-5f);

    float4 gg = *(const float4*)(g2 + t * 4);
    float4 bb = *(const float4*)(b2 + t * 4);
    float y[4];
    y[0] = (x[0] - mean) * rs * gg.x + bb.x;
    y[1] = (x[1] - mean) * rs * gg.y + bb.y;
    y[2] = (x[2] - mean) * rs * gg.z + bb.z;
    y[3] = (x[3] - mean) * rs * gg.w + bb.w;

    __syncthreads();
    s  = y[0] + y[1] + y[2] + y[3];
    ss = y[0]*y[0] + y[1]*y[1] + y[2]*y[2] + y[3]*y[3];
#pragma unroll
    for (int o = 16; o; o >>= 1) {
        s  += __shfl_xor_sync(0xffffffffu, s, o);
        ss += __shfl_xor_sync(0xffffffffu, ss, o);
    }
    if (!(t & 31)) { sh1[t >> 5] = s; sh2[t >> 5] = ss; }
    __syncthreads();
    s  = sh1[0] + sh1[1] + sh1[2] + sh1[3];
    ss = sh2[0] + sh2[1] + sh2[2] + sh2[3];
    mean = s * (1.f / Dd);
    var = ss * (1.f / Dd) - mean * mean;
    rs = rsqrtf(var + 1e-5f);

    float4 g3v = *(const float4*)(g3 + t * 4);
    float4 b3v = *(const float4*)(b3 + t * 4);
    float4 o4;
    o4.x = (y[0] - mean) * rs * g3v.x + b3v.x;
    o4.y = (y[1] - mean) * rs * g3v.y + b3v.y;
    o4.z = (y[2] - mean) * rs * g3v.z + b3v.z;
    o4.w = (y[3] - mean) * rs * g3v.w + b3v.w;
    *(float4*)(O + base) = o4;
}

// ---------------- mean pool over S (deterministic 2-stage) ----------------
__global__ void __launch_bounds__(128) colmean_part_k(const float* __restrict__ X,
                                                      float* __restrict__ PP)
{
    const int b = blockIdx.x >> 2;
    const int d = (blockIdx.x & 3) * 128 + threadIdx.x;
    const int sc = blockIdx.y;
    float s = 0.f;
    for (int j = sc * 128; j < sc * 128 + 128; j++)
        s += X[((size_t)(b * Ss + j)) * Dd + d];
    PP[((size_t)sc * Bb + b) * Dd + d] = s;
}

__global__ void __launch_bounds__(128) colmean_fin_k(const float* __restrict__ PP,
                                                     float* __restrict__ P)
{
    const int idx = blockIdx.x * 128 + threadIdx.x;
    const int b = idx / Dd, d = idx % Dd;
    float s = 0.f;
#pragma unroll
    for (int c = 0; c < 16; c++) s += PP[((size_t)c * Bb + b) * Dd + d];
    P[idx] = s * (1.f / Ss);
}

// ---------------- final tiny GEMM ----------------
__global__ void __launch_bounds__(128) final_k(const float* __restrict__ P,
                                               const float* __restrict__ Wt,
                                               const float* __restrict__ bias,
                                               float* __restrict__ out)
{
    const int b = blockIdx.x, o = threadIdx.x;
    float s = bias[o];
    for (int d = 0; d < Dd; d++) s += P[b * Dd + d] * Wt[d * DOUT + o];
    out[b * DOUT + o] = s;
}

// ---------------- launch ----------------
extern "C" void kernel_launch(void* const* d_in, const int* in_sizes, int n_in,
                              void* d_out, int out_size)
{
    const float* x      = (const float*)d_in[0];
    const float* pos    = (const float*)d_in[1];
    const float* win_w  = (const float*)d_in[2];
    const float* win_b  = (const float*)d_in[3];
    const float* l_wqkv = (const float*)d_in[4];
    const float* l_bqkv = (const float*)d_in[5];
    const float* l_wo   = (const float*)d_in[6];
    const float* l_bo   = (const float*)d_in[7];
    const float* g_wqkv = (const float*)d_in[8];
    const float* g_bqkv = (const float*)d_in[9];
    const float* g_wo   = (const float*)d_in[10];
    const float* g_bo   = (const float*)d_in[11];
    const float* gate_w = (const float*)d_in[12];
    const float* gate_b = (const float*)d_in[13];
    const float* ffn_w1 = (const float*)d_in[14];
    const float* ffn_b1 = (const float*)d_in[15];
    const float* ffn_w2 = (const float*)d_in[16];
    const float* ffn_b2 = (const float*)d_in[17];
    const float* n1_g   = (const float*)d_in[18];
    const float* n1_b   = (const float*)d_in[19];
    const float* n2_g   = (const float*)d_in[20];
    const float* n2_b   = (const float*)d_in[21];
    const float* n3_g   = (const float*)d_in[22];
    const float* n3_b   = (const float*)d_in[23];
    const float* out_w  = (const float*)d_in[24];
    const float* out_b  = (const float*)d_in[25];

    float* sp = nullptr;
    cudaGetSymbolAddress((void**)&sp, g_scratch);
    float* bH   = sp + O_H;
    float* bLOC = sp + O_LOC;
    float* bGLO = sp + O_GLO;
    float* bFUS = sp + O_FUS;
    float* bH1  = sp + O_H1;
    float* bFFN = sp + O_FFN;
    float* bH3  = sp + O_H3;
    float* bPP  = sp + O_PP;
    float* bP   = sp + O_P;

    __half* hQKV = (__half*)(sp + O_QL);           // 6 slices, stride 2*NBD halfs
    const __half* hQL = (const __half*)(sp + O_QL);
    const __half* hKL = (const __half*)(sp + O_KL);
    const __half* hVL = (const __half*)(sp + O_VL);
    const __half* hQG = (const __half*)(sp + O_QG);
    const __half* hKG = (const __half*)(sp + O_KG);
    const __half* hVG = (const __half*)(sp + O_VG);
    __half* hAOL = (__half*)(sp + O_AOL);
    __half* hAOG = (__half*)(sp + O_AOG);
    __half* hT1  = (__half*)(sp + O_T1H);
    __half* bHh  = (__half*)(sp + O_HH);
    __half* bH1h = (__half*)(sp + O_HH + NBD / 2);
    __half* hLOCh = (__half*)(sp + O_LGH);          // GLOh = hLOCh + NBD halfs

    __half* pool = (__half*)(sp + O_WH);
    __half* hx    = pool;
    __half* hwin  = hx    + (size_t)BS * DIN;
    __half* hlq   = hwin  + (size_t)DIN * Dd;
    __half* hgq   = hlq   + (size_t)3 * Dd * Dd;
    __half* hlwo  = hgq   + (size_t)3 * Dd * Dd;
    __half* hgwo  = hlwo  + (size_t)Dd * Dd;
    __half* hgate = hgwo  + (size_t)Dd * Dd;
    __half* hf1   = hgate + (size_t)2 * Dd * Dd;
    __half* hf2   = hf1   + (size_t)2 * Dd * Dd;

    static bool attr_set = false;
    if (!attr_set) {
        cudaFuncSetAttribute(flash_tc_k<0>, cudaFuncAttributeMaxDynamicSharedMemorySize,
                             FL_SMEM_BYTES);
        cudaFuncSetAttribute(flash_tc_k<1>, cudaFuncAttributeMaxDynamicSharedMemorySize,
                             FL_SMEM_BYTES);
        attr_set = true;
    }

    const dim3 blk(256);
    auto cvt = [](const float* s, __half* d, int n) {
        f2h_k<<<(n / 8 + 255) / 256, 256>>>(s, d, n);
    };

    // 0. convert inputs + weights to fp16
    cvt(x, hx, BS * DIN);
    cvt(win_w, hwin, DIN * Dd);
    cvt(l_wqkv, hlq, 3 * Dd * Dd);
    cvt(g_wqkv, hgq, 3 * Dd * Dd);
    cvt(l_wo, hlwo, Dd * Dd);
    cvt(g_wo, hgwo, Dd * Dd);
    cvt(gate_w, hgate, 2 * Dd * Dd);
    cvt(ffn_w1, hf1, Dd * 2 * Dd);
    cvt(ffn_w2, hf2, 2 * Dd * Dd);

    // 1. h = x @ win_w + win_b + pos  (fp32 + fp16 copies)
    gemm_tc_k<1><<<dim3(4, 64), blk>>>(hx, nullptr, DIN, 0, hwin, nullptr,
                                       win_b, nullptr, pos, nullptr,
                                       bH, bHh, 0, Dd, DIN);

    // 2. merged 6-slice QKV -> fp16 (Q pre-scaled); slice stride 2*NBD halfs
    gemm_tc_k<4><<<dim3(24, 64), blk>>>(bHh, nullptr, Dd, 0, hlq, hgq,
                                        l_bqkv, g_bqkv, nullptr, nullptr,
                                        nullptr, hQKV, 2 * (long)NBD, Dd, Dd);

    // 3. local banded flash attention (fp16 out)
    flash_tc_k<1><<<dim3(Ss / 128, Hh, Bb), 256, FL_SMEM_BYTES>>>(hQL, hKL, hVL, hAOL);

    // 4. global flash attention (fp16 out)
    flash_tc_k<0><<<dim3(Ss / 128, Hh, Bb), 256, FL_SMEM_BYTES>>>(hQG, hKG, hVG, hAOG);

    // 5. merged 2-slice output projections -> LOC/GLO fp32 + fp16
    gemm_tc_k<5><<<dim3(8, 64), blk>>>(hAOL, hAOG, Dd, 0, hlwo, hgwo,
                                       l_bo, g_bo, nullptr, nullptr,
                                       bLOC, hLOCh, (long)NBD, Dd, Dd);

    // 6. gate GEMM fused with blend (A = LOCh || GLOh)
    gemm_tc_k<3><<<dim3(4, 64), blk>>>(hLOCh, hLOCh + NBD, Dd, Dd, hgate, nullptr,
                                       gate_b, nullptr, bLOC, bGLO,
                                       bFUS, nullptr, 0, Dd, 2 * Dd);

    // 7. h1 = LN(h + fused)  (fp32 + fp16)
    ln_add_k<<<BS, 128>>>(bH, bFUS, n1_g, n1_b, bH1, bH1h);

    // 8. FFN
    gemm_tc_k<2><<<dim3(8, 64), blk>>>(bH1h, nullptr, Dd, 0, hf1, nullptr,
                                       ffn_b1, nullptr, nullptr, nullptr,
                                       nullptr, hT1, 0, 2 * Dd, Dd);
    gemm_tc_k<0><<<dim3(4, 64), blk>>>(hT1, nullptr, 2 * Dd, 0, hf2, nullptr,
                                       ffn_b2, nullptr, nullptr, nullptr,
                                       bFFN, nullptr, 0, Dd, 2 * Dd);

    // 9. h3 = LN(LN(h1 + ffn))
    ln_add_ln_k<<<BS, 128>>>(bH1, bFFN, n2_g, n2_b, n3_g, n3_b, bH3);

    // 10. mean-pool over S, then final projection
    colmean_part_k<<<dim3(Bb * 4, 16), 128>>>(bH3, bPP);
    colmean_fin_k<<<(Bb * Dd) / 128, 128>>>(bPP, bP);
    final_k<<<Bb, DOUT>>>(bP, out_w, out_b, (float*)d_out);

    (void)in_sizes; (void)n_in; (void)out_size;
}

// round 11
// speedup vs baseline: 1.9922x; 1.0594x over previous
#include <cuda_runtime.h>
#include <cuda_fp16.h>
#include <math.h>
#include <stdint.h>

// ---------------- problem constants (hardcoded) ----------------
constexpr int   Bb   = 4;
constexpr int   Ss   = 2048;
constexpr int   DIN  = 256;
constexpr int   Dd   = 512;
constexpr int   Hh   = 8;
constexpr int   DOUT = 128;
constexpr int   HD   = 64;       // Dd / Hh
constexpr int   BS   = Bb * Ss;  // 8192 rows
constexpr float SCALE = 0.125f;  // 1/sqrt(64)
constexpr float LOG2E = 1.4426950408889634f;

// ---------------- scratch (static device memory; no allocs) ----------------
constexpr size_t NBD  = (size_t)BS * Dd;
constexpr size_t O_H   = 0;          // fp32
constexpr size_t O_QL  = 1 * NBD;    // fp16 QKV slices (slot stride NBD floats)
constexpr size_t O_KL  = 2 * NBD;
constexpr size_t O_VL  = 3 * NBD;
constexpr size_t O_QG  = 4 * NBD;
constexpr size_t O_KG  = 5 * NBD;
constexpr size_t O_VG  = 6 * NBD;
constexpr size_t O_AOL = 7 * NBD;    // fp16
constexpr size_t O_AOG = 8 * NBD;    // fp16
constexpr size_t O_LOC = 9 * NBD;    // fp32
constexpr size_t O_GLO = 10 * NBD;   // fp32
constexpr size_t O_FUS = 11 * NBD;   // fp32
constexpr size_t O_H1  = 12 * NBD;   // fp32
constexpr size_t O_FFN = 13 * NBD;   // fp32
constexpr size_t O_H3  = 14 * NBD;   // fp32
constexpr size_t O_T1H = 15 * NBD;   // fp16, 2*NBD halfs
constexpr size_t O_HH  = 16 * NBD;   // bHh + bH1h
constexpr size_t O_LGH = 17 * NBD;   // LOCh + GLOh
constexpr size_t O_WH  = 18 * NBD;   // fp16 weights + x pool
constexpr size_t O_PP  = 19 * NBD;
constexpr size_t O_P   = 19 * NBD + (size_t)16 * Bb * Dd;
constexpr size_t SCRATCH_FLOATS = O_P + (size_t)Bb * Dd;

__device__ float g_scratch[SCRATCH_FLOATS];

// ---------------- helpers ----------------
__device__ __forceinline__ uint32_t pack_h2(float x, float y) {
    __half2 h = __floats2half2_rn(x, y);
    return *(uint32_t*)&h;
}

__device__ __forceinline__ float ex2(float x) {
    float y;
    asm("ex2.approx.f32 %0, %1;" : "=f"(y) : "f"(x));
    return y;
}

__device__ __forceinline__ void mma_f16(float c[4], const uint32_t a[4],
                                        uint32_t b0, uint32_t b1) {
    asm volatile(
        "mma.sync.aligned.m16n8k16.row.col.f32.f16.f16.f32 "
        "{%0,%1,%2,%3},{%4,%5,%6,%7},{%8,%9},{%0,%1,%2,%3};\n"
        : "+f"(c[0]), "+f"(c[1]), "+f"(c[2]), "+f"(c[3])
        : "r"(a[0]), "r"(a[1]), "r"(a[2]), "r"(a[3]), "r"(b0), "r"(b1));
}

__device__ __forceinline__ void ldsm_x4(uint32_t r[4], uint32_t saddr) {
    asm volatile("ldmatrix.sync.aligned.m8n8.x4.shared.b16 {%0,%1,%2,%3}, [%4];"
                 : "=r"(r[0]), "=r"(r[1]), "=r"(r[2]), "=r"(r[3]) : "r"(saddr));
}

__device__ __forceinline__ void ldsm_x4_t(uint32_t r[4], uint32_t saddr) {
    asm volatile("ldmatrix.sync.aligned.m8n8.x4.trans.shared.b16 {%0,%1,%2,%3}, [%4];"
                 : "=r"(r[0]), "=r"(r[1]), "=r"(r[2]), "=r"(r[3]) : "r"(saddr));
}

__device__ __forceinline__ uint32_t smem_u32(const void* p) {
    uint32_t a;
    asm("{ .reg .u64 t; cvta.to.shared.u64 t, %1; cvt.u32.u64 %0, t; }"
        : "=r"(a) : "l"(p));
    return a;
}

__device__ __forceinline__ void cp_async16(uint32_t dst, const void* src) {
    asm volatile("cp.async.cg.shared.global [%0], [%1], 16;"
                 :: "r"(dst), "l"(src));
}
__device__ __forceinline__ void cp_async_commit() {
    asm volatile("cp.async.commit_group;");
}
template <int N>
__device__ __forceinline__ void cp_async_wait() {
    asm volatile("cp.async.wait_group %0;" :: "n"(N));
}

// ---------------- merged fp32 -> fp16 convert (9 jobs, one launch) ---------
struct CvtJob { const float* s; __half* d; int n; };
struct CvtJobs { CvtJob j[9]; };

__global__ void __launch_bounds__(256) f2h_all_k(CvtJobs jobs)
{
    const CvtJob jb = jobs.j[blockIdx.y];
    const int i = (blockIdx.x * 256 + threadIdx.x) * 8;
    if (i >= jb.n) return;
    float4 a = *(const float4*)(jb.s + i);
    float4 b = *(const float4*)(jb.s + i + 4);
    uint4 o;
    o.x = pack_h2(a.x, a.y); o.y = pack_h2(a.z, a.w);
    o.z = pack_h2(b.x, b.y); o.w = pack_h2(b.z, b.w);
    *(uint4*)(jb.d + i) = o;
}

// ---------------- FP16 GEMM, 3-stage cp.async, one sync/iter ---------------
// MODE 0: C=fp32 +bias
// MODE 1: C=fp32 +bias+pos(p1); Ch=fp16 copy
// MODE 2: Ch=fp16 relu(+bias)
// MODE 3: A=concat(A,A2) on K; g=tanh(relu(acc+bias)); C=g*p1+(1-g)*p2 fp32
// MODE 4: 6-slice QKV -> Ch fp16 (Q slices x SCALE*LOG2E)
// MODE 5: 2-slice Wo -> C fp32 and Ch fp16
constexpr int SRA = 24;
constexpr int SRB = 136;
constexpr int STG = 3;

template <int MODE>
__global__ void __launch_bounds__(256) gemm_tc_k(
    const __half* __restrict__ A, const __half* __restrict__ A2, int lda, int KA,
    const __half* __restrict__ W, const __half* __restrict__ W2,
    const float* __restrict__ bias, const float* __restrict__ bias2,
    const float* __restrict__ p1, const float* __restrict__ p2,
    float* __restrict__ C, __half* __restrict__ Ch, long chStride,
    int N, int K)
{
    __shared__ __half As[STG][128][SRA];
    __shared__ __half Bs[STG][16][SRB];

    const int t  = threadIdx.x;
    const int m0 = blockIdx.y * 128;

    const __half* Asel = A;
    const __half* Wsel = W;
    const float* bsel = bias;
    float* Csel = C;
    __half* Chsel = Ch;
    float oscale = 1.f;
    int n0;
    if (MODE == 4 || MODE == 5) {
        const int isl = blockIdx.x >> 2;
        n0 = (blockIdx.x & 3) * 128;
        if (MODE == 4) {
            Wsel = (isl < 3) ? W + (size_t)isl * Dd * Dd
                             : W2 + (size_t)(isl - 3) * Dd * Dd;
            bsel = (isl < 3) ? bias + isl * Dd : bias2 + (isl - 3) * Dd;
            if (isl == 0 || isl == 3) oscale = SCALE * LOG2E;
        } else {
            Asel = isl ? A2 : A;
            Wsel = isl ? W2 : W;
            bsel = isl ? bias2 : bias;
            Csel = C + (size_t)isl * NBD;
        }
        Chsel = Ch + (size_t)isl * chStride;
    } else {
        n0 = blockIdx.x * 128;
    }

    const int lane = t & 31, w = t >> 5;
    const int wm = w & 1, wn = w >> 1;
    const int gid = lane >> 2, tig = lane & 3;
    const int mw = wm * 64, nw = wn * 32;

    const int amr = t >> 1;
    const int akc = (t & 1) * 8;
    const int bkr = t >> 4;
    const int bnc = (t & 15) * 8;

    constexpr uint32_t ABUF = 128 * SRA * 2;
    constexpr uint32_t BBUF = 16 * SRB * 2;
    const uint32_t aDst = smem_u32(&As[0][amr][akc]);
    const uint32_t bDst = smem_u32(&Bs[0][bkr][bnc]);
    const uint32_t aAddr0 = smem_u32(&As[0][mw + (lane & 15)][(lane >> 4) * 8]);
    const uint32_t bAddr0 = smem_u32(&Bs[0][(lane & 7) + 8 * ((lane >> 3) & 1)]
                                        [nw + 8 * (lane >> 4)]);

    float acc[4][4][4] = {};

    const int nk = K / 16;
    auto load_tile = [&](int kt, int stg) {
        const __half* Asrc = Asel;
        int kk0 = kt * 16;
        if (MODE == 3 && kk0 >= KA) { Asrc = A2; kk0 -= KA; }
        cp_async16(aDst + (uint32_t)stg * ABUF,
                   Asrc + (size_t)(m0 + amr) * lda + kk0 + akc);
        cp_async16(bDst + (uint32_t)stg * BBUF,
                   Wsel + (size_t)(kt * 16 + bkr) * N + n0 + bnc);
        cp_async_commit();
    };

    load_tile(0, 0);
    load_tile(1, 1);

    for (int it = 0; it < nk; it++) {
        if (it == nk - 1) cp_async_wait<0>();
        else              cp_async_wait<1>();
        __syncthreads();

        if (it + 2 < nk) load_tile(it + 2, (it + 2) % STG);

        const int stg = it % STG;
        const uint32_t aA = aAddr0 + (uint32_t)stg * ABUF;
        const uint32_t bA = bAddr0 + (uint32_t)stg * BBUF;
        uint32_t af[4][4], bb[2][4];
#pragma unroll
        for (int mt = 0; mt < 4; mt++)
            ldsm_x4(af[mt], aA + (uint32_t)(mt * 16 * SRA * 2));
#pragma unroll
        for (int nb2 = 0; nb2 < 2; nb2++)
            ldsm_x4_t(bb[nb2], bA + (uint32_t)(nb2 * 32));
#pragma unroll
        for (int mt = 0; mt < 4; mt++) {
            mma_f16(acc[mt][0], af[mt], bb[0][0], bb[0][1]);
            mma_f16(acc[mt][1], af[mt], bb[0][2], bb[0][3]);
            mma_f16(acc[mt][2], af[mt], bb[1][0], bb[1][1]);
            mma_f16(acc[mt][3], af[mt], bb[1][2], bb[1][3]);
        }
    }

    // ---- epilogue ----
#pragma unroll
    for (int mt = 0; mt < 4; mt++) {
#pragma unroll
        for (int hf = 0; hf < 2; hf++) {
            const int row = m0 + mw + mt * 16 + gid + hf * 8;
#pragma unroll
            for (int nt = 0; nt < 4; nt++) {
                const int col = n0 + nw + nt * 8 + tig * 2;
                float v0 = acc[mt][nt][hf * 2 + 0] + bsel[col];
                float v1 = acc[mt][nt][hf * 2 + 1] + bsel[col + 1];
                if (MODE == 1) {
                    const size_t pr = (size_t)(row & (Ss - 1)) * N + col;
                    v0 += p1[pr]; v1 += p1[pr + 1];
                }
                if (MODE == 2) { v0 = fmaxf(v0, 0.f); v1 = fmaxf(v1, 0.f); }
                if (MODE == 3) {
                    const size_t pr = (size_t)row * N + col;
                    float g0 = tanhf(fmaxf(v0, 0.f));
                    float g1 = tanhf(fmaxf(v1, 0.f));
                    v0 = g0 * p1[pr] + (1.f - g0) * p2[pr];
                    v1 = g1 * p1[pr + 1] + (1.f - g1) * p2[pr + 1];
                }
                if (MODE == 0 || MODE == 1 || MODE == 3 || MODE == 5) {
                    float2 o2; o2.x = v0; o2.y = v1;
                    *(float2*)(Csel + (size_t)row * N + col) = o2;
                }
                if (MODE == 1 || MODE == 2 || MODE == 4 || MODE == 5) {
                    *(uint32_t*)(Chsel + (size_t)row * N + col) =
                        pack_h2(v0 * oscale, v1 * oscale);
                }
            }
        }
    }
}

// ---------------- merged FP16 flash attention (local band + global) --------
// grid z in [0, 2*Bb): z<Bb -> banded path (|q-k|<=32), else global.
// Scores arrive pre-scaled by 1/sqrt(HD)*log2(e); softmax uses ex2 (base-2).
constexpr int SRF = 72;
constexpr int FQ_OFF = 0;
constexpr int FP_OFF = 128 * SRF;
constexpr int FK_OFF = 2 * 128 * SRF;
constexpr int FV_OFF = FK_OFF + 2 * 64 * SRF;
constexpr int FL_SMEM_HALFS = FV_OFF + 2 * 64 * SRF;
constexpr int FL_SMEM_BYTES = FL_SMEM_HALFS * 2;   // 73,728 B

__global__ void __launch_bounds__(256) flash_tc_k(
    const __half* __restrict__ QL, const __half* __restrict__ KL,
    const __half* __restrict__ VL, __half* __restrict__ OL,
    const __half* __restrict__ QG, const __half* __restrict__ KG,
    const __half* __restrict__ VG, __half* __restrict__ OG)
{
    extern __shared__ __half smh[];
    __half* Qs = smh + FQ_OFF;
    __half* Ps = smh + FP_OFF;
    __half* Ks = smh + FK_OFF;
    __half* Vs = smh + FV_OFF;

    const int qt = blockIdx.x, h = blockIdx.y;
    const bool banded = blockIdx.z < (unsigned)Bb;
    const int b = blockIdx.z & (Bb - 1);
    const __half* Q = banded ? QL : QG;
    const __half* K = banded ? KL : KG;
    const __half* V = banded ? VL : VG;
    __half* O = banded ? OL : OG;

    const int t  = threadIdx.x;
    const int lane = t & 31, w = t >> 5;
    const int gid = lane >> 2, tig = lane & 3;
    const int q0 = w * 16;

    constexpr uint32_t BUFO  = 64 * SRF * 2;
    constexpr uint32_t ROW16 = 16 * SRF * 2;
    const uint32_t qA  = smem_u32(&Qs[(q0 + (lane & 15)) * SRF + (lane >> 4) * 8]);
    const uint32_t pA  = smem_u32(&Ps[(q0 + (lane & 15)) * SRF + (lane >> 4) * 8]);
    const uint32_t kA0 = smem_u32(&Ks[((lane & 7) + 8 * ((lane >> 3) & 1)) * SRF
                                      + (lane >> 4) * 8]);
    const uint32_t vA0 = smem_u32(&Vs[((lane & 7) + 8 * ((lane >> 3) & 1)) * SRF
                                      + (lane >> 4) * 8]);

    const int lr = t >> 2;
    const int lc = (t & 3) * 16;
    const uint32_t kDst0 = smem_u32(&Ks[lr * SRF + lc]);
    const uint32_t vDst0 = smem_u32(&Vs[lr * SRF + lc]);
    const size_t g_row_base = ((size_t)(b * Ss + lr)) * Dd + h * HD + lc;

    // ---- load Q tile (fp16, pre-scaled incl. log2e) ----
    {
        const int r  = t >> 1;
        const int c0 = (t & 1) * 32;
        const __half* src = Q + ((size_t)(b * Ss + qt * 128 + r)) * Dd + h * HD + c0;
#pragma unroll
        for (int i = 0; i < 4; i++)
            *(uint4*)&Qs[r * SRF + c0 + i * 8] = *(const uint4*)(src + i * 8);
    }

    float o_acc[8][4] = {};
    float m0 = -1e30f, m1 = -1e30f, l0 = 0.f, l1 = 0.f;

    const int rowA0 = (q0 + gid) * SRF;
    const int rowA1 = (q0 + gid + 8) * SRF;
    const int qr0 = qt * 128 + q0 + gid;
    const int qr1 = qr0 + 8;

    int k_begin = 0, k_end = Ss;
    if (banded) {
        k_begin = qt * 128 - 64; if (k_begin < 0) k_begin = 0;
        k_end   = qt * 128 + 192; if (k_end > Ss) k_end = Ss;
    }

    {
        const __half* ks = K + g_row_base + (size_t)k_begin * Dd;
        const __half* vs = V + g_row_base + (size_t)k_begin * Dd;
        cp_async16(kDst0,      ks);
        cp_async16(kDst0 + 16, ks + 8);
        cp_async16(vDst0,      vs);
        cp_async16(vDst0 + 16, vs + 8);
        cp_async_commit();
    }

    int buf = 0;
    for (int k0 = k_begin; k0 < k_end; k0 += 64) {
        __syncthreads();

        const bool has_next = (k0 + 64) < k_end;
        if (has_next) {
            const uint32_t off = (buf ^ 1) ? BUFO : 0u;
            const __half* ks = K + g_row_base + (size_t)(k0 + 64) * Dd;
            const __half* vs = V + g_row_base + (size_t)(k0 + 64) * Dd;
            cp_async16(kDst0 + off,      ks);
            cp_async16(kDst0 + off + 16, ks + 8);
            cp_async16(vDst0 + off,      vs);
            cp_async16(vDst0 + off + 16, vs + 8);
            cp_async_commit();
            cp_async_wait<1>();
        } else {
            cp_async_wait<0>();
        }
        __syncthreads();

        const uint32_t kA = kA0 + (buf ? BUFO : 0u);
        const uint32_t vA = vA0 + (buf ? BUFO : 0u);

        // ---- S = Q K^T (scores in log2 domain) ----
        float sreg[8][4] = {};
#pragma unroll
        for (int kk = 0; kk < 4; kk++) {
            uint32_t a[4];
            ldsm_x4(a, qA + (uint32_t)(kk * 32));
#pragma unroll
            for (int nt2 = 0; nt2 < 4; nt2++) {
                uint32_t kb[4];
                ldsm_x4(kb, kA + (uint32_t)(nt2 * ROW16 + kk * 32));
                mma_f16(sreg[2 * nt2],     a, kb[0], kb[2]);
                mma_f16(sreg[2 * nt2 + 1], a, kb[1], kb[3]);
            }
        }

        if (banded) {
#pragma unroll
            for (int nt = 0; nt < 8; nt++) {
                const int kg = k0 + nt * 8 + 2 * tig;
                if (abs(qr0 - kg)       > 32) sreg[nt][0] = -1e30f;
                if (abs(qr0 - (kg + 1)) > 32) sreg[nt][1] = -1e30f;
                if (abs(qr1 - kg)       > 32) sreg[nt][2] = -1e30f;
                if (abs(qr1 - (kg + 1)) > 32) sreg[nt][3] = -1e30f;
            }
        }

        // ---- online softmax (base-2) ----
        float mt0 = -1e30f, mt1 = -1e30f;
#pragma unroll
        for (int nt = 0; nt < 8; nt++) {
            mt0 = fmaxf(mt0, fmaxf(sreg[nt][0], sreg[nt][1]));
            mt1 = fmaxf(mt1, fmaxf(sreg[nt][2], sreg[nt][3]));
        }
        mt0 = fmaxf(mt0, __shfl_xor_sync(0xffffffffu, mt0, 1));
        mt0 = fmaxf(mt0, __shfl_xor_sync(0xffffffffu, mt0, 2));
        mt1 = fmaxf(mt1, __shfl_xor_sync(0xffffffffu, mt1, 1));
        mt1 = fmaxf(mt1, __shfl_xor_sync(0xffffffffu, mt1, 2));

        const float mn0 = fmaxf(m0, mt0), mn1 = fmaxf(m1, mt1);
        const float al0 = ex2(m0 - mn0), al1 = ex2(m1 - mn1);
        m0 = mn0; m1 = mn1;

        float ls0 = 0.f, ls1 = 0.f;
#pragma unroll
        for (int nt = 0; nt < 8; nt++) {
            float p00, p01, p10, p11;
            if (banded) {
                p00 = (sreg[nt][0] > -1e29f) ? ex2(sreg[nt][0] - mn0) : 0.f;
                p01 = (sreg[nt][1] > -1e29f) ? ex2(sreg[nt][1] - mn0) : 0.f;
                p10 = (sreg[nt][2] > -1e29f) ? ex2(sreg[nt][2] - mn1) : 0.f;
                p11 = (sreg[nt][3] > -1e29f) ? ex2(sreg[nt][3] - mn1) : 0.f;
            } else {
                p00 = ex2(sreg[nt][0] - mn0);
                p01 = ex2(sreg[nt][1] - mn0);
                p10 = ex2(sreg[nt][2] - mn1);
                p11 = ex2(sreg[nt][3] - mn1);
            }
            ls0 += p00 + p01;
            ls1 += p10 + p11;
            *(uint32_t*)&Ps[rowA0 + nt * 8 + 2 * tig] = pack_h2(p00, p01);
            *(uint32_t*)&Ps[rowA1 + nt * 8 + 2 * tig] = pack_h2(p10, p11);
        }
        ls0 += __shfl_xor_sync(0xffffffffu, ls0, 1);
        ls0 += __shfl_xor_sync(0xffffffffu, ls0, 2);
        ls1 += __shfl_xor_sync(0xffffffffu, ls1, 1);
        ls1 += __shfl_xor_sync(0xffffffffu, ls1, 2);
        l0 = l0 * al0 + ls0;
        l1 = l1 * al1 + ls1;
#pragma unroll
        for (int nt = 0; nt < 8; nt++) {
            o_acc[nt][0] *= al0; o_acc[nt][1] *= al0;
            o_acc[nt][2] *= al1; o_acc[nt][3] *= al1;
        }
        __syncwarp();

        // ---- O += P V ----
#pragma unroll
        for (int kk = 0; kk < 4; kk++) {
            uint32_t a[4];
            ldsm_x4(a, pA + (uint32_t)(kk * 32));
#pragma unroll
            for (int nt2 = 0; nt2 < 4; nt2++) {
                uint32_t vb[4];
                ldsm_x4_t(vb, vA + (uint32_t)(kk * ROW16 + nt2 * 32));
                mma_f16(o_acc[2 * nt2],     a, vb[0], vb[1]);
                mma_f16(o_acc[2 * nt2 + 1], a, vb[2], vb[3]);
            }
        }
        buf ^= 1;
    }

    // ---- epilogue: fp16 output ----
    const float inv0 = 1.f / l0, inv1 = 1.f / l1;
    __half* orow0 = O + ((size_t)(b * Ss + qt * 128 + q0 + gid)) * Dd + h * HD;
    __half* orow1 = O + ((size_t)(b * Ss + qt * 128 + q0 + gid + 8)) * Dd + h * HD;
#pragma unroll
    for (int nt = 0; nt < 8; nt++) {
        *(uint32_t*)(orow0 + nt * 8 + 2 * tig) =
            pack_h2(o_acc[nt][0] * inv0, o_acc[nt][1] * inv0);
        *(uint32_t*)(orow1 + nt * 8 + 2 * tig) =
            pack_h2(o_acc[nt][2] * inv1, o_acc[nt][3] * inv1);
    }
}

// ---------------- LayerNorm kernels ----------------
__global__ void __launch_bounds__(128) ln_add_k(
    const float* __restrict__ A, const float* __restrict__ R,
    const float* __restrict__ g, const float* __restrict__ be,
    float* __restrict__ O, __half* __restrict__ Oh)
{
    const int row = blockIdx.x, t = threadIdx.x;
    const size_t base = (size_t)row * Dd + t * 4;
    float4 a = *(const float4*)(A + base);
    float4 r = *(const float4*)(R + base);
    float x[4] = {a.x + r.x, a.y + r.y, a.z + r.z, a.w + r.w};

    float s = x[0] + x[1] + x[2] + x[3];
    float ss = x[0]*x[0] + x[1]*x[1] + x[2]*x[2] + x[3]*x[3];
    __shared__ float sh1[4], sh2[4];
#pragma unroll
    for (int o = 16; o; o >>= 1) {
        s  += __shfl_xor_sync(0xffffffffu, s, o);
        ss += __shfl_xor_sync(0xffffffffu, ss, o);
    }
    if (!(t & 31)) { sh1[t >> 5] = s; sh2[t >> 5] = ss; }
    __syncthreads();
    s  = sh1[0] + sh1[1] + sh1[2] + sh1[3];
    ss = sh2[0] + sh2[1] + sh2[2] + sh2[3];

    const float mean = s * (1.f / Dd);
    const float var = ss * (1.f / Dd) - mean * mean;
    const float rs = rsqrtf(var + 1e-5f);
    float4 gg = *(const float4*)(g + t * 4);
    float4 bb = *(const float4*)(be + t * 4);
    float4 o4;
    o4.x = (x[0] - mean) * rs * gg.x + bb.x;
    o4.y = (x[1] - mean) * rs * gg.y + bb.y;
    o4.z = (x[2] - mean) * rs * gg.z + bb.z;
    o4.w = (x[3] - mean) * rs * gg.w + bb.w;
    *(float4*)(O + base) = o4;
    uint2 hv;
    hv.x = pack_h2(o4.x, o4.y);
    hv.y = pack_h2(o4.z, o4.w);
    *(uint2*)(Oh + base) = hv;
}

__global__ void __launch_bounds__(128) ln_add_ln_k(
    const float* __restrict__ A, const float* __restrict__ R,
    const float* __restrict__ g2, const float* __restrict__ b2,
    const float* __restrict__ g3, const float* __restrict__ b3,
    float* __restrict__ O)
{
    const int row = blockIdx.x, t = threadIdx.x;
    const size_t base = (size_t)row * Dd + t * 4;
    float4 a = *(const float4*)(A + base);
    float4 r = *(const float4*)(R + base);
    float x[4] = {a.x + r.x, a.y + r.y, a.z + r.z, a.w + r.w};

    __shared__ float sh1[4], sh2[4];
    float s = x[0] + x[1] + x[2] + x[3];
    float ss = x[0]*x[0] + x[1]*x[1] + x[2]*x[2] + x[3]*x[3];
#pragma unroll
    for (int o = 16; o; o >>= 1) {
        s  += __shfl_xor_sync(0xffffffffu, s, o);
        ss += __shfl_xor_sync(0xffffffffu, ss, o);
    }
    if (!(t & 31)) { sh1[t >> 5] = s; sh2[t >> 5] = ss; }
    __syncthreads();
    s  = sh1[0] + sh1[1] + sh1[2] + sh1[3];
    ss = sh2[0] + sh2[1] + sh2[2] + sh2[3];
    float mean = s * (1.f / Dd);
    float var = ss * (1.f / Dd) - mean * mean;
    float rs = rsqrtf(var + 1e-5f);

    float4 gg = *(const float4*)(g2 + t * 4);
    float4 bb = *(const float4*)(b2 + t * 4);
    float y[4];
    y[0] = (x[0] - mean) * rs * gg.x + bb.x;
    y[1] = (x[1] - mean) * rs * gg.y + bb.y;
    y[2] = (x[2] - mean) * rs * gg.z + bb.z;
    y[3] = (x[3] - mean) * rs * gg.w + bb.w;

    __syncthreads();
    s  = y[0] + y[1] + y[2] + y[3];
    ss = y[0]*y[0] + y[1]*y[1] + y[2]*y[2] + y[3]*y[3];
#pragma unroll
    for (int o = 16; o; o >>= 1) {
        s  += __shfl_xor_sync(0xffffffffu, s, o);
        ss += __shfl_xor_sync(0xffffffffu, ss, o);
    }
    if (!(t & 31)) { sh1[t >> 5] = s; sh2[t >> 5] = ss; }
    __syncthreads();
    s  = sh1[0] + sh1[1] + sh1[2] + sh1[3];
    ss = sh2[0] + sh2[1] + sh2[2] + sh2[3];
    mean = s * (1.f / Dd);
    var = ss * (1.f / Dd) - mean * mean;
    rs = rsqrtf(var + 1e-5f);

    float4 g3v = *(const float4*)(g3 + t * 4);
    float4 b3v = *(const float4*)(b3 + t * 4);
    float4 o4;
    o4.x = (y[0] - mean) * rs * g3v.x + b3v.x;
    o4.y = (y[1] - mean) * rs * g3v.y + b3v.y;
    o4.z = (y[2] - mean) * rs * g3v.z + b3v.z;
    o4.w = (y[3] - mean) * rs * g3v.w + b3v.w;
    *(float4*)(O + base) = o4;
}

// ---------------- mean pool over S (deterministic 2-stage) ----------------
__global__ void __launch_bounds__(128) colmean_part_k(const float* __restrict__ X,
                                                      float* __restrict__ PP)
{
    const int b = blockIdx.x >> 2;
    const int d = (blockIdx.x & 3) * 128 + threadIdx.x;
    const int sc = blockIdx.y;
    float s = 0.f;
    for (int j = sc * 128; j < sc * 128 + 128; j++)
        s += X[((size_t)(b * Ss + j)) * Dd + d];
    PP[((size_t)sc * Bb + b) * Dd + d] = s;
}

__global__ void __launch_bounds__(128) colmean_fin_k(const float* __restrict__ PP,
                                                     float* __restrict__ P)
{
    const int idx = blockIdx.x * 128 + threadIdx.x;
    const int b = idx / Dd, d = idx % Dd;
    float s = 0.f;
#pragma unroll
    for (int c = 0; c < 16; c++) s += PP[((size_t)c * Bb + b) * Dd + d];
    P[idx] = s * (1.f / Ss);
}

// ---------------- final tiny GEMM ----------------
__global__ void __launch_bounds__(128) final_k(const float* __restrict__ P,
                                               const float* __restrict__ Wt,
                                               const float* __restrict__ bias,
                                               float* __restrict__ out)
{
    const int b = blockIdx.x, o = threadIdx.x;
    float s = bias[o];
    for (int d = 0; d < Dd; d++) s += P[b * Dd + d] * Wt[d * DOUT + o];
    out[b * DOUT + o] = s;
}

// ---------------- launch ----------------
extern "C" void kernel_launch(void* const* d_in, const int* in_sizes, int n_in,
                              void* d_out, int out_size)
{
    const float* x      = (const float*)d_in[0];
    const float* pos    = (const float*)d_in[1];
    const float* win_w  = (const float*)d_in[2];
    const float* win_b  = (const float*)d_in[3];
    const float* l_wqkv = (const float*)d_in[4];
    const float* l_bqkv = (const float*)d_in[5];
    const float* l_wo   = (const float*)d_in[6];
    const float* l_bo   = (const float*)d_in[7];
    const float* g_wqkv = (const float*)d_in[8];
    const float* g_bqkv = (const float*)d_in[9];
    const float* g_wo   = (const float*)d_in[10];
    const float* g_bo   = (const float*)d_in[11];
    const float* gate_w = (const float*)d_in[12];
    const float* gate_b = (const float*)d_in[13];
    const float* ffn_w1 = (const float*)d_in[14];
    const float* ffn_b1 = (const float*)d_in[15];
    const float* ffn_w2 = (const float*)d_in[16];
    const float* ffn_b2 = (const float*)d_in[17];
    const float* n1_g   = (const float*)d_in[18];
    const float* n1_b   = (const float*)d_in[19];
    const float* n2_g   = (const float*)d_in[20];
    const float* n2_b   = (const float*)d_in[21];
    const float* n3_g   = (const float*)d_in[22];
    const float* n3_b   = (const float*)d_in[23];
    const float* out_w  = (const float*)d_in[24];
    const float* out_b  = (const float*)d_in[25];

    float* sp = nullptr;
    cudaGetSymbolAddress((void**)&sp, g_scratch);
    float* bH   = sp + O_H;
    float* bLOC = sp + O_LOC;
    float* bGLO = sp + O_GLO;
    float* bFUS = sp + O_FUS;
    float* bH1  = sp + O_H1;
    float* bFFN = sp + O_FFN;
    float* bH3  = sp + O_H3;
    float* bPP  = sp + O_PP;
    float* bP   = sp + O_P;

    __half* hQKV = (__half*)(sp + O_QL);           // 6 slices, stride 2*NBD halfs
    const __half* hQL = (const __half*)(sp + O_QL);
    const __half* hKL = (const __half*)(sp + O_KL);
    const __half* hVL = (const __half*)(sp + O_VL);
    const __half* hQG = (const __half*)(sp + O_QG);
    const __half* hKG = (const __half*)(sp + O_KG);
    const __half* hVG = (const __half*)(sp + O_VG);
    __half* hAOL = (__half*)(sp + O_AOL);
    __half* hAOG = (__half*)(sp + O_AOG);
    __half* hT1  = (__half*)(sp + O_T1H);
    __half* bHh  = (__half*)(sp + O_HH);
    __half* bH1h = (__half*)(sp + O_HH + NBD / 2);
    __half* hLOCh = (__half*)(sp + O_LGH);          // GLOh = hLOCh + NBD halfs

    __half* pool = (__half*)(sp + O_WH);
    __half* hx    = pool;
    __half* hwin  = hx    + (size_t)BS * DIN;
    __half* hlq   = hwin  + (size_t)DIN * Dd;
    __half* hgq   = hlq   + (size_t)3 * Dd * Dd;
    __half* hlwo  = hgq   + (size_t)3 * Dd * Dd;
    __half* hgwo  = hlwo  + (size_t)Dd * Dd;
    __half* hgate = hgwo  + (size_t)Dd * Dd;
    __half* hf1   = hgate + (size_t)2 * Dd * Dd;
    __half* hf2   = hf1   + (size_t)2 * Dd * Dd;

    static bool attr_set = false;
    if (!attr_set) {
        cudaFuncSetAttribute(flash_tc_k, cudaFuncAttributeMaxDynamicSharedMemorySize,
                             FL_SMEM_BYTES);
        attr_set = true;
    }

    const dim3 blk(256);

    // 0. convert inputs + weights to fp16 (one merged launch)
    {
        CvtJobs jobs;
        jobs.j[0] = {x,      hx,    BS * DIN};
        jobs.j[1] = {win_w,  hwin,  DIN * Dd};
        jobs.j[2] = {l_wqkv, hlq,   3 * Dd * Dd};
        jobs.j[3] = {g_wqkv, hgq,   3 * Dd * Dd};
        jobs.j[4] = {l_wo,   hlwo,  Dd * Dd};
        jobs.j[5] = {g_wo,   hgwo,  Dd * Dd};
        jobs.j[6] = {gate_w, hgate, 2 * Dd * Dd};
        jobs.j[7] = {ffn_w1, hf1,   Dd * 2 * Dd};
        jobs.j[8] = {ffn_w2, hf2,   2 * Dd * Dd};
        f2h_all_k<<<dim3((BS * DIN / 8 + 255) / 256, 9), 256>>>(jobs);
    }

    // 1. h = x @ win_w + win_b + pos  (fp32 + fp16 copies)
    gemm_tc_k<1><<<dim3(4, 64), blk>>>(hx, nullptr, DIN, 0, hwin, nullptr,
                                       win_b, nullptr, pos, nullptr,
                                       bH, bHh, 0, Dd, DIN);

    // 2. merged 6-slice QKV -> fp16 (Q pre-scaled by SCALE*log2e)
    gemm_tc_k<4><<<dim3(24, 64), blk>>>(bHh, nullptr, Dd, 0, hlq, hgq,
                                        l_bqkv, g_bqkv, nullptr, nullptr,
                                        nullptr, hQKV, 2 * (long)NBD, Dd, Dd);

    // 3+4. merged local banded + global flash attention (one launch)
    flash_tc_k<<<dim3(Ss / 128, Hh, 2 * Bb), 256, FL_SMEM_BYTES>>>(
        hQL, hKL, hVL, hAOL, hQG, hKG, hVG, hAOG);

    // 5. merged 2-slice output projections -> LOC/GLO fp32 + fp16
    gemm_tc_k<5><<<dim3(8, 64), blk>>>(hAOL, hAOG, Dd, 0, hlwo, hgwo,
                                       l_bo, g_bo, nullptr, nullptr,
                                       bLOC, hLOCh, (long)NBD, Dd, Dd);

    // 6. gate GEMM fused with blend (A = LOCh || GLOh)
    gemm_tc_k<3><<<dim3(4, 64), blk>>>(hLOCh, hLOCh + NBD, Dd, Dd, hgate, nullptr,
                                       gate_b, nullptr, bLOC, bGLO,
                                       bFUS, nullptr, 0, Dd, 2 * Dd);

    // 7. h1 = LN(h + fused)  (fp32 + fp16)
    ln_add_k<<<BS, 128>>>(bH, bFUS, n1_g, n1_b, bH1, bH1h);

    // 8. FFN
    gemm_tc_k<2><<<dim3(8, 64), blk>>>(bH1h, nullptr, Dd, 0, hf1, nullptr,
                                       ffn_b1, nullptr, nullptr, nullptr,
                                       nullptr, hT1, 0, 2 * Dd, Dd);
    gemm_tc_k<0><<<dim3(4, 64), blk>>>(hT1, nullptr, 2 * Dd, 0, hf2, nullptr,
                                       ffn_b2, nullptr, nullptr, nullptr,
                                       bFFN, nullptr, 0, Dd, 2 * Dd);

    // 9. h3 = LN(LN(h1 + ffn))
    ln_add_ln_k<<<BS, 128>>>(bH1, bFFN, n2_g, n2_b, n3_g, n3_b, bH3);

    // 10. mean-pool over S, then final projection
    colmean_part_k<<<dim3(Bb * 4, 16), 128>>>(bH3, bPP);
    colmean_fin_k<<<(Bb * Dd) / 128, 128>>>(bPP, bP);
    final_k<<<Bb, DOUT>>>(bP, out_w, out_b, (float*)d_out);

    (void)in_sizes; (void)n_in; (void)out_size;
}

// round 12
// speedup vs baseline: 2.0277x; 1.0178x over previous
#include <cuda_runtime.h>
#include <cuda_fp16.h>
#include <math.h>
#include <stdint.h>

// ---------------- problem constants (hardcoded) ----------------
constexpr int   Bb   = 4;
constexpr int   Ss   = 2048;
constexpr int   DIN  = 256;
constexpr int   Dd   = 512;
constexpr int   Hh   = 8;
constexpr int   DOUT = 128;
constexpr int   HD   = 64;       // Dd / Hh
constexpr int   BS   = Bb * Ss;  // 8192 rows
constexpr float SCALE = 0.125f;  // 1/sqrt(64)
constexpr float LOG2E = 1.4426950408889634f;

// ---------------- scratch (static device memory; no allocs) ----------------
constexpr size_t NBD  = (size_t)BS * Dd;
constexpr size_t O_H   = 0;          // fp32
constexpr size_t O_QL  = 1 * NBD;    // fp16 QKV slices (slot stride NBD floats)
constexpr size_t O_KL  = 2 * NBD;
constexpr size_t O_VL  = 3 * NBD;
constexpr size_t O_QG  = 4 * NBD;
constexpr size_t O_KG  = 5 * NBD;
constexpr size_t O_VG  = 6 * NBD;
constexpr size_t O_AOL = 7 * NBD;    // fp16
constexpr size_t O_AOG = 8 * NBD;    // fp16
constexpr size_t O_LOC = 9 * NBD;    // fp32
constexpr size_t O_GLO = 10 * NBD;   // fp32
constexpr size_t O_FUS = 11 * NBD;   // fp32
constexpr size_t O_H1  = 12 * NBD;   // fp32
constexpr size_t O_FFN = 13 * NBD;   // fp32
constexpr size_t O_H3  = 14 * NBD;   // fp32
constexpr size_t O_T1H = 15 * NBD;   // fp16, 2*NBD halfs
constexpr size_t O_HH  = 16 * NBD;   // bHh + bH1h
constexpr size_t O_LGH = 17 * NBD;   // LOCh + GLOh
constexpr size_t O_WH  = 18 * NBD;   // fp16 weights + x pool
constexpr size_t O_PP  = 19 * NBD;
constexpr size_t O_P   = 19 * NBD + (size_t)16 * Bb * Dd;
constexpr size_t SCRATCH_FLOATS = O_P + (size_t)Bb * Dd;

__device__ float g_scratch[SCRATCH_FLOATS];

// ---------------- helpers ----------------
__device__ __forceinline__ uint32_t pack_h2(float x, float y) {
    __half2 h = __floats2half2_rn(x, y);
    return *(uint32_t*)&h;
}

__device__ __forceinline__ float ex2(float x) {
    float y;
    asm("ex2.approx.f32 %0, %1;" : "=f"(y) : "f"(x));
    return y;
}

__device__ __forceinline__ void mma_f16(float c[4], const uint32_t a[4],
                                        uint32_t b0, uint32_t b1) {
    asm volatile(
        "mma.sync.aligned.m16n8k16.row.col.f32.f16.f16.f32 "
        "{%0,%1,%2,%3},{%4,%5,%6,%7},{%8,%9},{%0,%1,%2,%3};\n"
        : "+f"(c[0]), "+f"(c[1]), "+f"(c[2]), "+f"(c[3])
        : "r"(a[0]), "r"(a[1]), "r"(a[2]), "r"(a[3]), "r"(b0), "r"(b1));
}

__device__ __forceinline__ void ldsm_x4(uint32_t r[4], uint32_t saddr) {
    asm volatile("ldmatrix.sync.aligned.m8n8.x4.shared.b16 {%0,%1,%2,%3}, [%4];"
                 : "=r"(r[0]), "=r"(r[1]), "=r"(r[2]), "=r"(r[3]) : "r"(saddr));
}

__device__ __forceinline__ void ldsm_x4_t(uint32_t r[4], uint32_t saddr) {
    asm volatile("ldmatrix.sync.aligned.m8n8.x4.trans.shared.b16 {%0,%1,%2,%3}, [%4];"
                 : "=r"(r[0]), "=r"(r[1]), "=r"(r[2]), "=r"(r[3]) : "r"(saddr));
}

__device__ __forceinline__ uint32_t smem_u32(const void* p) {
    uint32_t a;
    asm("{ .reg .u64 t; cvta.to.shared.u64 t, %1; cvt.u32.u64 %0, t; }"
        : "=r"(a) : "l"(p));
    return a;
}

__device__ __forceinline__ void cp_async16(uint32_t dst, const void* src) {
    asm volatile("cp.async.cg.shared.global [%0], [%1], 16;"
                 :: "r"(dst), "l"(src));
}
__device__ __forceinline__ void cp_async_commit() {
    asm volatile("cp.async.commit_group;");
}
template <int N>
__device__ __forceinline__ void cp_async_wait() {
    asm volatile("cp.async.wait_group %0;" :: "n"(N));
}

// ---------------- merged fp32 -> fp16 convert (9 jobs, one launch) ---------
struct CvtJob { const float* s; __half* d; int n; };
struct CvtJobs { CvtJob j[9]; };

__global__ void __launch_bounds__(256) f2h_all_k(CvtJobs jobs)
{
    const CvtJob jb = jobs.j[blockIdx.y];
    const int i = (blockIdx.x * 256 + threadIdx.x) * 8;
    if (i >= jb.n) return;
    float4 a = *(const float4*)(jb.s + i);
    float4 b = *(const float4*)(jb.s + i + 4);
    uint4 o;
    o.x = pack_h2(a.x, a.y); o.y = pack_h2(a.z, a.w);
    o.z = pack_h2(b.x, b.y); o.w = pack_h2(b.z, b.w);
    *(uint4*)(jb.d + i) = o;
}

// ---------------- FP16 GEMM, k-tile 32, 3-stage cp.async, one sync/iter ----
// MODE 0: C=fp32 +bias
// MODE 1: C=fp32 +bias+pos(p1); Ch=fp16 copy
// MODE 2: Ch=fp16 relu(+bias)
// MODE 3: A=concat(A,A2) on K; g=tanh(relu(acc+bias)); C=g*p1+(1-g)*p2 fp32
// MODE 4: 6-slice QKV -> Ch fp16 (Q slices x SCALE*LOG2E)
// MODE 5: 2-slice Wo -> C fp32 and Ch fp16
constexpr int SRA = 40;    // 32 + 8 pad (5r%8 conflict-free)
constexpr int SRB = 136;
constexpr int STG = 3;

template <int MODE>
__global__ void __launch_bounds__(256) gemm_tc_k(
    const __half* __restrict__ A, const __half* __restrict__ A2, int lda, int KA,
    const __half* __restrict__ W, const __half* __restrict__ W2,
    const float* __restrict__ bias, const float* __restrict__ bias2,
    const float* __restrict__ p1, const float* __restrict__ p2,
    float* __restrict__ C, __half* __restrict__ Ch, long chStride,
    int N, int K)
{
    __shared__ __half As[STG][128][SRA];
    __shared__ __half Bs[STG][32][SRB];

    const int t  = threadIdx.x;
    const int m0 = blockIdx.y * 128;

    const __half* Asel = A;
    const __half* Wsel = W;
    const float* bsel = bias;
    float* Csel = C;
    __half* Chsel = Ch;
    float oscale = 1.f;
    int n0;
    if (MODE == 4 || MODE == 5) {
        const int isl = blockIdx.x >> 2;
        n0 = (blockIdx.x & 3) * 128;
        if (MODE == 4) {
            Wsel = (isl < 3) ? W + (size_t)isl * Dd * Dd
                             : W2 + (size_t)(isl - 3) * Dd * Dd;
            bsel = (isl < 3) ? bias + isl * Dd : bias2 + (isl - 3) * Dd;
            if (isl == 0 || isl == 3) oscale = SCALE * LOG2E;
        } else {
            Asel = isl ? A2 : A;
            Wsel = isl ? W2 : W;
            bsel = isl ? bias2 : bias;
            Csel = C + (size_t)isl * NBD;
        }
        Chsel = Ch + (size_t)isl * chStride;
    } else {
        n0 = blockIdx.x * 128;
    }

    const int lane = t & 31, w = t >> 5;
    const int wm = w & 1, wn = w >> 1;
    const int gid = lane >> 2, tig = lane & 3;
    const int mw = wm * 64, nw = wn * 32;

    const int amr = t >> 1;          // A loader: m row
    const int akc = (t & 1) * 16;    // A loader: k col 0/16
    const int bkr = t >> 4;          // B loader: k rows bkr, bkr+16
    const int bnc = (t & 15) * 8;    // B loader: n col

    constexpr uint32_t ABUF = 128 * SRA * 2;
    constexpr uint32_t BBUF = 32 * SRB * 2;
    const uint32_t aDst  = smem_u32(&As[0][amr][akc]);
    const uint32_t bDst0 = smem_u32(&Bs[0][bkr][bnc]);
    const uint32_t bDst1 = smem_u32(&Bs[0][bkr + 16][bnc]);
    const uint32_t aAddr0 = smem_u32(&As[0][mw + (lane & 15)][(lane >> 4) * 8]);
    const uint32_t bAddr0 = smem_u32(&Bs[0][(lane & 7) + 8 * ((lane >> 3) & 1)]
                                        [nw + 8 * (lane >> 4)]);

    float acc[4][4][4] = {};

    const int nk = K / 32;
    auto load_tile = [&](int kt, int stg) {
        const __half* Asrc = Asel;
        int kk0 = kt * 32;
        if (MODE == 3 && kk0 >= KA) { Asrc = A2; kk0 -= KA; }
        const __half* arow = Asrc + (size_t)(m0 + amr) * lda + kk0 + akc;
        cp_async16(aDst + (uint32_t)stg * ABUF,      arow);
        cp_async16(aDst + (uint32_t)stg * ABUF + 16, arow + 8);
        cp_async16(bDst0 + (uint32_t)stg * BBUF,
                   Wsel + (size_t)(kt * 32 + bkr) * N + n0 + bnc);
        cp_async16(bDst1 + (uint32_t)stg * BBUF,
                   Wsel + (size_t)(kt * 32 + bkr + 16) * N + n0 + bnc);
        cp_async_commit();
    };

    load_tile(0, 0);
    load_tile(1, 1);

    for (int it = 0; it < nk; it++) {
        if (it == nk - 1) cp_async_wait<0>();
        else              cp_async_wait<1>();
        __syncthreads();

        if (it + 2 < nk) load_tile(it + 2, (it + 2) % STG);

        const int stg = it % STG;
        const uint32_t aA = aAddr0 + (uint32_t)stg * ABUF;
        const uint32_t bA = bAddr0 + (uint32_t)stg * BBUF;
#pragma unroll
        for (int kk2 = 0; kk2 < 2; kk2++) {
            uint32_t af[4][4], bb[2][4];
#pragma unroll
            for (int mt = 0; mt < 4; mt++)
                ldsm_x4(af[mt], aA + (uint32_t)(mt * 16 * SRA * 2 + kk2 * 32));
#pragma unroll
            for (int nb2 = 0; nb2 < 2; nb2++)
                ldsm_x4_t(bb[nb2], bA + (uint32_t)(kk2 * 16 * SRB * 2 + nb2 * 32));
#pragma unroll
            for (int mt = 0; mt < 4; mt++) {
                mma_f16(acc[mt][0], af[mt], bb[0][0], bb[0][1]);
                mma_f16(acc[mt][1], af[mt], bb[0][2], bb[0][3]);
                mma_f16(acc[mt][2], af[mt], bb[1][0], bb[1][1]);
                mma_f16(acc[mt][3], af[mt], bb[1][2], bb[1][3]);
            }
        }
    }

    // ---- epilogue ----
#pragma unroll
    for (int mt = 0; mt < 4; mt++) {
#pragma unroll
        for (int hf = 0; hf < 2; hf++) {
            const int row = m0 + mw + mt * 16 + gid + hf * 8;
#pragma unroll
            for (int nt = 0; nt < 4; nt++) {
                const int col = n0 + nw + nt * 8 + tig * 2;
                float v0 = acc[mt][nt][hf * 2 + 0] + bsel[col];
                float v1 = acc[mt][nt][hf * 2 + 1] + bsel[col + 1];
                if (MODE == 1) {
                    const size_t pr = (size_t)(row & (Ss - 1)) * N + col;
                    v0 += p1[pr]; v1 += p1[pr + 1];
                }
                if (MODE == 2) { v0 = fmaxf(v0, 0.f); v1 = fmaxf(v1, 0.f); }
                if (MODE == 3) {
                    const size_t pr = (size_t)row * N + col;
                    float g0 = tanhf(fmaxf(v0, 0.f));
                    float g1 = tanhf(fmaxf(v1, 0.f));
                    v0 = g0 * p1[pr] + (1.f - g0) * p2[pr];
                    v1 = g1 * p1[pr + 1] + (1.f - g1) * p2[pr + 1];
                }
                if (MODE == 0 || MODE == 1 || MODE == 3 || MODE == 5) {
                    float2 o2; o2.x = v0; o2.y = v1;
                    *(float2*)(Csel + (size_t)row * N + col) = o2;
                }
                if (MODE == 1 || MODE == 2 || MODE == 4 || MODE == 5) {
                    *(uint32_t*)(Chsel + (size_t)row * N + col) =
                        pack_h2(v0 * oscale, v1 * oscale);
                }
            }
        }
    }
}

// ---------------- merged FP16 flash attention (3-stage K/V, h2exp2) --------
// grid z in [0, 2*Bb): z<Bb -> banded (|q-k|<=32), else global.
// Scores pre-scaled by 1/sqrt(HD)*log2(e); softmax in base-2 via ex2/h2exp2.
constexpr int SRF = 72;
constexpr int FQ_OFF = 0;
constexpr int FP_OFF = 128 * SRF;
constexpr int FK_OFF = 2 * 128 * SRF;
constexpr int FV_OFF = FK_OFF + 3 * 64 * SRF;
constexpr int FL_SMEM_HALFS = FV_OFF + 3 * 64 * SRF;
constexpr int FL_SMEM_BYTES = FL_SMEM_HALFS * 2;   // 92,160 B

__global__ void __launch_bounds__(256) flash_tc_k(
    const __half* __restrict__ QL, const __half* __restrict__ KL,
    const __half* __restrict__ VL, __half* __restrict__ OL,
    const __half* __restrict__ QG, const __half* __restrict__ KG,
    const __half* __restrict__ VG, __half* __restrict__ OG)
{
    extern __shared__ __half smh[];
    __half* Qs = smh + FQ_OFF;
    __half* Ps = smh + FP_OFF;
    __half* Ks = smh + FK_OFF;
    __half* Vs = smh + FV_OFF;

    const int qt = blockIdx.x, h = blockIdx.y;
    const bool banded = blockIdx.z < (unsigned)Bb;
    const int b = blockIdx.z & (Bb - 1);
    const __half* Q = banded ? QL : QG;
    const __half* K = banded ? KL : KG;
    const __half* V = banded ? VL : VG;
    __half* O = banded ? OL : OG;

    const int t  = threadIdx.x;
    const int lane = t & 31, w = t >> 5;
    const int gid = lane >> 2, tig = lane & 3;
    const int q0 = w * 16;

    constexpr uint32_t BUFO  = 64 * SRF * 2;
    constexpr uint32_t ROW16 = 16 * SRF * 2;
    const uint32_t qA  = smem_u32(&Qs[(q0 + (lane & 15)) * SRF + (lane >> 4) * 8]);
    const uint32_t pA  = smem_u32(&Ps[(q0 + (lane & 15)) * SRF + (lane >> 4) * 8]);
    const uint32_t kA0 = smem_u32(&Ks[((lane & 7) + 8 * ((lane >> 3) & 1)) * SRF
                                      + (lane >> 4) * 8]);
    const uint32_t vA0 = smem_u32(&Vs[((lane & 7) + 8 * ((lane >> 3) & 1)) * SRF
                                      + (lane >> 4) * 8]);

    const int lr = t >> 2;
    const int lc = (t & 3) * 16;
    const uint32_t kDst0 = smem_u32(&Ks[lr * SRF + lc]);
    const uint32_t vDst0 = smem_u32(&Vs[lr * SRF + lc]);
    const size_t g_row_base = ((size_t)(b * Ss + lr)) * Dd + h * HD + lc;

    // ---- load Q tile (fp16, pre-scaled incl. log2e) ----
    {
        const int r  = t >> 1;
        const int c0 = (t & 1) * 32;
        const __half* src = Q + ((size_t)(b * Ss + qt * 128 + r)) * Dd + h * HD + c0;
#pragma unroll
        for (int i = 0; i < 4; i++)
            *(uint4*)&Qs[r * SRF + c0 + i * 8] = *(const uint4*)(src + i * 8);
    }

    float o_acc[8][4] = {};
    float m0 = -1e30f, m1 = -1e30f, l0 = 0.f, l1 = 0.f;

    const int rowA0 = (q0 + gid) * SRF;
    const int rowA1 = (q0 + gid + 8) * SRF;
    const int qr0 = qt * 128 + q0 + gid;
    const int qr1 = qr0 + 8;

    int k_begin = 0, k_end = Ss;
    if (banded) {
        k_begin = qt * 128 - 64; if (k_begin < 0) k_begin = 0;
        k_end   = qt * 128 + 192; if (k_end > Ss) k_end = Ss;
    }
    const int ntile = (k_end - k_begin) >> 6;   // always >= 2

    auto load_kv = [&](int k0, int stg) {
        const uint32_t off = (uint32_t)stg * BUFO;
        const __half* ks = K + g_row_base + (size_t)k0 * Dd;
        const __half* vs = V + g_row_base + (size_t)k0 * Dd;
        cp_async16(kDst0 + off,      ks);
        cp_async16(kDst0 + off + 16, ks + 8);
        cp_async16(vDst0 + off,      vs);
        cp_async16(vDst0 + off + 16, vs + 8);
        cp_async_commit();
    };

    load_kv(k_begin, 0);
    load_kv(k_begin + 64, 1);

    for (int it = 0; it < ntile; it++) {
        if (it == ntile - 1) cp_async_wait<0>();
        else                 cp_async_wait<1>();
        __syncthreads();

        if (it + 2 < ntile) load_kv(k_begin + (it + 2) * 64, (it + 2) % STG);

        const int k0 = k_begin + it * 64;
        const int stg = it % STG;
        const uint32_t kA = kA0 + (uint32_t)stg * BUFO;
        const uint32_t vA = vA0 + (uint32_t)stg * BUFO;

        // ---- S = Q K^T (scores in log2 domain) ----
        float sreg[8][4] = {};
#pragma unroll
        for (int kk = 0; kk < 4; kk++) {
            uint32_t a[4];
            ldsm_x4(a, qA + (uint32_t)(kk * 32));
#pragma unroll
            for (int nt2 = 0; nt2 < 4; nt2++) {
                uint32_t kb[4];
                ldsm_x4(kb, kA + (uint32_t)(nt2 * ROW16 + kk * 32));
                mma_f16(sreg[2 * nt2],     a, kb[0], kb[2]);
                mma_f16(sreg[2 * nt2 + 1], a, kb[1], kb[3]);
            }
        }

        if (banded) {
#pragma unroll
            for (int nt = 0; nt < 8; nt++) {
                const int kg = k0 + nt * 8 + 2 * tig;
                if (abs(qr0 - kg)       > 32) sreg[nt][0] = -1e30f;
                if (abs(qr0 - (kg + 1)) > 32) sreg[nt][1] = -1e30f;
                if (abs(qr1 - kg)       > 32) sreg[nt][2] = -1e30f;
                if (abs(qr1 - (kg + 1)) > 32) sreg[nt][3] = -1e30f;
            }
        }

        // ---- online softmax (base-2, f16x2 exp) ----
        float mt0 = -1e30f, mt1 = -1e30f;
#pragma unroll
        for (int nt = 0; nt < 8; nt++) {
            mt0 = fmaxf(mt0, fmaxf(sreg[nt][0], sreg[nt][1]));
            mt1 = fmaxf(mt1, fmaxf(sreg[nt][2], sreg[nt][3]));
        }
        mt0 = fmaxf(mt0, __shfl_xor_sync(0xffffffffu, mt0, 1));
        mt0 = fmaxf(mt0, __shfl_xor_sync(0xffffffffu, mt0, 2));
        mt1 = fmaxf(mt1, __shfl_xor_sync(0xffffffffu, mt1, 1));
        mt1 = fmaxf(mt1, __shfl_xor_sync(0xffffffffu, mt1, 2));

        const float mn0 = fmaxf(m0, mt0), mn1 = fmaxf(m1, mt1);
        const float al0 = ex2(m0 - mn0), al1 = ex2(m1 - mn1);
        m0 = mn0; m1 = mn1;

        float ls0 = 0.f, ls1 = 0.f;
#pragma unroll
        for (int nt = 0; nt < 8; nt++) {
            float d00, d01, d10, d11;
            if (banded) {
                d00 = (sreg[nt][0] > -1e29f) ? sreg[nt][0] - mn0 : -INFINITY;
                d01 = (sreg[nt][1] > -1e29f) ? sreg[nt][1] - mn0 : -INFINITY;
                d10 = (sreg[nt][2] > -1e29f) ? sreg[nt][2] - mn1 : -INFINITY;
                d11 = (sreg[nt][3] > -1e29f) ? sreg[nt][3] - mn1 : -INFINITY;
            } else {
                d00 = sreg[nt][0] - mn0;
                d01 = sreg[nt][1] - mn0;
                d10 = sreg[nt][2] - mn1;
                d11 = sreg[nt][3] - mn1;
            }
            __half2 p0 = h2exp2(__floats2half2_rn(d00, d01));
            __half2 p1 = h2exp2(__floats2half2_rn(d10, d11));
            *(__half2*)&Ps[rowA0 + nt * 8 + 2 * tig] = p0;
            *(__half2*)&Ps[rowA1 + nt * 8 + 2 * tig] = p1;
            float2 f0 = __half22float2(p0);
            float2 f1 = __half22float2(p1);
            ls0 += f0.x + f0.y;
            ls1 += f1.x + f1.y;
        }
        ls0 += __shfl_xor_sync(0xffffffffu, ls0, 1);
        ls0 += __shfl_xor_sync(0xffffffffu, ls0, 2);
        ls1 += __shfl_xor_sync(0xffffffffu, ls1, 1);
        ls1 += __shfl_xor_sync(0xffffffffu, ls1, 2);
        l0 = l0 * al0 + ls0;
        l1 = l1 * al1 + ls1;
#pragma unroll
        for (int nt = 0; nt < 8; nt++) {
            o_acc[nt][0] *= al0; o_acc[nt][1] *= al0;
            o_acc[nt][2] *= al1; o_acc[nt][3] *= al1;
        }
        __syncwarp();   // Ps rows q0..q0+15 are warp-local

        // ---- O += P V ----
#pragma unroll
        for (int kk = 0; kk < 4; kk++) {
            uint32_t a[4];
            ldsm_x4(a, pA + (uint32_t)(kk * 32));
#pragma unroll
            for (int nt2 = 0; nt2 < 4; nt2++) {
                uint32_t vb[4];
                ldsm_x4_t(vb, vA + (uint32_t)(kk * ROW16 + nt2 * 32));
                mma_f16(o_acc[2 * nt2],     a, vb[0], vb[1]);
                mma_f16(o_acc[2 * nt2 + 1], a, vb[2], vb[3]);
            }
        }
    }

    // ---- epilogue: fp16 output ----
    const float inv0 = 1.f / l0, inv1 = 1.f / l1;
    __half* orow0 = O + ((size_t)(b * Ss + qt * 128 + q0 + gid)) * Dd + h * HD;
    __half* orow1 = O + ((size_t)(b * Ss + qt * 128 + q0 + gid + 8)) * Dd + h * HD;
#pragma unroll
    for (int nt = 0; nt < 8; nt++) {
        *(uint32_t*)(orow0 + nt * 8 + 2 * tig) =
            pack_h2(o_acc[nt][0] * inv0, o_acc[nt][1] * inv0);
        *(uint32_t*)(orow1 + nt * 8 + 2 * tig) =
            pack_h2(o_acc[nt][2] * inv1, o_acc[nt][3] * inv1);
    }
}

// ---------------- LayerNorm kernels ----------------
__global__ void __launch_bounds__(128) ln_add_k(
    const float* __restrict__ A, const float* __restrict__ R,
    const float* __restrict__ g, const float* __restrict__ be,
    float* __restrict__ O, __half* __restrict__ Oh)
{
    const int row = blockIdx.x, t = threadIdx.x;
    const size_t base = (size_t)row * Dd + t * 4;
    float4 a = *(const float4*)(A + base);
    float4 r = *(const float4*)(R + base);
    float x[4] = {a.x + r.x, a.y + r.y, a.z + r.z, a.w + r.w};

    float s = x[0] + x[1] + x[2] + x[3];
    float ss = x[0]*x[0] + x[1]*x[1] + x[2]*x[2] + x[3]*x[3];
    __shared__ float sh1[4], sh2[4];
#pragma unroll
    for (int o = 16; o; o >>= 1) {
        s  += __shfl_xor_sync(0xffffffffu, s, o);
        ss += __shfl_xor_sync(0xffffffffu, ss, o);
    }
    if (!(t & 31)) { sh1[t >> 5] = s; sh2[t >> 5] = ss; }
    __syncthreads();
    s  = sh1[0] + sh1[1] + sh1[2] + sh1[3];
    ss = sh2[0] + sh2[1] + sh2[2] + sh2[3];

    const float mean = s * (1.f / Dd);
    const float var = ss * (1.f / Dd) - mean * mean;
    const float rs = rsqrtf(var + 1e-5f);
    float4 gg = *(const float4*)(g + t * 4);
    float4 bb = *(const float4*)(be + t * 4);
    float4 o4;
    o4.x = (x[0] - mean) * rs * gg.x + bb.x;
    o4.y = (x[1] - mean) * rs * gg.y + bb.y;
    o4.z = (x[2] - mean) * rs * gg.z + bb.z;
    o4.w = (x[3] - mean) * rs * gg.w + bb.w;
    *(float4*)(O + base) = o4;
    uint2 hv;
    hv.x = pack_h2(o4.x, o4.y);
    hv.y = pack_h2(o4.z, o4.w);
    *(uint2*)(Oh + base) = hv;
}

__global__ void __launch_bounds__(128) ln_add_ln_k(
    const float* __restrict__ A, const float* __restrict__ R,
    const float* __restrict__ g2, const float* __restrict__ b2,
    const float* __restrict__ g3, const float* __restrict__ b3,
    float* __restrict__ O)
{
    const int row = blockIdx.x, t = threadIdx.x;
    const size_t base = (size_t)row * Dd + t * 4;
    float4 a = *(const float4*)(A + base);
    float4 r = *(const float4*)(R + base);
    float x[4] = {a.x + r.x, a.y + r.y, a.z + r.z, a.w + r.w};

    __shared__ float sh1[4], sh2[4];
    float s = x[0] + x[1] + x[2] + x[3];
    float ss = x[0]*x[0] + x[1]*x[1] + x[2]*x[2] + x[3]*x[3];
#pragma unroll
    for (int o = 16; o; o >>= 1) {
        s  += __shfl_xor_sync(0xffffffffu, s, o);
        ss += __shfl_xor_sync(0xffffffffu, ss, o);
    }
    if (!(t & 31)) { sh1[t >> 5] = s; sh2[t >> 5] = ss; }
    __syncthreads();
    s  = sh1[0] + sh1[1] + sh1[2] + sh1[3];
    ss = sh2[0] + sh2[1] + sh2[2] + sh2[3];
    float mean = s * (1.f / Dd);
    float var = ss * (1.f / Dd) - mean * mean;
    float rs = rsqrtf(var + 1e-5f);

    float4 gg = *(const float4*)(g2 + t * 4);
    float4 bb = *(const float4*)(b2 + t * 4);
    float y[4];
    y[0] = (x[0] - mean) * rs * gg.x + bb.x;
    y[1] = (x[1] - mean) * rs * gg.y + bb.y;
    y[2] = (x[2] - mean) * rs * gg.z + bb.z;
    y[3] = (x[3] - mean) * rs * gg.w + bb.w;

    __syncthreads();
    s  = y[0] + y[1] + y[2] + y[3];
    ss = y[0]*y[0] + y[1]*y[1] + y[2]*y[2] + y[3]*y[3];
#pragma unroll
    for (int o = 16; o; o >>= 1) {
        s  += __shfl_xor_sync(0xffffffffu, s, o);
        ss += __shfl_xor_sync(0xffffffffu, ss, o);
    }
    if (!(t & 31)) { sh1[t >> 5] = s; sh2[t >> 5] = ss; }
    __syncthreads();
    s  = sh1[0] + sh1[1] + sh1[2] + sh1[3];
    ss = sh2[0] + sh2[1] + sh2[2] + sh2[3];
    mean = s * (1.f / Dd);
    var = ss * (1.f / Dd) - mean * mean;
    rs = rsqrtf(var + 1e-5f);

    float4 g3v = *(const float4*)(g3 + t * 4);
    float4 b3v = *(const float4*)(b3 + t * 4);
    float4 o4;
    o4.x = (y[0] - mean) * rs * g3v.x + b3v.x;
    o4.y = (y[1] - mean) * rs * g3v.y + b3v.y;
    o4.z = (y[2] - mean) * rs * g3v.z + b3v.z;
    o4.w = (y[3] - mean) * rs * g3v.w + b3v.w;
    *(float4*)(O + base) = o4;
}

// ---------------- mean pool over S (deterministic 2-stage) ----------------
__global__ void __launch_bounds__(128) colmean_part_k(const float* __restrict__ X,
                                                      float* __restrict__ PP)
{
    const int b = blockIdx.x >> 2;
    const int d = (blockIdx.x & 3) * 128 + threadIdx.x;
    const int sc = blockIdx.y;
    float s = 0.f;
    for (int j = sc * 128; j < sc * 128 + 128; j++)
        s += X[((size_t)(b * Ss + j)) * Dd + d];
    PP[((size_t)sc * Bb + b) * Dd + d] = s;
}

__global__ void __launch_bounds__(128) colmean_fin_k(const float* __restrict__ PP,
                                                     float* __restrict__ P)
{
    const int idx = blockIdx.x * 128 + threadIdx.x;
    const int b = idx / Dd, d = idx % Dd;
    float s = 0.f;
#pragma unroll
    for (int c = 0; c < 16; c++) s += PP[((size_t)c * Bb + b) * Dd + d];
    P[idx] = s * (1.f / Ss);
}

// ---------------- final tiny GEMM ----------------
__global__ void __launch_bounds__(128) final_k(const float* __restrict__ P,
                                               const float* __restrict__ Wt,
                                               const float* __restrict__ bias,
                                               float* __restrict__ out)
{
    const int b = blockIdx.x, o = threadIdx.x;
    float s = bias[o];
    for (int d = 0; d < Dd; d++) s += P[b * Dd + d] * Wt[d * DOUT + o];
    out[b * DOUT + o] = s;
}

// ---------------- launch ----------------
extern "C" void kernel_launch(void* const* d_in, const int* in_sizes, int n_in,
                              void* d_out, int out_size)
{
    const float* x      = (const float*)d_in[0];
    const float* pos    = (const float*)d_in[1];
    const float* win_w  = (const float*)d_in[2];
    const float* win_b  = (const float*)d_in[3];
    const float* l_wqkv = (const float*)d_in[4];
    const float* l_bqkv = (const float*)d_in[5];
    const float* l_wo   = (const float*)d_in[6];
    const float* l_bo   = (const float*)d_in[7];
    const float* g_wqkv = (const float*)d_in[8];
    const float* g_bqkv = (const float*)d_in[9];
    const float* g_wo   = (const float*)d_in[10];
    const float* g_bo   = (const float*)d_in[11];
    const float* gate_w = (const float*)d_in[12];
    const float* gate_b = (const float*)d_in[13];
    const float* ffn_w1 = (const float*)d_in[14];
    const float* ffn_b1 = (const float*)d_in[15];
    const float* ffn_w2 = (const float*)d_in[16];
    const float* ffn_b2 = (const float*)d_in[17];
    const float* n1_g   = (const float*)d_in[18];
    const float* n1_b   = (const float*)d_in[19];
    const float* n2_g   = (const float*)d_in[20];
    const float* n2_b   = (const float*)d_in[21];
    const float* n3_g   = (const float*)d_in[22];
    const float* n3_b   = (const float*)d_in[23];
    const float* out_w  = (const float*)d_in[24];
    const float* out_b  = (const float*)d_in[25];

    float* sp = nullptr;
    cudaGetSymbolAddress((void**)&sp, g_scratch);
    float* bH   = sp + O_H;
    float* bLOC = sp + O_LOC;
    float* bGLO = sp + O_GLO;
    float* bFUS = sp + O_FUS;
    float* bH1  = sp + O_H1;
    float* bFFN = sp + O_FFN;
    float* bH3  = sp + O_H3;
    float* bPP  = sp + O_PP;
    float* bP   = sp + O_P;

    __half* hQKV = (__half*)(sp + O_QL);
    const __half* hQL = (const __half*)(sp + O_QL);
    const __half* hKL = (const __half*)(sp + O_KL);
    const __half* hVL = (const __half*)(sp + O_VL);
    const __half* hQG = (const __half*)(sp + O_QG);
    const __half* hKG = (const __half*)(sp + O_KG);
    const __half* hVG = (const __half*)(sp + O_VG);
    __half* hAOL = (__half*)(sp + O_AOL);
    __half* hAOG = (__half*)(sp + O_AOG);
    __half* hT1  = (__half*)(sp + O_T1H);
    __half* bHh  = (__half*)(sp + O_HH);
    __half* bH1h = (__half*)(sp + O_HH + NBD / 2);
    __half* hLOCh = (__half*)(sp + O_LGH);

    __half* pool = (__half*)(sp + O_WH);
    __half* hx    = pool;
    __half* hwin  = hx    + (size_t)BS * DIN;
    __half* hlq   = hwin  + (size_t)DIN * Dd;
    __half* hgq   = hlq   + (size_t)3 * Dd * Dd;
    __half* hlwo  = hgq   + (size_t)3 * Dd * Dd;
    __half* hgwo  = hlwo  + (size_t)Dd * Dd;
    __half* hgate = hgwo  + (size_t)Dd * Dd;
    __half* hf1   = hgate + (size_t)2 * Dd * Dd;
    __half* hf2   = hf1   + (size_t)2 * Dd * Dd;

    static bool attr_set = false;
    if (!attr_set) {
        cudaFuncSetAttribute(flash_tc_k, cudaFuncAttributeMaxDynamicSharedMemorySize,
                             FL_SMEM_BYTES);
        attr_set = true;
    }

    const dim3 blk(256);

    // 0. convert inputs + weights to fp16 (one merged launch)
    {
        CvtJobs jobs;
        jobs.j[0] = {x,      hx,    BS * DIN};
        jobs.j[1] = {win_w,  hwin,  DIN * Dd};
        jobs.j[2] = {l_wqkv, hlq,   3 * Dd * Dd};
        jobs.j[3] = {g_wqkv, hgq,   3 * Dd * Dd};
        jobs.j[4] = {l_wo,   hlwo,  Dd * Dd};
        jobs.j[5] = {g_wo,   hgwo,  Dd * Dd};
        jobs.j[6] = {gate_w, hgate, 2 * Dd * Dd};
        jobs.j[7] = {ffn_w1, hf1,   Dd * 2 * Dd};
        jobs.j[8] = {ffn_w2, hf2,   2 * Dd * Dd};
        f2h_all_k<<<dim3((BS * DIN / 8 + 255) / 256, 9), 256>>>(jobs);
    }

    // 1. h = x @ win_w + win_b + pos  (fp32 + fp16 copies)
    gemm_tc_k<1><<<dim3(4, 64), blk>>>(hx, nullptr, DIN, 0, hwin, nullptr,
                                       win_b, nullptr, pos, nullptr,
                                       bH, bHh, 0, Dd, DIN);

    // 2. merged 6-slice QKV -> fp16 (Q pre-scaled by SCALE*log2e)
    gemm_tc_k<4><<<dim3(24, 64), blk>>>(bHh, nullptr, Dd, 0, hlq, hgq,
                                        l_bqkv, g_bqkv, nullptr, nullptr,
                                        nullptr, hQKV, 2 * (long)NBD, Dd, Dd);

    // 3+4. merged local banded + global flash attention (one launch)
    flash_tc_k<<<dim3(Ss / 128, Hh, 2 * Bb), 256, FL_SMEM_BYTES>>>(
        hQL, hKL, hVL, hAOL, hQG, hKG, hVG, hAOG);

    // 5. merged 2-slice output projections -> LOC/GLO fp32 + fp16
    gemm_tc_k<5><<<dim3(8, 64), blk>>>(hAOL, hAOG, Dd, 0, hlwo, hgwo,
                                       l_bo, g_bo, nullptr, nullptr,
                                       bLOC, hLOCh, (long)NBD, Dd, Dd);

    // 6. gate GEMM fused with blend (A = LOCh || GLOh)
    gemm_tc_k<3><<<dim3(4, 64), blk>>>(hLOCh, hLOCh + NBD, Dd, Dd, hgate, nullptr,
                                       gate_b, nullptr, bLOC, bGLO,
                                       bFUS, nullptr, 0, Dd, 2 * Dd);

    // 7. h1 = LN(h + fused)  (fp32 + fp16)
    ln_add_k<<<BS, 128>>>(bH, bFUS, n1_g, n1_b, bH1, bH1h);

    // 8. FFN
    gemm_tc_k<2><<<dim3(8, 64), blk>>>(bH1h, nullptr, Dd, 0, hf1, nullptr,
                                       ffn_b1, nullptr, nullptr, nullptr,
                                       nullptr, hT1, 0, 2 * Dd, Dd);
    gemm_tc_k<0><<<dim3(4, 64), blk>>>(hT1, nullptr, 2 * Dd, 0, hf2, nullptr,
                                       ffn_b2, nullptr, nullptr, nullptr,
                                       bFFN, nullptr, 0, Dd, 2 * Dd);

    // 9. h3 = LN(LN(h1 + ffn))
    ln_add_ln_k<<<BS, 128>>>(bH1, bFFN, n2_g, n2_b, n3_g, n3_b, bH3);

    // 10. mean-pool over S, then final projection
    colmean_part_k<<<dim3(Bb * 4, 16), 128>>>(bH3, bPP);
    colmean_fin_k<<<(Bb * Dd) / 128, 128>>>(bPP, bP);
    final_k<<<Bb, DOUT>>>(bP, out_w, out_b, (float*)d_out);

    (void)in_sizes; (void)n_in; (void)out_size;
}